// round 2
// baseline (speedup 1.0000x reference)
#include <cuda_runtime.h>
#include <math.h>

#define S    1024
#define D    2048
#define NH   32
#define HD   64
#define FF   8192
#define NE   4
#define NV   50257
#define BLKQ 64
#define NB   16   // S / BLKQ

// ---------------- scratch (static device globals; no runtime alloc) ----------------
__device__ float g_x  [S*D];
__device__ float g_q  [S*D];
__device__ float g_k  [S*D];
__device__ float g_v  [S*D];
__device__ float g_att[S*D];
__device__ float g_x1 [S*D];
__device__ float g_x2 [S*D];
__device__ float g_x3 [S*D];
__device__ float g_x4 [S*D];
__device__ float g_x5 [S*D];
__device__ float g_moe[S*D];
__device__ float g_t1 [(long)NE*S*FF];
__device__ float g_t2 [(long)NE*S*FF];
__device__ int   g_cnt[NE];
__device__ int   g_list[NE*S];
__device__ float g_wgt[NE*S];
__device__ float g_var[S];

// ---------------- init: zero moe accumulator + routing counts ----------------
__global__ void zero_kernel(float* moe) {
    long i = (long)blockIdx.x * blockDim.x + threadIdx.x;
    if (i < (long)S*D) moe[i] = 0.f;
    if (i < NE) g_cnt[i] = 0;
}

// ---------------- embedding gather ----------------
__global__ void embed_kernel(const int* __restrict__ tok, const float* __restrict__ emb,
                             float* __restrict__ x) {
    int t = blockIdx.x;
    long r = (long)tok[t] * D;
    for (int d = threadIdx.x; d < D; d += blockDim.x)
        x[(long)t*D + d] = emb[r + d];
}

// ---------------- RoPE (in-place on q and k) ----------------
__global__ void rope_kernel(float* __restrict__ q, float* __restrict__ k) {
    int idx = blockIdx.x * blockDim.x + threadIdx.x;     // S * NH * (HD/2)
    if (idx >= S*NH*(HD/2)) return;
    int j = idx & 31;
    int h = (idx >> 5) & 31;
    int s = idx >> 10;
    double inv = pow(10000.0, -(double)(2*j) / (double)HD);
    double ang = (double)s * inv;
    float c = (float)cos(ang), sn = (float)sin(ang);
    long base = (long)s*D + h*HD + 2*j;
    float q0 = q[base], q1 = q[base+1];
    q[base]   = q0*c - q1*sn;
    q[base+1] = q0*sn + q1*c;
    float k0 = k[base], k1 = k[base+1];
    k[base]   = k0*c - k1*sn;
    k[base+1] = k0*sn + k1*c;
}

// ---------------- attention with per-(i,j)-block max softmax (matches reference) --------
// grid (NH, NB), 256 threads = 8 warps; each warp owns 8 query rows.
#define ATTN_SMEM ((64*64 + 64*65 + 64*64 + 8*64) * 4)
__global__ void attn_kernel(const float* __restrict__ q, const float* __restrict__ k,
                            const float* __restrict__ v, float* __restrict__ o) {
    int h  = blockIdx.x;
    int ib = blockIdx.y;
    extern __shared__ float sm[];
    float* Qs = sm;                 // [64][64]
    float* Ks = Qs + 64*64;         // [64][65] padded
    float* Vs = Ks + 64*65;         // [64][64]
    float* Ps = Vs + 64*64;         // [8][64]
    int tid = threadIdx.x;
    int w = tid >> 5, l = tid & 31;

    for (int idx = tid; idx < 64*64; idx += 256) {
        int r = idx >> 6, c = idx & 63;
        Qs[r*64 + c] = q[((long)(ib*BLKQ + r))*D + h*HD + c];
    }
    float num0[8], num1[8], den[8];
    #pragma unroll
    for (int r = 0; r < 8; r++) { num0[r]=0.f; num1[r]=0.f; den[r]=0.f; }

    for (int jb = 0; jb <= ib; jb++) {
        __syncthreads();
        for (int idx = tid; idx < 64*64; idx += 256) {
            int r = idx >> 6, c = idx & 63;
            Ks[r*65 + c] = k[((long)(jb*BLKQ + r))*D + h*HD + c];
            Vs[r*64 + c] = v[((long)(jb*BLKQ + r))*D + h*HD + c];
        }
        __syncthreads();
        for (int r = 0; r < 8; r++) {
            int qr = w*8 + r;
            float s0 = 0.f, s1 = 0.f;
            #pragma unroll 8
            for (int d = 0; d < HD; d++) {
                float qv = Qs[qr*64 + d];
                s0 = fmaf(qv, Ks[l*65 + d], s0);
                s1 = fmaf(qv, Ks[(l+32)*65 + d], s1);
            }
            s0 *= 0.125f; s1 *= 0.125f;
            if (jb == ib) {
                if (l      > qr) s0 = -INFINITY;
                if (l + 32 > qr) s1 = -INFINITY;
            }
            float m = fmaxf(s0, s1);
            #pragma unroll
            for (int off = 16; off; off >>= 1)
                m = fmaxf(m, __shfl_xor_sync(0xffffffffu, m, off));
            float p0 = expf(s0 - m), p1 = expf(s1 - m);
            float ds = p0 + p1;
            #pragma unroll
            for (int off = 16; off; off >>= 1)
                ds += __shfl_xor_sync(0xffffffffu, ds, off);
            den[r] += ds;
            Ps[w*64 + l] = p0; Ps[w*64 + l + 32] = p1;
            __syncwarp();
            #pragma unroll 8
            for (int kk = 0; kk < 64; kk++) {
                float pk = Ps[w*64 + kk];
                num0[r] = fmaf(pk, Vs[kk*64 + l],      num0[r]);
                num1[r] = fmaf(pk, Vs[kk*64 + l + 32], num1[r]);
            }
            __syncwarp();
        }
    }
    for (int r = 0; r < 8; r++) {
        int qr = w*8 + r;
        float dinv = 1.0f / (den[r] + 1e-6f);
        long base = ((long)(ib*BLKQ + qr))*D + h*HD;
        o[base + l]      = num0[r] * dinv;
        o[base + l + 32] = num1[r] * dinv;
    }
}

// ---------------- layernorm (per token) ----------------
__global__ void ln_kernel(const float* __restrict__ x, const float* __restrict__ g,
                          const float* __restrict__ b, float* __restrict__ y) {
    int t = blockIdx.x;
    __shared__ float red[256];
    const float* row = x + (long)t*D;
    float s = 0.f;
    for (int d = threadIdx.x; d < D; d += 256) s += row[d];
    red[threadIdx.x] = s; __syncthreads();
    for (int o = 128; o; o >>= 1) { if (threadIdx.x < o) red[threadIdx.x] += red[threadIdx.x+o]; __syncthreads(); }
    float mu = red[0] / (float)D;
    __syncthreads();
    float vs = 0.f;
    for (int d = threadIdx.x; d < D; d += 256) { float dd = row[d]-mu; vs = fmaf(dd, dd, vs); }
    red[threadIdx.x] = vs; __syncthreads();
    for (int o = 128; o; o >>= 1) { if (threadIdx.x < o) red[threadIdx.x] += red[threadIdx.x+o]; __syncthreads(); }
    float inv = 1.0f / sqrtf(red[0]/(float)D + 1e-5f);
    for (int d = threadIdx.x; d < D; d += 256)
        y[(long)t*D + d] = (row[d]-mu)*inv*g[d] + b[d];
}

// ---------------- gate: logits, softmax, top-2, routing, per-token variance ----------------
__global__ void gate_kernel(const float* __restrict__ x, const float* __restrict__ gw) {
    int t = blockIdx.x;
    int tid = threadIdx.x;  // 128
    __shared__ float red[4][128];
    const float* row = x + (long)t*D;
    float p[4] = {0.f,0.f,0.f,0.f};
    for (int d = tid; d < D; d += 128) {
        float xv = row[d];
        #pragma unroll
        for (int e = 0; e < 4; e++) p[e] = fmaf(xv, gw[e*D + d], p[e]);
    }
    #pragma unroll
    for (int e = 0; e < 4; e++) red[e][tid] = p[e];
    __syncthreads();
    for (int o = 64; o; o >>= 1) {
        if (tid < o) {
            red[0][tid] += red[0][tid+o];
            red[1][tid] += red[1][tid+o];
            red[2][tid] += red[2][tid+o];
            red[3][tid] += red[3][tid+o];
        }
        __syncthreads();
    }
    if (tid == 0) {
        float l[4];
        #pragma unroll
        for (int e = 0; e < 4; e++) l[e] = red[e][0];
        float mu = (l[0]+l[1]+l[2]+l[3]) * 0.25f;
        float var = 0.f;
        #pragma unroll
        for (int e = 0; e < 4; e++) { float d0 = l[e]-mu; var = fmaf(d0, d0, var); }
        g_var[t] = var / 3.0f;                       // ddof=1
        int i1 = 0;
        for (int e = 1; e < 4; e++) if (l[e] > l[i1]) i1 = e;
        int i2 = (i1 == 0) ? 1 : 0;
        for (int e = 0; e < 4; e++) if (e != i1 && l[e] > l[i2]) i2 = e;
        float m = fmaxf(fmaxf(l[0],l[1]), fmaxf(l[2],l[3]));
        float e1 = expf(l[i1]-m), e2 = expf(l[i2]-m);
        float w1 = e1/(e1+e2), w2 = e2/(e1+e2);
        int pos1 = atomicAdd(&g_cnt[i1], 1);
        g_list[i1*S + pos1] = t; g_wgt[i1*S + pos1] = w1;
        int pos2 = atomicAdd(&g_cnt[i2], 1);
        g_list[i2*S + pos2] = t; g_wgt[i2*S + pos2] = w2;
    }
}

// ---------------- aux = mean over tokens of var ----------------
__global__ void aux_kernel(float* __restrict__ out, int out_size) {
    __shared__ float red[256];
    float s = 0.f;
    for (int i = threadIdx.x; i < S; i += 256) s += g_var[i];
    red[threadIdx.x] = s; __syncthreads();
    for (int o = 128; o; o >>= 1) { if (threadIdx.x < o) red[threadIdx.x] += red[threadIdx.x+o]; __syncthreads(); }
    if (threadIdx.x == 0) {
        long pos = (long)S * NV;
        if ((long)out_size > pos) out[pos] = red[0] / (float)S;
    }
}

// ---------------- silu-gate elementwise: t1 = silu(t1) * t2 ----------------
__global__ void silu_kernel() {
    long i = (long)blockIdx.x * 256 + threadIdx.x;
    if (i >= (long)NE*S*FF) return;
    float a = g_t1[i], b = g_t2[i];
    float sg = a / (1.0f + expf(-a));
    g_t1[i] = sg * b;
}

// ---------------- elementwise add ----------------
__global__ void add_kernel(const float* __restrict__ a, const float* __restrict__ b,
                           float* __restrict__ c) {
    long i = (long)blockIdx.x * 256 + threadIdx.x;
    if (i < (long)S*D) c[i] = a[i] + b[i];
}

// ---------------- tiled SGEMM: C[M,N] = A[M,K] @ B[N,K]^T ----------------
// EPI: 0 = store, 1 = store + resid, 2 = atomicAdd(C[rowidx[m]*N+n], acc*roww[m])
// GA: gather A rows via rowidx. GCNT: M limited by cnt[z].
constexpr int BM = 128, BN = 128, BKs = 8;

template<int EPI, bool GA, bool GCNT>
__global__ void __launch_bounds__(256)
sgemm_k(const float* __restrict__ A, const float* __restrict__ Bm, float* __restrict__ Cm,
        int M, int N, int K,
        const int* __restrict__ cnt, const int* __restrict__ rowidx,
        const float* __restrict__ roww, const float* __restrict__ resid,
        long sAz, long sBz, long sCz)
{
    int z = blockIdx.z;
    A  += (long)z * sAz;
    Bm += (long)z * sBz;
    Cm += (long)z * sCz;
    const int*   ridx = rowidx ? rowidx + z*S : nullptr;
    const float* rw   = roww   ? roww   + z*S : nullptr;
    int Meff = GCNT ? cnt[z] : M;
    int m0 = blockIdx.y * BM, n0 = blockIdx.x * BN;
    if (m0 >= Meff) return;

    __shared__ float As[BKs][BM];
    __shared__ float Bs[BKs][BN];
    int tid = threadIdx.x;
    int tx = tid & 15, ty = tid >> 4;

    float acc[8][8];
    #pragma unroll
    for (int i = 0; i < 8; i++)
        #pragma unroll
        for (int j = 0; j < 8; j++) acc[i][j] = 0.f;

    int am = tid >> 1, aseg = (tid & 1) * 4;
    int arow = m0 + am;
    bool avld = arow < Meff;
    const float* Ap = nullptr;
    if (avld) Ap = A + (long)(GA ? ridx[arow] : arow) * K + aseg;
    int bn = tid >> 1, bseg = (tid & 1) * 4;
    int brow = n0 + bn;
    bool bvld = brow < N;
    const float* Bp = bvld ? (Bm + (long)brow * K + bseg) : nullptr;

    for (int k0 = 0; k0 < K; k0 += BKs) {
        float4 a4 = avld ? *(const float4*)(Ap + k0) : make_float4(0.f,0.f,0.f,0.f);
        float4 b4 = bvld ? *(const float4*)(Bp + k0) : make_float4(0.f,0.f,0.f,0.f);
        __syncthreads();
        As[aseg+0][am] = a4.x; As[aseg+1][am] = a4.y; As[aseg+2][am] = a4.z; As[aseg+3][am] = a4.w;
        Bs[bseg+0][bn] = b4.x; Bs[bseg+1][bn] = b4.y; Bs[bseg+2][bn] = b4.z; Bs[bseg+3][bn] = b4.w;
        __syncthreads();
        #pragma unroll
        for (int kk = 0; kk < BKs; kk++) {
            float a[8], b[8];
            #pragma unroll
            for (int i = 0; i < 8; i++) a[i] = As[kk][ty*8 + i];
            #pragma unroll
            for (int j = 0; j < 8; j++) b[j] = Bs[kk][tx*8 + j];
            #pragma unroll
            for (int i = 0; i < 8; i++)
                #pragma unroll
                for (int j = 0; j < 8; j++)
                    acc[i][j] = fmaf(a[i], b[j], acc[i][j]);
        }
    }
    #pragma unroll
    for (int i = 0; i < 8; i++) {
        int m = m0 + ty*8 + i;
        if (m >= Meff) continue;
        #pragma unroll
        for (int j = 0; j < 8; j++) {
            int n = n0 + tx*8 + j;
            if (n >= N) continue;
            float vv = acc[i][j];
            if constexpr (EPI == 0) {
                Cm[(long)m*N + n] = vv;
            } else if constexpr (EPI == 1) {
                Cm[(long)m*N + n] = vv + resid[(long)m*N + n];
            } else {
                atomicAdd(&Cm[(long)ridx[m]*N + n], vv * rw[m]);
            }
        }
    }
}

// ---------------- launcher ----------------
extern "C" void kernel_launch(void* const* d_in, const int* in_sizes, int n_in,
                              void* d_out, int out_size) {
    const int*   tokens = (const int*)  d_in[0];
    const float* emb    = (const float*)d_in[1];
    const float* wq     = (const float*)d_in[2];
    const float* wk     = (const float*)d_in[3];
    const float* wv     = (const float*)d_in[4];
    const float* wo     = (const float*)d_in[5];
    const float* ln1g   = (const float*)d_in[6];
    const float* ln1b   = (const float*)d_in[7];
    const float* gatew  = (const float*)d_in[8];
    const float* w1     = (const float*)d_in[9];
    const float* w2     = (const float*)d_in[10];
    const float* w3     = (const float*)d_in[11];
    const float* ln2g   = (const float*)d_in[12];
    const float* ln2b   = (const float*)d_in[13];
    const float* fing   = (const float*)d_in[14];
    const float* finb   = (const float*)d_in[15];
    const float* headw  = (const float*)d_in[16];
    float* out = (float*)d_out;

    float *x, *q, *k, *v, *att, *x1, *x2, *x3, *x4, *x5, *moe, *t1, *t2, *wgt;
    int *cnt, *lst;
    cudaGetSymbolAddress((void**)&x,   g_x);
    cudaGetSymbolAddress((void**)&q,   g_q);
    cudaGetSymbolAddress((void**)&k,   g_k);
    cudaGetSymbolAddress((void**)&v,   g_v);
    cudaGetSymbolAddress((void**)&att, g_att);
    cudaGetSymbolAddress((void**)&x1,  g_x1);
    cudaGetSymbolAddress((void**)&x2,  g_x2);
    cudaGetSymbolAddress((void**)&x3,  g_x3);
    cudaGetSymbolAddress((void**)&x4,  g_x4);
    cudaGetSymbolAddress((void**)&x5,  g_x5);
    cudaGetSymbolAddress((void**)&moe, g_moe);
    cudaGetSymbolAddress((void**)&t1,  g_t1);
    cudaGetSymbolAddress((void**)&t2,  g_t2);
    cudaGetSymbolAddress((void**)&wgt, g_wgt);
    cudaGetSymbolAddress((void**)&cnt, g_cnt);
    cudaGetSymbolAddress((void**)&lst, g_list);

    cudaFuncSetAttribute(attn_kernel, cudaFuncAttributeMaxDynamicSharedMemorySize, ATTN_SMEM);

    // 0. init
    zero_kernel<<<(S*D + 255)/256, 256>>>(moe);
    // 1. embedding
    embed_kernel<<<S, 256>>>(tokens, emb, x);
    // 2. QKV projections
    sgemm_k<0,false,false><<<dim3(D/BN, S/BM, 1), 256>>>(x, wq, q, S, D, D, nullptr,nullptr,nullptr,nullptr, 0,0,0);
    sgemm_k<0,false,false><<<dim3(D/BN, S/BM, 1), 256>>>(x, wk, k, S, D, D, nullptr,nullptr,nullptr,nullptr, 0,0,0);
    sgemm_k<0,false,false><<<dim3(D/BN, S/BM, 1), 256>>>(x, wv, v, S, D, D, nullptr,nullptr,nullptr,nullptr, 0,0,0);
    // 3. RoPE
    rope_kernel<<<(S*NH*(HD/2))/256, 256>>>(q, k);
    // 4. attention
    attn_kernel<<<dim3(NH, NB), 256, ATTN_SMEM>>>(q, k, v, att);
    // 5. output projection + residual
    sgemm_k<1,false,false><<<dim3(D/BN, S/BM, 1), 256>>>(att, wo, x1, S, D, D, nullptr,nullptr,nullptr, x, 0,0,0);
    // 6. layernorm 1
    ln_kernel<<<S, 256>>>(x1, ln1g, ln1b, x2);
    // 7. gating + routing + per-token variance
    gate_kernel<<<S, 128>>>(x2, gatew);
    aux_kernel<<<1, 256>>>(out, out_size);
    // 8. MoE expert GEMMs (grid.z = experts, dynamic M with early-exit)
    sgemm_k<0,true,true><<<dim3(FF/BN, S/BM, NE), 256>>>(x2, w1, t1, S, FF, D, cnt, lst, nullptr, nullptr,
                                                         0, (long)FF*D, (long)S*FF);
    sgemm_k<0,true,true><<<dim3(FF/BN, S/BM, NE), 256>>>(x2, w3, t2, S, FF, D, cnt, lst, nullptr, nullptr,
                                                         0, (long)FF*D, (long)S*FF);
    silu_kernel<<<(int)(((long)NE*S*FF + 255)/256), 256>>>();
    sgemm_k<2,false,true><<<dim3(D/BN, S/BM, NE), 256>>>(t1, w2, moe, S, D, FF, cnt, lst, wgt, nullptr,
                                                         (long)S*FF, (long)D*FF, 0);
    // 9. residual + layernorm 2 + final layernorm
    add_kernel<<<(S*D + 255)/256, 256>>>(moe, x2, x3);
    ln_kernel<<<S, 256>>>(x3, ln2g, ln2b, x4);
    ln_kernel<<<S, 256>>>(x4, fing, finb, x5);
    // 10. LM head -> logits
    sgemm_k<0,false,false><<<dim3((NV + BN - 1)/BN, S/BM, 1), 256>>>(x5, headw, out, S, NV, D,
                                                                     nullptr,nullptr,nullptr,nullptr, 0,0,0);
}

// round 3
// speedup vs baseline: 1.5580x; 1.5580x over previous
#include <cuda_runtime.h>
#include <math.h>
#include <stdint.h>

#define S    1024
#define D    2048
#define NH   32
#define HD   64
#define FF   8192
#define NE   4
#define NV   50257
#define BLKQ 64
#define NB   16   // S / BLKQ

// ---------------- scratch (static device globals; no runtime alloc) ----------------
__device__ float g_x  [S*D];
__device__ float g_q  [S*D];
__device__ float g_k  [S*D];
__device__ float g_v  [S*D];
__device__ float g_att[S*D];
__device__ float g_x1 [S*D];
__device__ float g_x2 [S*D];
__device__ float g_x3 [S*D];
__device__ float g_x4 [S*D];
__device__ float g_x5 [S*D];
__device__ float g_moe[S*D];
__device__ float g_t1 [(long)NE*S*FF];
__device__ float g_t2 [(long)NE*S*FF];
__device__ int   g_cnt[NE];
__device__ int   g_list[NE*S];
__device__ float g_wgt[NE*S];
__device__ float g_var[S];

// ---------------- init ----------------
__global__ void zero_kernel(float* moe) {
    long i = (long)blockIdx.x * blockDim.x + threadIdx.x;
    if (i < (long)S*D) moe[i] = 0.f;
    if (i < NE) g_cnt[i] = 0;
}

// ---------------- embedding gather ----------------
__global__ void embed_kernel(const int* __restrict__ tok, const float* __restrict__ emb,
                             float* __restrict__ x) {
    int t = blockIdx.x;
    long r = (long)tok[t] * D;
    for (int d = threadIdx.x; d < D; d += blockDim.x)
        x[(long)t*D + d] = emb[r + d];
}

// ---------------- RoPE ----------------
__global__ void rope_kernel(float* __restrict__ q, float* __restrict__ k) {
    int idx = blockIdx.x * blockDim.x + threadIdx.x;
    if (idx >= S*NH*(HD/2)) return;
    int j = idx & 31;
    int h = (idx >> 5) & 31;
    int s = idx >> 10;
    double inv = pow(10000.0, -(double)(2*j) / (double)HD);
    double ang = (double)s * inv;
    float c = (float)cos(ang), sn = (float)sin(ang);
    long base = (long)s*D + h*HD + 2*j;
    float q0 = q[base], q1 = q[base+1];
    q[base]   = q0*c - q1*sn;
    q[base+1] = q0*sn + q1*c;
    float k0 = k[base], k1 = k[base+1];
    k[base]   = k0*c - k1*sn;
    k[base+1] = k0*sn + k1*c;
}

// ---------------- attention (per-block-max softmax, matches reference) ----------------
#define ATTN_SMEM ((64*64 + 64*65 + 64*64 + 8*64) * 4)
__global__ void attn_kernel(const float* __restrict__ q, const float* __restrict__ k,
                            const float* __restrict__ v, float* __restrict__ o) {
    int h  = blockIdx.x;
    int ib = blockIdx.y;
    extern __shared__ float sm[];
    float* Qs = sm;
    float* Ks = Qs + 64*64;
    float* Vs = Ks + 64*65;
    float* Ps = Vs + 64*64;
    int tid = threadIdx.x;
    int w = tid >> 5, l = tid & 31;

    for (int idx = tid; idx < 64*64; idx += 256) {
        int r = idx >> 6, c = idx & 63;
        Qs[r*64 + c] = q[((long)(ib*BLKQ + r))*D + h*HD + c];
    }
    float num0[8], num1[8], den[8];
    #pragma unroll
    for (int r = 0; r < 8; r++) { num0[r]=0.f; num1[r]=0.f; den[r]=0.f; }

    for (int jb = 0; jb <= ib; jb++) {
        __syncthreads();
        for (int idx = tid; idx < 64*64; idx += 256) {
            int r = idx >> 6, c = idx & 63;
            Ks[r*65 + c] = k[((long)(jb*BLKQ + r))*D + h*HD + c];
            Vs[r*64 + c] = v[((long)(jb*BLKQ + r))*D + h*HD + c];
        }
        __syncthreads();
        for (int r = 0; r < 8; r++) {
            int qr = w*8 + r;
            float s0 = 0.f, s1 = 0.f;
            #pragma unroll 8
            for (int d = 0; d < HD; d++) {
                float qv = Qs[qr*64 + d];
                s0 = fmaf(qv, Ks[l*65 + d], s0);
                s1 = fmaf(qv, Ks[(l+32)*65 + d], s1);
            }
            s0 *= 0.125f; s1 *= 0.125f;
            if (jb == ib) {
                if (l      > qr) s0 = -INFINITY;
                if (l + 32 > qr) s1 = -INFINITY;
            }
            float m = fmaxf(s0, s1);
            #pragma unroll
            for (int off = 16; off; off >>= 1)
                m = fmaxf(m, __shfl_xor_sync(0xffffffffu, m, off));
            float p0 = expf(s0 - m), p1 = expf(s1 - m);
            float ds = p0 + p1;
            #pragma unroll
            for (int off = 16; off; off >>= 1)
                ds += __shfl_xor_sync(0xffffffffu, ds, off);
            den[r] += ds;
            Ps[w*64 + l] = p0; Ps[w*64 + l + 32] = p1;
            __syncwarp();
            #pragma unroll 8
            for (int kk = 0; kk < 64; kk++) {
                float pk = Ps[w*64 + kk];
                num0[r] = fmaf(pk, Vs[kk*64 + l],      num0[r]);
                num1[r] = fmaf(pk, Vs[kk*64 + l + 32], num1[r]);
            }
            __syncwarp();
        }
    }
    for (int r = 0; r < 8; r++) {
        int qr = w*8 + r;
        float dinv = 1.0f / (den[r] + 1e-6f);
        long base = ((long)(ib*BLKQ + qr))*D + h*HD;
        o[base + l]      = num0[r] * dinv;
        o[base + l + 32] = num1[r] * dinv;
    }
}

// ---------------- layernorm ----------------
__global__ void ln_kernel(const float* __restrict__ x, const float* __restrict__ g,
                          const float* __restrict__ b, float* __restrict__ y) {
    int t = blockIdx.x;
    __shared__ float red[256];
    const float* row = x + (long)t*D;
    float s = 0.f;
    for (int d = threadIdx.x; d < D; d += 256) s += row[d];
    red[threadIdx.x] = s; __syncthreads();
    for (int o = 128; o; o >>= 1) { if (threadIdx.x < o) red[threadIdx.x] += red[threadIdx.x+o]; __syncthreads(); }
    float mu = red[0] / (float)D;
    __syncthreads();
    float vs = 0.f;
    for (int d = threadIdx.x; d < D; d += 256) { float dd = row[d]-mu; vs = fmaf(dd, dd, vs); }
    red[threadIdx.x] = vs; __syncthreads();
    for (int o = 128; o; o >>= 1) { if (threadIdx.x < o) red[threadIdx.x] += red[threadIdx.x+o]; __syncthreads(); }
    float inv = 1.0f / sqrtf(red[0]/(float)D + 1e-5f);
    for (int d = threadIdx.x; d < D; d += 256)
        y[(long)t*D + d] = (row[d]-mu)*inv*g[d] + b[d];
}

// ---------------- gate ----------------
__global__ void gate_kernel(const float* __restrict__ x, const float* __restrict__ gw) {
    int t = blockIdx.x;
    int tid = threadIdx.x;  // 128
    __shared__ float red[4][128];
    const float* row = x + (long)t*D;
    float p[4] = {0.f,0.f,0.f,0.f};
    for (int d = tid; d < D; d += 128) {
        float xv = row[d];
        #pragma unroll
        for (int e = 0; e < 4; e++) p[e] = fmaf(xv, gw[e*D + d], p[e]);
    }
    #pragma unroll
    for (int e = 0; e < 4; e++) red[e][tid] = p[e];
    __syncthreads();
    for (int o = 64; o; o >>= 1) {
        if (tid < o) {
            red[0][tid] += red[0][tid+o];
            red[1][tid] += red[1][tid+o];
            red[2][tid] += red[2][tid+o];
            red[3][tid] += red[3][tid+o];
        }
        __syncthreads();
    }
    if (tid == 0) {
        float l[4];
        #pragma unroll
        for (int e = 0; e < 4; e++) l[e] = red[e][0];
        float mu = (l[0]+l[1]+l[2]+l[3]) * 0.25f;
        float var = 0.f;
        #pragma unroll
        for (int e = 0; e < 4; e++) { float d0 = l[e]-mu; var = fmaf(d0, d0, var); }
        g_var[t] = var / 3.0f;
        int i1 = 0;
        for (int e = 1; e < 4; e++) if (l[e] > l[i1]) i1 = e;
        int i2 = (i1 == 0) ? 1 : 0;
        for (int e = 0; e < 4; e++) if (e != i1 && l[e] > l[i2]) i2 = e;
        float m = fmaxf(fmaxf(l[0],l[1]), fmaxf(l[2],l[3]));
        float e1 = expf(l[i1]-m), e2 = expf(l[i2]-m);
        float w1 = e1/(e1+e2), w2 = e2/(e1+e2);
        int pos1 = atomicAdd(&g_cnt[i1], 1);
        g_list[i1*S + pos1] = t; g_wgt[i1*S + pos1] = w1;
        int pos2 = atomicAdd(&g_cnt[i2], 1);
        g_list[i2*S + pos2] = t; g_wgt[i2*S + pos2] = w2;
    }
}

// ---------------- aux ----------------
__global__ void aux_kernel(float* __restrict__ out, int out_size) {
    __shared__ float red[256];
    float s = 0.f;
    for (int i = threadIdx.x; i < S; i += 256) s += g_var[i];
    red[threadIdx.x] = s; __syncthreads();
    for (int o = 128; o; o >>= 1) { if (threadIdx.x < o) red[threadIdx.x] += red[threadIdx.x+o]; __syncthreads(); }
    if (threadIdx.x == 0) {
        long pos = (long)S * NV;
        if ((long)out_size > pos) out[pos] = red[0] / (float)S;
    }
}

// ---------------- silu-gate on valid routed rows only ----------------
__global__ void silu_kernel() {
    int row = blockIdx.x;            // e*S + slot
    int e = row >> 10;               // /S
    int slot = row & (S-1);
    if (slot >= g_cnt[e]) return;
    long base = (long)row * FF;
    for (int i = threadIdx.x; i < FF; i += 256) {
        float a = g_t1[base + i], b = g_t2[base + i];
        g_t1[base + i] = b * (a / (1.0f + expf(-a)));
    }
}

// ---------------- elementwise add ----------------
__global__ void add_kernel(const float* __restrict__ a, const float* __restrict__ b,
                           float* __restrict__ c) {
    long i = (long)blockIdx.x * 256 + threadIdx.x;
    if (i < (long)S*D) c[i] = a[i] + b[i];
}

// ================= fp32 SGEMM (kept for QKV / WO: exact routing path) =================
constexpr int BM = 128, BN = 128, BKs = 8;

template<int EPI, bool GA, bool GCNT>
__global__ void __launch_bounds__(256)
sgemm_k(const float* __restrict__ A, const float* __restrict__ Bm, float* __restrict__ Cm,
        int M, int N, int K,
        const int* __restrict__ cnt, const int* __restrict__ rowidx,
        const float* __restrict__ roww, const float* __restrict__ resid,
        long sAz, long sBz, long sCz)
{
    int z = blockIdx.z;
    A  += (long)z * sAz;
    Bm += (long)z * sBz;
    Cm += (long)z * sCz;
    const int*   ridx = rowidx ? rowidx + z*S : nullptr;
    const float* rw   = roww   ? roww   + z*S : nullptr;
    int Meff = GCNT ? cnt[z] : M;
    int m0 = blockIdx.y * BM, n0 = blockIdx.x * BN;
    if (m0 >= Meff) return;

    __shared__ float As[BKs][BM];
    __shared__ float Bs[BKs][BN];
    int tid = threadIdx.x;
    int tx = tid & 15, ty = tid >> 4;

    float acc[8][8];
    #pragma unroll
    for (int i = 0; i < 8; i++)
        #pragma unroll
        for (int j = 0; j < 8; j++) acc[i][j] = 0.f;

    int am = tid >> 1, aseg = (tid & 1) * 4;
    int arow = m0 + am;
    bool avld = arow < Meff;
    const float* Ap = nullptr;
    if (avld) Ap = A + (long)(GA ? ridx[arow] : arow) * K + aseg;
    int bn = tid >> 1, bseg = (tid & 1) * 4;
    int brow = n0 + bn;
    bool bvld = brow < N;
    const float* Bp = bvld ? (Bm + (long)brow * K + bseg) : nullptr;

    for (int k0 = 0; k0 < K; k0 += BKs) {
        float4 a4 = avld ? *(const float4*)(Ap + k0) : make_float4(0.f,0.f,0.f,0.f);
        float4 b4 = bvld ? *(const float4*)(Bp + k0) : make_float4(0.f,0.f,0.f,0.f);
        __syncthreads();
        As[aseg+0][am] = a4.x; As[aseg+1][am] = a4.y; As[aseg+2][am] = a4.z; As[aseg+3][am] = a4.w;
        Bs[bseg+0][bn] = b4.x; Bs[bseg+1][bn] = b4.y; Bs[bseg+2][bn] = b4.z; Bs[bseg+3][bn] = b4.w;
        __syncthreads();
        #pragma unroll
        for (int kk = 0; kk < BKs; kk++) {
            float a[8], b[8];
            #pragma unroll
            for (int i = 0; i < 8; i++) a[i] = As[kk][ty*8 + i];
            #pragma unroll
            for (int j = 0; j < 8; j++) b[j] = Bs[kk][tx*8 + j];
            #pragma unroll
            for (int i = 0; i < 8; i++)
                #pragma unroll
                for (int j = 0; j < 8; j++)
                    acc[i][j] = fmaf(a[i], b[j], acc[i][j]);
        }
    }
    #pragma unroll
    for (int i = 0; i < 8; i++) {
        int m = m0 + ty*8 + i;
        if (m >= Meff) continue;
        #pragma unroll
        for (int j = 0; j < 8; j++) {
            int n = n0 + tx*8 + j;
            if (n >= N) continue;
            float vv = acc[i][j];
            if constexpr (EPI == 0) {
                Cm[(long)m*N + n] = vv;
            } else if constexpr (EPI == 1) {
                Cm[(long)m*N + n] = vv + resid[(long)m*N + n];
            } else {
                atomicAdd(&Cm[(long)ridx[m]*N + n], vv * rw[m]);
            }
        }
    }
}

// ================= tf32 tensor-core GEMM: C[M,N] = A[M,K] @ B[N,K]^T =================
// 128x128x16 tiles, 256 thr = 8 warps (2 M x 4 N), warp tile 64x32 via mma.m16n8k8.
// EPI: 0 = store, 2 = atomicAdd(C[rowidx[m]*N+n], acc*roww[m]). GA: gather A rows.
constexpr int TBM = 128, TBN = 128, TBK = 16;
#define TPAD 132

__device__ __forceinline__ float f2tf32(float x) {
    uint32_t u;
    asm("cvt.rna.tf32.f32 %0, %1;" : "=r"(u) : "f"(x));
    return __uint_as_float(u);
}

template<int EPI, bool GA, bool GCNT>
__global__ void __launch_bounds__(256, 1)
tgemm_k(const float* __restrict__ A, const float* __restrict__ Bm, float* __restrict__ Cm,
        int M, int N, int K,
        const int* __restrict__ cnt, const int* __restrict__ rowidx,
        const float* __restrict__ roww,
        long sAz, long sBz, long sCz)
{
    int z = blockIdx.z;
    A  += (long)z * sAz;
    Bm += (long)z * sBz;
    Cm += (long)z * sCz;
    const int*   ridx = rowidx ? rowidx + z*S : nullptr;
    const float* rw   = roww   ? roww   + z*S : nullptr;
    int Meff = GCNT ? cnt[z] : M;
    int m0 = blockIdx.y * TBM, n0 = blockIdx.x * TBN;
    if (m0 >= Meff) return;

    __shared__ float As[2][TBK][TPAD];
    __shared__ float Bs[2][TBK][TPAD];

    int tid = threadIdx.x, lane = tid & 31, wid = tid >> 5;
    int wm = (wid & 1) * 64;
    int wn = (wid >> 1) * 32;
    int lr = lane >> 2;          // 0..7
    int lc = lane & 3;           // 0..3

    float acc[4][4][4];
    #pragma unroll
    for (int mt = 0; mt < 4; mt++)
        #pragma unroll
        for (int nt = 0; nt < 4; nt++)
            #pragma unroll
            for (int r = 0; r < 4; r++) acc[mt][nt][r] = 0.f;

    int ktiles = K / TBK;

    // staging
    float4 sa[2], sb[2];
    int fr0 = tid >> 2, fk0 = (tid & 3) << 2;          // f = tid
    int fr1 = (tid + 256) >> 2, fk1 = ((tid + 256) & 3) << 2;

    auto gload = [&](int kt) {
        {
            int grow = m0 + fr0;
            bool v = grow < Meff;
            long row = v ? (GA ? (long)ridx[grow] : (long)grow) : 0;
            sa[0] = v ? *(const float4*)(A + row*K + kt*TBK + fk0) : make_float4(0.f,0.f,0.f,0.f);
            int brow = n0 + fr0;
            bool bv = brow < N;
            sb[0] = bv ? *(const float4*)(Bm + (long)brow*K + kt*TBK + fk0) : make_float4(0.f,0.f,0.f,0.f);
        }
        {
            int grow = m0 + fr1;
            bool v = grow < Meff;
            long row = v ? (GA ? (long)ridx[grow] : (long)grow) : 0;
            sa[1] = v ? *(const float4*)(A + row*K + kt*TBK + fk1) : make_float4(0.f,0.f,0.f,0.f);
            int brow = n0 + fr1;
            bool bv = brow < N;
            sb[1] = bv ? *(const float4*)(Bm + (long)brow*K + kt*TBK + fk1) : make_float4(0.f,0.f,0.f,0.f);
        }
    };
    auto sstore = [&](int buf) {
        As[buf][fk0+0][fr0] = f2tf32(sa[0].x);
        As[buf][fk0+1][fr0] = f2tf32(sa[0].y);
        As[buf][fk0+2][fr0] = f2tf32(sa[0].z);
        As[buf][fk0+3][fr0] = f2tf32(sa[0].w);
        As[buf][fk1+0][fr1] = f2tf32(sa[1].x);
        As[buf][fk1+1][fr1] = f2tf32(sa[1].y);
        As[buf][fk1+2][fr1] = f2tf32(sa[1].z);
        As[buf][fk1+3][fr1] = f2tf32(sa[1].w);
        Bs[buf][fk0+0][fr0] = f2tf32(sb[0].x);
        Bs[buf][fk0+1][fr0] = f2tf32(sb[0].y);
        Bs[buf][fk0+2][fr0] = f2tf32(sb[0].z);
        Bs[buf][fk0+3][fr0] = f2tf32(sb[0].w);
        Bs[buf][fk1+0][fr1] = f2tf32(sb[1].x);
        Bs[buf][fk1+1][fr1] = f2tf32(sb[1].y);
        Bs[buf][fk1+2][fr1] = f2tf32(sb[1].z);
        Bs[buf][fk1+3][fr1] = f2tf32(sb[1].w);
    };

    gload(0);
    sstore(0);
    __syncthreads();

    for (int t = 0; t < ktiles; t++) {
        int buf = t & 1;
        bool more = (t + 1) < ktiles;
        if (more) gload(t + 1);

        #pragma unroll
        for (int ks = 0; ks < 2; ks++) {
            int kb = ks * 8;
            uint32_t af[4][4], bf[4][2];
            #pragma unroll
            for (int mt = 0; mt < 4; mt++) {
                int r = wm + mt*16 + lr;
                af[mt][0] = __float_as_uint(As[buf][kb + lc    ][r    ]);
                af[mt][1] = __float_as_uint(As[buf][kb + lc    ][r + 8]);
                af[mt][2] = __float_as_uint(As[buf][kb + lc + 4][r    ]);
                af[mt][3] = __float_as_uint(As[buf][kb + lc + 4][r + 8]);
            }
            #pragma unroll
            for (int nt = 0; nt < 4; nt++) {
                int c = wn + nt*8 + lr;
                bf[nt][0] = __float_as_uint(Bs[buf][kb + lc    ][c]);
                bf[nt][1] = __float_as_uint(Bs[buf][kb + lc + 4][c]);
            }
            #pragma unroll
            for (int mt = 0; mt < 4; mt++)
                #pragma unroll
                for (int nt = 0; nt < 4; nt++) {
                    asm volatile(
                        "mma.sync.aligned.m16n8k8.row.col.f32.tf32.tf32.f32 "
                        "{%0,%1,%2,%3}, {%4,%5,%6,%7}, {%8,%9}, {%0,%1,%2,%3};"
                        : "+f"(acc[mt][nt][0]), "+f"(acc[mt][nt][1]),
                          "+f"(acc[mt][nt][2]), "+f"(acc[mt][nt][3])
                        : "r"(af[mt][0]), "r"(af[mt][1]), "r"(af[mt][2]), "r"(af[mt][3]),
                          "r"(bf[nt][0]), "r"(bf[nt][1]));
                }
        }

        if (more) {
            sstore(buf ^ 1);
            __syncthreads();
        }
    }

    // ---------------- epilogue ----------------
    #pragma unroll
    for (int mt = 0; mt < 4; mt++) {
        int r0 = m0 + wm + mt*16 + lr;
        int r1 = r0 + 8;
        #pragma unroll
        for (int nt = 0; nt < 4; nt++) {
            int c0 = n0 + wn + nt*8 + (lc << 1);
            int c1 = c0 + 1;
            if constexpr (EPI == 0) {
                if (r0 < Meff) {
                    if (c0 < N) Cm[(long)r0*N + c0] = acc[mt][nt][0];
                    if (c1 < N) Cm[(long)r0*N + c1] = acc[mt][nt][1];
                }
                if (r1 < Meff) {
                    if (c0 < N) Cm[(long)r1*N + c0] = acc[mt][nt][2];
                    if (c1 < N) Cm[(long)r1*N + c1] = acc[mt][nt][3];
                }
            } else {
                if (r0 < Meff) {
                    long orow = (long)ridx[r0] * N;
                    float w = rw[r0];
                    if (c0 < N) atomicAdd(&Cm[orow + c0], acc[mt][nt][0] * w);
                    if (c1 < N) atomicAdd(&Cm[orow + c1], acc[mt][nt][1] * w);
                }
                if (r1 < Meff) {
                    long orow = (long)ridx[r1] * N;
                    float w = rw[r1];
                    if (c0 < N) atomicAdd(&Cm[orow + c0], acc[mt][nt][2] * w);
                    if (c1 < N) atomicAdd(&Cm[orow + c1], acc[mt][nt][3] * w);
                }
            }
        }
    }
}

// ---------------- launcher ----------------
extern "C" void kernel_launch(void* const* d_in, const int* in_sizes, int n_in,
                              void* d_out, int out_size) {
    const int*   tokens = (const int*)  d_in[0];
    const float* emb    = (const float*)d_in[1];
    const float* wq     = (const float*)d_in[2];
    const float* wk     = (const float*)d_in[3];
    const float* wv     = (const float*)d_in[4];
    const float* wo     = (const float*)d_in[5];
    const float* ln1g   = (const float*)d_in[6];
    const float* ln1b   = (const float*)d_in[7];
    const float* gatew  = (const float*)d_in[8];
    const float* w1     = (const float*)d_in[9];
    const float* w2     = (const float*)d_in[10];
    const float* w3     = (const float*)d_in[11];
    const float* ln2g   = (const float*)d_in[12];
    const float* ln2b   = (const float*)d_in[13];
    const float* fing   = (const float*)d_in[14];
    const float* finb   = (const float*)d_in[15];
    const float* headw  = (const float*)d_in[16];
    float* out = (float*)d_out;

    float *x, *q, *k, *v, *att, *x1, *x2, *x3, *x4, *x5, *moe, *t1, *t2, *wgt;
    int *cnt, *lst;
    cudaGetSymbolAddress((void**)&x,   g_x);
    cudaGetSymbolAddress((void**)&q,   g_q);
    cudaGetSymbolAddress((void**)&k,   g_k);
    cudaGetSymbolAddress((void**)&v,   g_v);
    cudaGetSymbolAddress((void**)&att, g_att);
    cudaGetSymbolAddress((void**)&x1,  g_x1);
    cudaGetSymbolAddress((void**)&x2,  g_x2);
    cudaGetSymbolAddress((void**)&x3,  g_x3);
    cudaGetSymbolAddress((void**)&x4,  g_x4);
    cudaGetSymbolAddress((void**)&x5,  g_x5);
    cudaGetSymbolAddress((void**)&moe, g_moe);
    cudaGetSymbolAddress((void**)&t1,  g_t1);
    cudaGetSymbolAddress((void**)&t2,  g_t2);
    cudaGetSymbolAddress((void**)&wgt, g_wgt);
    cudaGetSymbolAddress((void**)&cnt, g_cnt);
    cudaGetSymbolAddress((void**)&lst, g_list);

    cudaFuncSetAttribute(attn_kernel, cudaFuncAttributeMaxDynamicSharedMemorySize, ATTN_SMEM);

    // 0. init
    zero_kernel<<<(S*D + 255)/256, 256>>>(moe);
    // 1. embedding
    embed_kernel<<<S, 256>>>(tokens, emb, x);
    // 2. QKV projections (fp32 — keeps routing bit-exact)
    sgemm_k<0,false,false><<<dim3(D/BN, S/BM, 1), 256>>>(x, wq, q, S, D, D, nullptr,nullptr,nullptr,nullptr, 0,0,0);
    sgemm_k<0,false,false><<<dim3(D/BN, S/BM, 1), 256>>>(x, wk, k, S, D, D, nullptr,nullptr,nullptr,nullptr, 0,0,0);
    sgemm_k<0,false,false><<<dim3(D/BN, S/BM, 1), 256>>>(x, wv, v, S, D, D, nullptr,nullptr,nullptr,nullptr, 0,0,0);
    // 3. RoPE
    rope_kernel<<<(S*NH*(HD/2))/256, 256>>>(q, k);
    // 4. attention
    attn_kernel<<<dim3(NH, NB), 256, ATTN_SMEM>>>(q, k, v, att);
    // 5. output projection + residual (fp32)
    sgemm_k<1,false,false><<<dim3(D/BN, S/BM, 1), 256>>>(att, wo, x1, S, D, D, nullptr,nullptr,nullptr, x, 0,0,0);
    // 6. layernorm 1
    ln_kernel<<<S, 256>>>(x1, ln1g, ln1b, x2);
    // 7. gating + routing + per-token variance
    gate_kernel<<<S, 128>>>(x2, gatew);
    aux_kernel<<<1, 256>>>(out, out_size);
    // 8. MoE expert GEMMs — tf32 tensor cores
    tgemm_k<0,true,true><<<dim3(FF/TBN, S/TBM, NE), 256>>>(x2, w1, t1, S, FF, D, cnt, lst, nullptr,
                                                           0, (long)FF*D, (long)S*FF);
    tgemm_k<0,true,true><<<dim3(FF/TBN, S/TBM, NE), 256>>>(x2, w3, t2, S, FF, D, cnt, lst, nullptr,
                                                           0, (long)FF*D, (long)S*FF);
    silu_kernel<<<NE*S, 256>>>();
    tgemm_k<2,false,true><<<dim3(D/TBN, S/TBM, NE), 256>>>(t1, w2, moe, S, D, FF, cnt, lst, wgt,
                                                           (long)S*FF, (long)D*FF, 0);
    // 9. residual + layernorm 2 + final layernorm
    add_kernel<<<(S*D + 255)/256, 256>>>(moe, x2, x3);
    ln_kernel<<<S, 256>>>(x3, ln2g, ln2b, x4);
    ln_kernel<<<S, 256>>>(x4, fing, finb, x5);
    // 10. LM head — tf32 tensor cores
    tgemm_k<0,false,false><<<dim3((NV + TBN - 1)/TBN, S/TBM, 1), 256>>>(x5, headw, out, S, NV, D,
                                                                        nullptr, nullptr, nullptr, 0, 0, 0);
}

// round 4
// speedup vs baseline: 2.3649x; 1.5179x over previous
#include <cuda_runtime.h>
#include <math.h>
#include <stdint.h>

#define S    1024
#define D    2048
#define NH   32
#define HD   64
#define FF   8192
#define NE   4
#define NV   50257
#define BLKQ 64
#define NB   16   // S / BLKQ

// ---------------- scratch (static device globals; no runtime alloc) ----------------
__device__ float g_x  [S*D];
__device__ float g_q  [S*D];
__device__ float g_k  [S*D];
__device__ float g_v  [S*D];
__device__ float g_att[S*D];
__device__ float g_x1 [S*D];
__device__ float g_x2 [S*D];
__device__ float g_x3 [S*D];
__device__ float g_x4 [S*D];
__device__ float g_x5 [S*D];
__device__ float g_moe[S*D];
__device__ float g_t1 [(long)NE*S*FF];
__device__ float g_t2 [(long)NE*S*FF];
__device__ int   g_cnt[NE];
__device__ int   g_list[NE*S];
__device__ float g_wgt[NE*S];
__device__ float g_var[S];

// ---------------- init ----------------
__global__ void zero_kernel(float* moe) {
    long i = (long)blockIdx.x * blockDim.x + threadIdx.x;
    if (i < (long)S*D) moe[i] = 0.f;
    if (i < NE) g_cnt[i] = 0;
}

// ---------------- embedding gather ----------------
__global__ void embed_kernel(const int* __restrict__ tok, const float* __restrict__ emb,
                             float* __restrict__ x) {
    int t = blockIdx.x;
    long r = (long)tok[t] * D;
    for (int d = threadIdx.x; d < D; d += blockDim.x)
        x[(long)t*D + d] = emb[r + d];
}

// ---------------- RoPE ----------------
__global__ void rope_kernel(float* __restrict__ q, float* __restrict__ k) {
    int idx = blockIdx.x * blockDim.x + threadIdx.x;
    if (idx >= S*NH*(HD/2)) return;
    int j = idx & 31;
    int h = (idx >> 5) & 31;
    int s = idx >> 10;
    double inv = pow(10000.0, -(double)(2*j) / (double)HD);
    double ang = (double)s * inv;
    float c = (float)cos(ang), sn = (float)sin(ang);
    long base = (long)s*D + h*HD + 2*j;
    float q0 = q[base], q1 = q[base+1];
    q[base]   = q0*c - q1*sn;
    q[base+1] = q0*sn + q1*c;
    float k0 = k[base], k1 = k[base+1];
    k[base]   = k0*c - k1*sn;
    k[base+1] = k0*sn + k1*c;
}

// ---------------- attention (per-block-max softmax, matches reference) ----------------
#define ATTN_SMEM ((64*64 + 64*65 + 64*64 + 8*64) * 4)
__global__ void attn_kernel(const float* __restrict__ q, const float* __restrict__ k,
                            const float* __restrict__ v, float* __restrict__ o) {
    int h  = blockIdx.x;
    int ib = blockIdx.y;
    extern __shared__ float sm[];
    float* Qs = sm;
    float* Ks = Qs + 64*64;
    float* Vs = Ks + 64*65;
    float* Ps = Vs + 64*64;
    int tid = threadIdx.x;
    int w = tid >> 5, l = tid & 31;

    for (int idx = tid; idx < 64*64; idx += 256) {
        int r = idx >> 6, c = idx & 63;
        Qs[r*64 + c] = q[((long)(ib*BLKQ + r))*D + h*HD + c];
    }
    float num0[8], num1[8], den[8];
    #pragma unroll
    for (int r = 0; r < 8; r++) { num0[r]=0.f; num1[r]=0.f; den[r]=0.f; }

    for (int jb = 0; jb <= ib; jb++) {
        __syncthreads();
        for (int idx = tid; idx < 64*64; idx += 256) {
            int r = idx >> 6, c = idx & 63;
            Ks[r*65 + c] = k[((long)(jb*BLKQ + r))*D + h*HD + c];
            Vs[r*64 + c] = v[((long)(jb*BLKQ + r))*D + h*HD + c];
        }
        __syncthreads();
        for (int r = 0; r < 8; r++) {
            int qr = w*8 + r;
            float s0 = 0.f, s1 = 0.f;
            #pragma unroll 8
            for (int d = 0; d < HD; d++) {
                float qv = Qs[qr*64 + d];
                s0 = fmaf(qv, Ks[l*65 + d], s0);
                s1 = fmaf(qv, Ks[(l+32)*65 + d], s1);
            }
            s0 *= 0.125f; s1 *= 0.125f;
            if (jb == ib) {
                if (l      > qr) s0 = -INFINITY;
                if (l + 32 > qr) s1 = -INFINITY;
            }
            float m = fmaxf(s0, s1);
            #pragma unroll
            for (int off = 16; off; off >>= 1)
                m = fmaxf(m, __shfl_xor_sync(0xffffffffu, m, off));
            float p0 = expf(s0 - m), p1 = expf(s1 - m);
            float ds = p0 + p1;
            #pragma unroll
            for (int off = 16; off; off >>= 1)
                ds += __shfl_xor_sync(0xffffffffu, ds, off);
            den[r] += ds;
            Ps[w*64 + l] = p0; Ps[w*64 + l + 32] = p1;
            __syncwarp();
            #pragma unroll 8
            for (int kk = 0; kk < 64; kk++) {
                float pk = Ps[w*64 + kk];
                num0[r] = fmaf(pk, Vs[kk*64 + l],      num0[r]);
                num1[r] = fmaf(pk, Vs[kk*64 + l + 32], num1[r]);
            }
            __syncwarp();
        }
    }
    for (int r = 0; r < 8; r++) {
        int qr = w*8 + r;
        float dinv = 1.0f / (den[r] + 1e-6f);
        long base = ((long)(ib*BLKQ + qr))*D + h*HD;
        o[base + l]      = num0[r] * dinv;
        o[base + l + 32] = num1[r] * dinv;
    }
}

// ---------------- layernorm ----------------
__global__ void ln_kernel(const float* __restrict__ x, const float* __restrict__ g,
                          const float* __restrict__ b, float* __restrict__ y) {
    int t = blockIdx.x;
    __shared__ float red[256];
    const float* row = x + (long)t*D;
    float s = 0.f;
    for (int d = threadIdx.x; d < D; d += 256) s += row[d];
    red[threadIdx.x] = s; __syncthreads();
    for (int o = 128; o; o >>= 1) { if (threadIdx.x < o) red[threadIdx.x] += red[threadIdx.x+o]; __syncthreads(); }
    float mu = red[0] / (float)D;
    __syncthreads();
    float vs = 0.f;
    for (int d = threadIdx.x; d < D; d += 256) { float dd = row[d]-mu; vs = fmaf(dd, dd, vs); }
    red[threadIdx.x] = vs; __syncthreads();
    for (int o = 128; o; o >>= 1) { if (threadIdx.x < o) red[threadIdx.x] += red[threadIdx.x+o]; __syncthreads(); }
    float inv = 1.0f / sqrtf(red[0]/(float)D + 1e-5f);
    for (int d = threadIdx.x; d < D; d += 256)
        y[(long)t*D + d] = (row[d]-mu)*inv*g[d] + b[d];
}

// ---------------- gate ----------------
__global__ void gate_kernel(const float* __restrict__ x, const float* __restrict__ gw) {
    int t = blockIdx.x;
    int tid = threadIdx.x;  // 128
    __shared__ float red[4][128];
    const float* row = x + (long)t*D;
    float p[4] = {0.f,0.f,0.f,0.f};
    for (int d = tid; d < D; d += 128) {
        float xv = row[d];
        #pragma unroll
        for (int e = 0; e < 4; e++) p[e] = fmaf(xv, gw[e*D + d], p[e]);
    }
    #pragma unroll
    for (int e = 0; e < 4; e++) red[e][tid] = p[e];
    __syncthreads();
    for (int o = 64; o; o >>= 1) {
        if (tid < o) {
            red[0][tid] += red[0][tid+o];
            red[1][tid] += red[1][tid+o];
            red[2][tid] += red[2][tid+o];
            red[3][tid] += red[3][tid+o];
        }
        __syncthreads();
    }
    if (tid == 0) {
        float l[4];
        #pragma unroll
        for (int e = 0; e < 4; e++) l[e] = red[e][0];
        float mu = (l[0]+l[1]+l[2]+l[3]) * 0.25f;
        float var = 0.f;
        #pragma unroll
        for (int e = 0; e < 4; e++) { float d0 = l[e]-mu; var = fmaf(d0, d0, var); }
        g_var[t] = var / 3.0f;
        int i1 = 0;
        for (int e = 1; e < 4; e++) if (l[e] > l[i1]) i1 = e;
        int i2 = (i1 == 0) ? 1 : 0;
        for (int e = 0; e < 4; e++) if (e != i1 && l[e] > l[i2]) i2 = e;
        float m = fmaxf(fmaxf(l[0],l[1]), fmaxf(l[2],l[3]));
        float e1 = expf(l[i1]-m), e2 = expf(l[i2]-m);
        float w1 = e1/(e1+e2), w2 = e2/(e1+e2);
        int pos1 = atomicAdd(&g_cnt[i1], 1);
        g_list[i1*S + pos1] = t; g_wgt[i1*S + pos1] = w1;
        int pos2 = atomicAdd(&g_cnt[i2], 1);
        g_list[i2*S + pos2] = t; g_wgt[i2*S + pos2] = w2;
    }
}

// ---------------- aux ----------------
__global__ void aux_kernel(float* __restrict__ out, int out_size) {
    __shared__ float red[256];
    float s = 0.f;
    for (int i = threadIdx.x; i < S; i += 256) s += g_var[i];
    red[threadIdx.x] = s; __syncthreads();
    for (int o = 128; o; o >>= 1) { if (threadIdx.x < o) red[threadIdx.x] += red[threadIdx.x+o]; __syncthreads(); }
    if (threadIdx.x == 0) {
        long pos = (long)S * NV;
        if ((long)out_size > pos) out[pos] = red[0] / (float)S;
    }
}

// ---------------- silu-gate on valid routed rows only ----------------
__global__ void silu_kernel() {
    int row = blockIdx.x;            // e*S + slot
    int e = row >> 10;
    int slot = row & (S-1);
    if (slot >= g_cnt[e]) return;
    long base = (long)row * FF;
    for (int i = threadIdx.x; i < FF; i += 256) {
        float a = g_t1[base + i], b = g_t2[base + i];
        g_t1[base + i] = b * (a / (1.0f + expf(-a)));
    }
}

// ---------------- elementwise add ----------------
__global__ void add_kernel(const float* __restrict__ a, const float* __restrict__ b,
                           float* __restrict__ c) {
    long i = (long)blockIdx.x * 256 + threadIdx.x;
    if (i < (long)S*D) c[i] = a[i] + b[i];
}

// ================= fp32 SGEMM (exact routing path) =================
constexpr int BM = 128, BN = 128, BKs = 8;

// shared tile-compute body used by both fp32 kernels
template<int EPI>
__device__ __forceinline__ void sgemm_body(
    const float* __restrict__ A, const float* __restrict__ Bm, float* __restrict__ Cm,
    int M, int N, int K, int m0, int n0, const float* __restrict__ resid)
{
    __shared__ float As[BKs][BM];
    __shared__ float Bs[BKs][BN];
    int tid = threadIdx.x;
    int tx = tid & 15, ty = tid >> 4;

    float acc[8][8];
    #pragma unroll
    for (int i = 0; i < 8; i++)
        #pragma unroll
        for (int j = 0; j < 8; j++) acc[i][j] = 0.f;

    int am = tid >> 1, aseg = (tid & 1) * 4;
    int arow = m0 + am;
    bool avld = arow < M;
    const float* Ap = avld ? (A + (long)arow * K + aseg) : nullptr;
    int bn = tid >> 1, bseg = (tid & 1) * 4;
    int brow = n0 + bn;
    bool bvld = brow < N;
    const float* Bp = bvld ? (Bm + (long)brow * K + bseg) : nullptr;

    for (int k0 = 0; k0 < K; k0 += BKs) {
        float4 a4 = avld ? *(const float4*)(Ap + k0) : make_float4(0.f,0.f,0.f,0.f);
        float4 b4 = bvld ? *(const float4*)(Bp + k0) : make_float4(0.f,0.f,0.f,0.f);
        __syncthreads();
        As[aseg+0][am] = a4.x; As[aseg+1][am] = a4.y; As[aseg+2][am] = a4.z; As[aseg+3][am] = a4.w;
        Bs[bseg+0][bn] = b4.x; Bs[bseg+1][bn] = b4.y; Bs[bseg+2][bn] = b4.z; Bs[bseg+3][bn] = b4.w;
        __syncthreads();
        #pragma unroll
        for (int kk = 0; kk < BKs; kk++) {
            float a[8], b[8];
            #pragma unroll
            for (int i = 0; i < 8; i++) a[i] = As[kk][ty*8 + i];
            #pragma unroll
            for (int j = 0; j < 8; j++) b[j] = Bs[kk][tx*8 + j];
            #pragma unroll
            for (int i = 0; i < 8; i++)
                #pragma unroll
                for (int j = 0; j < 8; j++)
                    acc[i][j] = fmaf(a[i], b[j], acc[i][j]);
        }
    }
    #pragma unroll
    for (int i = 0; i < 8; i++) {
        int m = m0 + ty*8 + i;
        if (m >= M) continue;
        #pragma unroll
        for (int j = 0; j < 8; j++) {
            int n = n0 + tx*8 + j;
            if (n >= N) continue;
            if constexpr (EPI == 0) Cm[(long)m*N + n] = acc[i][j];
            else                    Cm[(long)m*N + n] = acc[i][j] + resid[(long)m*N + n];
        }
    }
}

__global__ void __launch_bounds__(256)
wo_gemm(const float* __restrict__ A, const float* __restrict__ Bm, float* __restrict__ Cm,
        const float* __restrict__ resid) {
    sgemm_body<1>(A, Bm, Cm, S, D, D, blockIdx.y * BM, blockIdx.x * BN, resid);
}

// batched QKV: grid.z selects weight + destination
__global__ void __launch_bounds__(256)
qkv_gemm(const float* __restrict__ x,
         const float* __restrict__ wq, const float* __restrict__ wk, const float* __restrict__ wv,
         float* __restrict__ q, float* __restrict__ k, float* __restrict__ v) {
    const float* Bm = (blockIdx.z == 0) ? wq : (blockIdx.z == 1) ? wk : wv;
    float*       Cm = (blockIdx.z == 0) ? q  : (blockIdx.z == 1) ? k  : v;
    sgemm_body<0>(x, Bm, Cm, S, D, D, blockIdx.y * BM, blockIdx.x * BN, nullptr);
}

// ================= tf32 tensor-core GEMM: C[M,N] = A[M,K] @ B[N,K]^T =================
// 128x128x32 tiles, 256 thr = 8 warps (2 M x 4 N), warp tile 64x32 via mma.m16n8k8.
// Smem layout [row][k] pad 36: conflict-free fragment loads + aligned float4 stores.
constexpr int TBM = 128, TBN = 128, TBK = 32;
constexpr int APAD = 36;
constexpr size_t TSMEM = (size_t)2 * TBM * APAD * sizeof(float) * 2;   // 73728 B

__device__ __forceinline__ float f2tf32(float x) {
    uint32_t u;
    asm("cvt.rna.tf32.f32 %0, %1;" : "=r"(u) : "f"(x));
    return __uint_as_float(u);
}

template<int EPI, bool GA, bool GCNT>
__global__ void __launch_bounds__(256, 1)
tgemm_k(const float* __restrict__ A, const float* __restrict__ Bm, float* __restrict__ Cm,
        int M, int N, int K,
        const int* __restrict__ cnt, const int* __restrict__ rowidx,
        const float* __restrict__ roww,
        long sAz, long sBz, long sCz)
{
    extern __shared__ float sh[];
    int z = blockIdx.z;
    A  += (long)z * sAz;
    Bm += (long)z * sBz;
    Cm += (long)z * sCz;
    const int*   ridx = rowidx ? rowidx + z*S : nullptr;
    const float* rw   = roww   ? roww   + z*S : nullptr;
    int Meff = GCNT ? cnt[z] : M;
    int m0 = blockIdx.y * TBM, n0 = blockIdx.x * TBN;
    if (m0 >= Meff) return;

    float (*As)[TBM][APAD] = (float (*)[TBM][APAD])sh;
    float (*Bs)[TBN][APAD] = (float (*)[TBN][APAD])(sh + 2*TBM*APAD);

    int tid = threadIdx.x, lane = tid & 31, wid = tid >> 5;
    int wm = (wid & 1) * 64;
    int wn = (wid >> 1) * 32;
    int lr = lane >> 2;          // 0..7
    int lc = lane & 3;           // 0..3

    float acc[4][4][4];
    #pragma unroll
    for (int mt = 0; mt < 4; mt++)
        #pragma unroll
        for (int nt = 0; nt < 4; nt++)
            #pragma unroll
            for (int r = 0; r < 4; r++) acc[mt][nt][r] = 0.f;

    // loader mapping: thread handles rows r0+32i at k-offset kq (float4)
    int kq = (tid & 7) * 4;
    int r0l = tid >> 3;
    const float* Ap[4];
    const float* Bp[4];
    #pragma unroll
    for (int i = 0; i < 4; i++) {
        int ar = r0l + 32*i;
        int arow = m0 + ar;
        bool av = arow < Meff;
        long grow = av ? (GA ? (long)ridx[arow] : (long)arow) : 0;
        Ap[i] = av ? (A + grow*(long)K + kq) : nullptr;
        int brow = n0 + ar;
        Bp[i] = (brow < N) ? (Bm + (long)brow*K + kq) : nullptr;
    }

    float4 sa[4], sb[4];
    auto gload = [&](int kt) {
        #pragma unroll
        for (int i = 0; i < 4; i++) {
            sa[i] = Ap[i] ? *(const float4*)(Ap[i] + (long)kt*TBK) : make_float4(0.f,0.f,0.f,0.f);
            sb[i] = Bp[i] ? *(const float4*)(Bp[i] + (long)kt*TBK) : make_float4(0.f,0.f,0.f,0.f);
        }
    };
    auto sstore = [&](int buf) {
        #pragma unroll
        for (int i = 0; i < 4; i++) {
            int ar = r0l + 32*i;
            float4 ta = make_float4(f2tf32(sa[i].x), f2tf32(sa[i].y), f2tf32(sa[i].z), f2tf32(sa[i].w));
            float4 tb = make_float4(f2tf32(sb[i].x), f2tf32(sb[i].y), f2tf32(sb[i].z), f2tf32(sb[i].w));
            *(float4*)&As[buf][ar][kq] = ta;
            *(float4*)&Bs[buf][ar][kq] = tb;
        }
    };

    int ktiles = K / TBK;
    gload(0);
    sstore(0);
    __syncthreads();

    for (int t = 0; t < ktiles; t++) {
        int buf = t & 1;
        bool more = (t + 1) < ktiles;
        if (more) gload(t + 1);

        #pragma unroll
        for (int ks = 0; ks < 4; ks++) {
            int kb = ks * 8;
            uint32_t af[4][4], bf[4][2];
            #pragma unroll
            for (int mt = 0; mt < 4; mt++) {
                int r = wm + mt*16 + lr;
                af[mt][0] = __float_as_uint(As[buf][r    ][kb + lc    ]);
                af[mt][1] = __float_as_uint(As[buf][r + 8][kb + lc    ]);
                af[mt][2] = __float_as_uint(As[buf][r    ][kb + lc + 4]);
                af[mt][3] = __float_as_uint(As[buf][r + 8][kb + lc + 4]);
            }
            #pragma unroll
            for (int nt = 0; nt < 4; nt++) {
                int c = wn + nt*8 + lr;
                bf[nt][0] = __float_as_uint(Bs[buf][c][kb + lc    ]);
                bf[nt][1] = __float_as_uint(Bs[buf][c][kb + lc + 4]);
            }
            #pragma unroll
            for (int mt = 0; mt < 4; mt++)
                #pragma unroll
                for (int nt = 0; nt < 4; nt++) {
                    asm volatile(
                        "mma.sync.aligned.m16n8k8.row.col.f32.tf32.tf32.f32 "
                        "{%0,%1,%2,%3}, {%4,%5,%6,%7}, {%8,%9}, {%0,%1,%2,%3};"
                        : "+f"(acc[mt][nt][0]), "+f"(acc[mt][nt][1]),
                          "+f"(acc[mt][nt][2]), "+f"(acc[mt][nt][3])
                        : "r"(af[mt][0]), "r"(af[mt][1]), "r"(af[mt][2]), "r"(af[mt][3]),
                          "r"(bf[nt][0]), "r"(bf[nt][1]));
                }
        }

        if (more) {
            sstore(buf ^ 1);
            __syncthreads();
        }
    }

    // ---------------- epilogue ----------------
    #pragma unroll
    for (int mt = 0; mt < 4; mt++) {
        int r0 = m0 + wm + mt*16 + lr;
        int r1 = r0 + 8;
        #pragma unroll
        for (int nt = 0; nt < 4; nt++) {
            int c0 = n0 + wn + nt*8 + (lc << 1);
            int c1 = c0 + 1;
            if constexpr (EPI == 0) {
                if (r0 < Meff) {
                    if (c0 < N) Cm[(long)r0*N + c0] = acc[mt][nt][0];
                    if (c1 < N) Cm[(long)r0*N + c1] = acc[mt][nt][1];
                }
                if (r1 < Meff) {
                    if (c0 < N) Cm[(long)r1*N + c0] = acc[mt][nt][2];
                    if (c1 < N) Cm[(long)r1*N + c1] = acc[mt][nt][3];
                }
            } else {
                if (r0 < Meff) {
                    long orow = (long)ridx[r0] * N;
                    float w = rw[r0];
                    if (c0 < N) atomicAdd(&Cm[orow + c0], acc[mt][nt][0] * w);
                    if (c1 < N) atomicAdd(&Cm[orow + c1], acc[mt][nt][1] * w);
                }
                if (r1 < Meff) {
                    long orow = (long)ridx[r1] * N;
                    float w = rw[r1];
                    if (c0 < N) atomicAdd(&Cm[orow + c0], acc[mt][nt][2] * w);
                    if (c1 < N) atomicAdd(&Cm[orow + c1], acc[mt][nt][3] * w);
                }
            }
        }
    }
}

// ---------------- launcher ----------------
extern "C" void kernel_launch(void* const* d_in, const int* in_sizes, int n_in,
                              void* d_out, int out_size) {
    const int*   tokens = (const int*)  d_in[0];
    const float* emb    = (const float*)d_in[1];
    const float* wq     = (const float*)d_in[2];
    const float* wk     = (const float*)d_in[3];
    const float* wv     = (const float*)d_in[4];
    const float* wo     = (const float*)d_in[5];
    const float* ln1g   = (const float*)d_in[6];
    const float* ln1b   = (const float*)d_in[7];
    const float* gatew  = (const float*)d_in[8];
    const float* w1     = (const float*)d_in[9];
    const float* w2     = (const float*)d_in[10];
    const float* w3     = (const float*)d_in[11];
    const float* ln2g   = (const float*)d_in[12];
    const float* ln2b   = (const float*)d_in[13];
    const float* fing   = (const float*)d_in[14];
    const float* finb   = (const float*)d_in[15];
    const float* headw  = (const float*)d_in[16];
    float* out = (float*)d_out;

    float *x, *q, *k, *v, *att, *x1, *x2, *x3, *x4, *x5, *moe, *t1, *t2, *wgt;
    int *cnt, *lst;
    cudaGetSymbolAddress((void**)&x,   g_x);
    cudaGetSymbolAddress((void**)&q,   g_q);
    cudaGetSymbolAddress((void**)&k,   g_k);
    cudaGetSymbolAddress((void**)&v,   g_v);
    cudaGetSymbolAddress((void**)&att, g_att);
    cudaGetSymbolAddress((void**)&x1,  g_x1);
    cudaGetSymbolAddress((void**)&x2,  g_x2);
    cudaGetSymbolAddress((void**)&x3,  g_x3);
    cudaGetSymbolAddress((void**)&x4,  g_x4);
    cudaGetSymbolAddress((void**)&x5,  g_x5);
    cudaGetSymbolAddress((void**)&moe, g_moe);
    cudaGetSymbolAddress((void**)&t1,  g_t1);
    cudaGetSymbolAddress((void**)&t2,  g_t2);
    cudaGetSymbolAddress((void**)&wgt, g_wgt);
    cudaGetSymbolAddress((void**)&cnt, g_cnt);
    cudaGetSymbolAddress((void**)&lst, g_list);

    cudaFuncSetAttribute(attn_kernel, cudaFuncAttributeMaxDynamicSharedMemorySize, ATTN_SMEM);
    cudaFuncSetAttribute(tgemm_k<0,true,true>,   cudaFuncAttributeMaxDynamicSharedMemorySize, (int)TSMEM);
    cudaFuncSetAttribute(tgemm_k<2,false,true>,  cudaFuncAttributeMaxDynamicSharedMemorySize, (int)TSMEM);
    cudaFuncSetAttribute(tgemm_k<0,false,false>, cudaFuncAttributeMaxDynamicSharedMemorySize, (int)TSMEM);

    // 0. init
    zero_kernel<<<(S*D + 255)/256, 256>>>(moe);
    // 1. embedding
    embed_kernel<<<S, 256>>>(tokens, emb, x);
    // 2. QKV projections (fp32, batched over z)
    qkv_gemm<<<dim3(D/BN, S/BM, 3), 256>>>(x, wq, wk, wv, q, k, v);
    // 3. RoPE
    rope_kernel<<<(S*NH*(HD/2))/256, 256>>>(q, k);
    // 4. attention
    attn_kernel<<<dim3(NH, NB), 256, ATTN_SMEM>>>(q, k, v, att);
    // 5. output projection + residual (fp32)
    wo_gemm<<<dim3(D/BN, S/BM, 1), 256>>>(att, wo, x1, x);
    // 6. layernorm 1
    ln_kernel<<<S, 256>>>(x1, ln1g, ln1b, x2);
    // 7. gating + routing + per-token variance
    gate_kernel<<<S, 128>>>(x2, gatew);
    aux_kernel<<<1, 256>>>(out, out_size);
    // 8. MoE expert GEMMs — tf32 tensor cores
    tgemm_k<0,true,true><<<dim3(FF/TBN, S/TBM, NE), 256, TSMEM>>>(x2, w1, t1, S, FF, D, cnt, lst, nullptr,
                                                                  0, (long)FF*D, (long)S*FF);
    tgemm_k<0,true,true><<<dim3(FF/TBN, S/TBM, NE), 256, TSMEM>>>(x2, w3, t2, S, FF, D, cnt, lst, nullptr,
                                                                  0, (long)FF*D, (long)S*FF);
    silu_kernel<<<NE*S, 256>>>();
    tgemm_k<2,false,true><<<dim3(D/TBN, S/TBM, NE), 256, TSMEM>>>(t1, w2, moe, S, D, FF, cnt, lst, wgt,
                                                                  (long)S*FF, (long)D*FF, 0);
    // 9. residual + layernorm 2 + final layernorm
    add_kernel<<<(S*D + 255)/256, 256>>>(moe, x2, x3);
    ln_kernel<<<S, 256>>>(x3, ln2g, ln2b, x4);
    ln_kernel<<<S, 256>>>(x4, fing, finb, x5);
    // 10. LM head — tf32 tensor cores
    tgemm_k<0,false,false><<<dim3((NV + TBN - 1)/TBN, S/TBM, 1), 256, TSMEM>>>(x5, headw, out, S, NV, D,
                                                                               nullptr, nullptr, nullptr, 0, 0, 0);
}

// round 5
// speedup vs baseline: 2.5017x; 1.0578x over previous
#include <cuda_runtime.h>
#include <math.h>
#include <stdint.h>

#define S    1024
#define D    2048
#define NH   32
#define HD   64
#define FF   8192
#define NE   4
#define NV   50257
#define BLKQ 64
#define NB   16   // S / BLKQ

// ---------------- scratch (static device globals; no runtime alloc) ----------------
__device__ float g_x  [S*D];
__device__ float g_q  [S*D];
__device__ float g_k  [S*D];
__device__ float g_v  [S*D];
__device__ float g_att[S*D];
__device__ float g_x1 [S*D];
__device__ float g_x2 [S*D];
__device__ float g_x3 [S*D];
__device__ float g_x4 [S*D];
__device__ float g_x5 [S*D];
__device__ float g_moe[S*D];
__device__ float g_t1 [(long)NE*S*FF];
__device__ float g_t2 [(long)NE*S*FF];
__device__ int   g_cnt[NE];
__device__ int   g_list[NE*S];
__device__ float g_wgt[NE*S];
__device__ float g_var[S];
__device__ float g_cos[S*32];
__device__ float g_sin[S*32];

// ---------------- init ----------------
__global__ void zero_kernel(float* moe) {
    long i = (long)blockIdx.x * blockDim.x + threadIdx.x;
    if (i < (long)S*D) moe[i] = 0.f;
    if (i < NE) g_cnt[i] = 0;
}

// ---------------- embedding gather ----------------
__global__ void embed_kernel(const int* __restrict__ tok, const float* __restrict__ emb,
                             float* __restrict__ x) {
    int t = blockIdx.x;
    long r = (long)tok[t] * D;
    for (int d = threadIdx.x; d < D; d += blockDim.x)
        x[(long)t*D + d] = emb[r + d];
}

// ---------------- RoPE tables (fp64, once: 32K entries instead of 1M fp64 evals) ------
__global__ void rope_table_kernel() {
    int idx = blockIdx.x * blockDim.x + threadIdx.x;   // S*32
    if (idx >= S*32) return;
    int j = idx & 31;
    int s = idx >> 5;
    double inv = pow(10000.0, -(double)(2*j) / (double)HD);
    double ang = (double)s * inv;
    g_cos[idx] = (float)cos(ang);
    g_sin[idx] = (float)sin(ang);
}

// ---------------- RoPE apply (table lookup) ----------------
__global__ void rope_kernel(float* __restrict__ q, float* __restrict__ k) {
    int idx = blockIdx.x * blockDim.x + threadIdx.x;     // S * NH * (HD/2)
    if (idx >= S*NH*(HD/2)) return;
    int j = idx & 31;
    int h = (idx >> 5) & 31;
    int s = idx >> 10;
    float c  = g_cos[s*32 + j];
    float sn = g_sin[s*32 + j];
    long base = (long)s*D + h*HD + 2*j;
    float q0 = q[base], q1 = q[base+1];
    q[base]   = q0*c - q1*sn;
    q[base+1] = q0*sn + q1*c;
    float k0 = k[base], k1 = k[base+1];
    k[base]   = k0*c - k1*sn;
    k[base+1] = k0*sn + k1*c;
}

// ---------------- attention (per-block-max softmax, matches reference) ----------------
#define ATTN_SMEM ((64*64 + 64*65 + 64*64 + 8*64) * 4)
__global__ void attn_kernel(const float* __restrict__ q, const float* __restrict__ k,
                            const float* __restrict__ v, float* __restrict__ o) {
    int h  = blockIdx.x;
    int ib = blockIdx.y;
    extern __shared__ float sm[];
    float* Qs = sm;
    float* Ks = Qs + 64*64;
    float* Vs = Ks + 64*65;
    float* Ps = Vs + 64*64;
    int tid = threadIdx.x;
    int w = tid >> 5, l = tid & 31;

    for (int idx = tid; idx < 64*64; idx += 256) {
        int r = idx >> 6, c = idx & 63;
        Qs[r*64 + c] = q[((long)(ib*BLKQ + r))*D + h*HD + c];
    }
    float num0[8], num1[8], den[8];
    #pragma unroll
    for (int r = 0; r < 8; r++) { num0[r]=0.f; num1[r]=0.f; den[r]=0.f; }

    for (int jb = 0; jb <= ib; jb++) {
        __syncthreads();
        for (int idx = tid; idx < 64*64; idx += 256) {
            int r = idx >> 6, c = idx & 63;
            Ks[r*65 + c] = k[((long)(jb*BLKQ + r))*D + h*HD + c];
            Vs[r*64 + c] = v[((long)(jb*BLKQ + r))*D + h*HD + c];
        }
        __syncthreads();
        for (int r = 0; r < 8; r++) {
            int qr = w*8 + r;
            float s0 = 0.f, s1 = 0.f;
            #pragma unroll 8
            for (int d = 0; d < HD; d++) {
                float qv = Qs[qr*64 + d];
                s0 = fmaf(qv, Ks[l*65 + d], s0);
                s1 = fmaf(qv, Ks[(l+32)*65 + d], s1);
            }
            s0 *= 0.125f; s1 *= 0.125f;
            if (jb == ib) {
                if (l      > qr) s0 = -INFINITY;
                if (l + 32 > qr) s1 = -INFINITY;
            }
            float m = fmaxf(s0, s1);
            #pragma unroll
            for (int off = 16; off; off >>= 1)
                m = fmaxf(m, __shfl_xor_sync(0xffffffffu, m, off));
            float p0 = expf(s0 - m), p1 = expf(s1 - m);
            float ds = p0 + p1;
            #pragma unroll
            for (int off = 16; off; off >>= 1)
                ds += __shfl_xor_sync(0xffffffffu, ds, off);
            den[r] += ds;
            Ps[w*64 + l] = p0; Ps[w*64 + l + 32] = p1;
            __syncwarp();
            #pragma unroll 8
            for (int kk = 0; kk < 64; kk++) {
                float pk = Ps[w*64 + kk];
                num0[r] = fmaf(pk, Vs[kk*64 + l],      num0[r]);
                num1[r] = fmaf(pk, Vs[kk*64 + l + 32], num1[r]);
            }
            __syncwarp();
        }
    }
    for (int r = 0; r < 8; r++) {
        int qr = w*8 + r;
        float dinv = 1.0f / (den[r] + 1e-6f);
        long base = ((long)(ib*BLKQ + qr))*D + h*HD;
        o[base + l]      = num0[r] * dinv;
        o[base + l + 32] = num1[r] * dinv;
    }
}

// ---------------- layernorm ----------------
__global__ void ln_kernel(const float* __restrict__ x, const float* __restrict__ g,
                          const float* __restrict__ b, float* __restrict__ y) {
    int t = blockIdx.x;
    __shared__ float red[256];
    const float* row = x + (long)t*D;
    float s = 0.f;
    for (int d = threadIdx.x; d < D; d += 256) s += row[d];
    red[threadIdx.x] = s; __syncthreads();
    for (int o = 128; o; o >>= 1) { if (threadIdx.x < o) red[threadIdx.x] += red[threadIdx.x+o]; __syncthreads(); }
    float mu = red[0] / (float)D;
    __syncthreads();
    float vs = 0.f;
    for (int d = threadIdx.x; d < D; d += 256) { float dd = row[d]-mu; vs = fmaf(dd, dd, vs); }
    red[threadIdx.x] = vs; __syncthreads();
    for (int o = 128; o; o >>= 1) { if (threadIdx.x < o) red[threadIdx.x] += red[threadIdx.x+o]; __syncthreads(); }
    float inv = 1.0f / sqrtf(red[0]/(float)D + 1e-5f);
    for (int d = threadIdx.x; d < D; d += 256)
        y[(long)t*D + d] = (row[d]-mu)*inv*g[d] + b[d];
}

// ---------------- gate ----------------
__global__ void gate_kernel(const float* __restrict__ x, const float* __restrict__ gw) {
    int t = blockIdx.x;
    int tid = threadIdx.x;  // 128
    __shared__ float red[4][128];
    const float* row = x + (long)t*D;
    float p[4] = {0.f,0.f,0.f,0.f};
    for (int d = tid; d < D; d += 128) {
        float xv = row[d];
        #pragma unroll
        for (int e = 0; e < 4; e++) p[e] = fmaf(xv, gw[e*D + d], p[e]);
    }
    #pragma unroll
    for (int e = 0; e < 4; e++) red[e][tid] = p[e];
    __syncthreads();
    for (int o = 64; o; o >>= 1) {
        if (tid < o) {
            red[0][tid] += red[0][tid+o];
            red[1][tid] += red[1][tid+o];
            red[2][tid] += red[2][tid+o];
            red[3][tid] += red[3][tid+o];
        }
        __syncthreads();
    }
    if (tid == 0) {
        float l[4];
        #pragma unroll
        for (int e = 0; e < 4; e++) l[e] = red[e][0];
        float mu = (l[0]+l[1]+l[2]+l[3]) * 0.25f;
        float var = 0.f;
        #pragma unroll
        for (int e = 0; e < 4; e++) { float d0 = l[e]-mu; var = fmaf(d0, d0, var); }
        g_var[t] = var / 3.0f;
        int i1 = 0;
        for (int e = 1; e < 4; e++) if (l[e] > l[i1]) i1 = e;
        int i2 = (i1 == 0) ? 1 : 0;
        for (int e = 0; e < 4; e++) if (e != i1 && l[e] > l[i2]) i2 = e;
        float m = fmaxf(fmaxf(l[0],l[1]), fmaxf(l[2],l[3]));
        float e1 = expf(l[i1]-m), e2 = expf(l[i2]-m);
        float w1 = e1/(e1+e2), w2 = e2/(e1+e2);
        int pos1 = atomicAdd(&g_cnt[i1], 1);
        g_list[i1*S + pos1] = t; g_wgt[i1*S + pos1] = w1;
        int pos2 = atomicAdd(&g_cnt[i2], 1);
        g_list[i2*S + pos2] = t; g_wgt[i2*S + pos2] = w2;
    }
}

// ---------------- aux ----------------
__global__ void aux_kernel(float* __restrict__ out, int out_size) {
    __shared__ float red[256];
    float s = 0.f;
    for (int i = threadIdx.x; i < S; i += 256) s += g_var[i];
    red[threadIdx.x] = s; __syncthreads();
    for (int o = 128; o; o >>= 1) { if (threadIdx.x < o) red[threadIdx.x] += red[threadIdx.x+o]; __syncthreads(); }
    if (threadIdx.x == 0) {
        long pos = (long)S * NV;
        if ((long)out_size > pos) out[pos] = red[0] / (float)S;
    }
}

// ---------------- silu-gate on valid routed rows only ----------------
__global__ void silu_kernel() {
    int row = blockIdx.x;            // e*S + slot
    int e = row >> 10;
    int slot = row & (S-1);
    if (slot >= g_cnt[e]) return;
    long base = (long)row * FF;
    for (int i = threadIdx.x; i < FF; i += 256) {
        float a = g_t1[base + i], b = g_t2[base + i];
        g_t1[base + i] = b * (a / (1.0f + expf(-a)));
    }
}

// ---------------- elementwise add ----------------
__global__ void add_kernel(const float* __restrict__ a, const float* __restrict__ b,
                           float* __restrict__ c) {
    long i = (long)blockIdx.x * 256 + threadIdx.x;
    if (i < (long)S*D) c[i] = a[i] + b[i];
}

// ================= fp32 SGEMM (exact routing path) =================
constexpr int BM = 128, BN = 128, BKs = 8;

template<int EPI>
__device__ __forceinline__ void sgemm_body(
    const float* __restrict__ A, const float* __restrict__ Bm, float* __restrict__ Cm,
    int M, int N, int K, int m0, int n0, const float* __restrict__ resid)
{
    __shared__ float As[BKs][BM];
    __shared__ float Bs[BKs][BN];
    int tid = threadIdx.x;
    int tx = tid & 15, ty = tid >> 4;

    float acc[8][8];
    #pragma unroll
    for (int i = 0; i < 8; i++)
        #pragma unroll
        for (int j = 0; j < 8; j++) acc[i][j] = 0.f;

    int am = tid >> 1, aseg = (tid & 1) * 4;
    int arow = m0 + am;
    bool avld = arow < M;
    const float* Ap = avld ? (A + (long)arow * K + aseg) : nullptr;
    int bn = tid >> 1, bseg = (tid & 1) * 4;
    int brow = n0 + bn;
    bool bvld = brow < N;
    const float* Bp = bvld ? (Bm + (long)brow * K + bseg) : nullptr;

    for (int k0 = 0; k0 < K; k0 += BKs) {
        float4 a4 = avld ? *(const float4*)(Ap + k0) : make_float4(0.f,0.f,0.f,0.f);
        float4 b4 = bvld ? *(const float4*)(Bp + k0) : make_float4(0.f,0.f,0.f,0.f);
        __syncthreads();
        As[aseg+0][am] = a4.x; As[aseg+1][am] = a4.y; As[aseg+2][am] = a4.z; As[aseg+3][am] = a4.w;
        Bs[bseg+0][bn] = b4.x; Bs[bseg+1][bn] = b4.y; Bs[bseg+2][bn] = b4.z; Bs[bseg+3][bn] = b4.w;
        __syncthreads();
        #pragma unroll
        for (int kk = 0; kk < BKs; kk++) {
            float a[8], b[8];
            #pragma unroll
            for (int i = 0; i < 8; i++) a[i] = As[kk][ty*8 + i];
            #pragma unroll
            for (int j = 0; j < 8; j++) b[j] = Bs[kk][tx*8 + j];
            #pragma unroll
            for (int i = 0; i < 8; i++)
                #pragma unroll
                for (int j = 0; j < 8; j++)
                    acc[i][j] = fmaf(a[i], b[j], acc[i][j]);
        }
    }
    #pragma unroll
    for (int i = 0; i < 8; i++) {
        int m = m0 + ty*8 + i;
        if (m >= M) continue;
        #pragma unroll
        for (int j = 0; j < 8; j++) {
            int n = n0 + tx*8 + j;
            if (n >= N) continue;
            if constexpr (EPI == 0) Cm[(long)m*N + n] = acc[i][j];
            else                    Cm[(long)m*N + n] = acc[i][j] + resid[(long)m*N + n];
        }
    }
}

__global__ void __launch_bounds__(256)
wo_gemm(const float* __restrict__ A, const float* __restrict__ Bm, float* __restrict__ Cm,
        const float* __restrict__ resid) {
    sgemm_body<1>(A, Bm, Cm, S, D, D, blockIdx.y * BM, blockIdx.x * BN, resid);
}

__global__ void __launch_bounds__(256)
qkv_gemm(const float* __restrict__ x,
         const float* __restrict__ wq, const float* __restrict__ wk, const float* __restrict__ wv,
         float* __restrict__ q, float* __restrict__ k, float* __restrict__ v) {
    const float* Bm = (blockIdx.z == 0) ? wq : (blockIdx.z == 1) ? wk : wv;
    float*       Cm = (blockIdx.z == 0) ? q  : (blockIdx.z == 1) ? k  : v;
    sgemm_body<0>(x, Bm, Cm, S, D, D, blockIdx.y * BM, blockIdx.x * BN, nullptr);
}

// ================= tf32 tensor-core GEMM: C[M,N] = A[M,K] @ B[N,K]^T =================
// 128x128x16 tiles, 256 thr = 8 warps (2 M x 4 N), warp tile 64x32 via mma.m16n8k8.
// Smem [row][k] pad 20: conflict-free fragment loads; 40KB/CTA => 2 CTAs/SM.
constexpr int TBM = 128, TBN = 128, TBK = 16;
constexpr int APAD = 20;
constexpr size_t TSMEM = (size_t)2 * TBM * APAD * sizeof(float) * 2;   // 40960 B

__device__ __forceinline__ float f2tf32(float x) {
    uint32_t u;
    asm("cvt.rna.tf32.f32 %0, %1;" : "=r"(u) : "f"(x));
    return __uint_as_float(u);
}

template<int EPI, bool GA, bool GCNT>
__global__ void __launch_bounds__(256, 2)
tgemm_k(const float* __restrict__ A, const float* __restrict__ Bm, float* __restrict__ Cm,
        int M, int N, int K,
        const int* __restrict__ cnt, const int* __restrict__ rowidx,
        const float* __restrict__ roww,
        long sAz, long sBz, long sCz)
{
    extern __shared__ float sh[];
    int z = blockIdx.z;
    A  += (long)z * sAz;
    Bm += (long)z * sBz;
    Cm += (long)z * sCz;
    const int*   ridx = rowidx ? rowidx + z*S : nullptr;
    const float* rw   = roww   ? roww   + z*S : nullptr;
    int Meff = GCNT ? cnt[z] : M;
    int m0 = blockIdx.y * TBM, n0 = blockIdx.x * TBN;
    if (m0 >= Meff) return;

    float (*As)[TBM][APAD] = (float (*)[TBM][APAD])sh;
    float (*Bs)[TBN][APAD] = (float (*)[TBN][APAD])(sh + 2*TBM*APAD);

    int tid = threadIdx.x, lane = tid & 31, wid = tid >> 5;
    int wm = (wid & 1) * 64;
    int wn = (wid >> 1) * 32;
    int lr = lane >> 2;          // 0..7
    int lc = lane & 3;           // 0..3

    float acc[4][4][4];
    #pragma unroll
    for (int mt = 0; mt < 4; mt++)
        #pragma unroll
        for (int nt = 0; nt < 4; nt++)
            #pragma unroll
            for (int r = 0; r < 4; r++) acc[mt][nt][r] = 0.f;

    // loader: thread covers rows r0l, r0l+64 at k-offset kq (float4)
    int kq = (tid & 3) * 4;
    int r0l = tid >> 2;          // 0..63
    const float* Ap[2];
    const float* Bp[2];
    #pragma unroll
    for (int i = 0; i < 2; i++) {
        int ar = r0l + 64*i;
        int arow = m0 + ar;
        bool av = arow < Meff;
        long grow = av ? (GA ? (long)ridx[arow] : (long)arow) : 0;
        Ap[i] = av ? (A + grow*(long)K + kq) : nullptr;
        int brow = n0 + ar;
        Bp[i] = (brow < N) ? (Bm + (long)brow*K + kq) : nullptr;
    }

    float4 sa[2], sb[2];
    auto gload = [&](int kt) {
        #pragma unroll
        for (int i = 0; i < 2; i++) {
            sa[i] = Ap[i] ? *(const float4*)(Ap[i] + (long)kt*TBK) : make_float4(0.f,0.f,0.f,0.f);
            sb[i] = Bp[i] ? *(const float4*)(Bp[i] + (long)kt*TBK) : make_float4(0.f,0.f,0.f,0.f);
        }
    };
    auto sstore = [&](int buf) {
        #pragma unroll
        for (int i = 0; i < 2; i++) {
            int ar = r0l + 64*i;
            float4 ta = make_float4(f2tf32(sa[i].x), f2tf32(sa[i].y), f2tf32(sa[i].z), f2tf32(sa[i].w));
            float4 tb = make_float4(f2tf32(sb[i].x), f2tf32(sb[i].y), f2tf32(sb[i].z), f2tf32(sb[i].w));
            *(float4*)&As[buf][ar][kq] = ta;
            *(float4*)&Bs[buf][ar][kq] = tb;
        }
    };

    int ktiles = K / TBK;
    gload(0);
    sstore(0);
    __syncthreads();

    for (int t = 0; t < ktiles; t++) {
        int buf = t & 1;
        bool more = (t + 1) < ktiles;
        if (more) gload(t + 1);

        #pragma unroll
        for (int ks = 0; ks < 2; ks++) {
            int kb = ks * 8;
            uint32_t af[4][4], bf[4][2];
            #pragma unroll
            for (int mt = 0; mt < 4; mt++) {
                int r = wm + mt*16 + lr;
                af[mt][0] = __float_as_uint(As[buf][r    ][kb + lc    ]);
                af[mt][1] = __float_as_uint(As[buf][r + 8][kb + lc    ]);
                af[mt][2] = __float_as_uint(As[buf][r    ][kb + lc + 4]);
                af[mt][3] = __float_as_uint(As[buf][r + 8][kb + lc + 4]);
            }
            #pragma unroll
            for (int nt = 0; nt < 4; nt++) {
                int c = wn + nt*8 + lr;
                bf[nt][0] = __float_as_uint(Bs[buf][c][kb + lc    ]);
                bf[nt][1] = __float_as_uint(Bs[buf][c][kb + lc + 4]);
            }
            #pragma unroll
            for (int mt = 0; mt < 4; mt++)
                #pragma unroll
                for (int nt = 0; nt < 4; nt++) {
                    asm volatile(
                        "mma.sync.aligned.m16n8k8.row.col.f32.tf32.tf32.f32 "
                        "{%0,%1,%2,%3}, {%4,%5,%6,%7}, {%8,%9}, {%0,%1,%2,%3};"
                        : "+f"(acc[mt][nt][0]), "+f"(acc[mt][nt][1]),
                          "+f"(acc[mt][nt][2]), "+f"(acc[mt][nt][3])
                        : "r"(af[mt][0]), "r"(af[mt][1]), "r"(af[mt][2]), "r"(af[mt][3]),
                          "r"(bf[nt][0]), "r"(bf[nt][1]));
                }
        }

        if (more) {
            sstore(buf ^ 1);
            __syncthreads();
        }
    }

    // ---------------- epilogue ----------------
    #pragma unroll
    for (int mt = 0; mt < 4; mt++) {
        int r0 = m0 + wm + mt*16 + lr;
        int r1 = r0 + 8;
        #pragma unroll
        for (int nt = 0; nt < 4; nt++) {
            int c0 = n0 + wn + nt*8 + (lc << 1);
            int c1 = c0 + 1;
            if constexpr (EPI == 0) {
                if (r0 < Meff) {
                    if (c0 < N) Cm[(long)r0*N + c0] = acc[mt][nt][0];
                    if (c1 < N) Cm[(long)r0*N + c1] = acc[mt][nt][1];
                }
                if (r1 < Meff) {
                    if (c0 < N) Cm[(long)r1*N + c0] = acc[mt][nt][2];
                    if (c1 < N) Cm[(long)r1*N + c1] = acc[mt][nt][3];
                }
            } else {
                if (r0 < Meff) {
                    long orow = (long)ridx[r0] * N;
                    float w = rw[r0];
                    if (c0 < N) atomicAdd(&Cm[orow + c0], acc[mt][nt][0] * w);
                    if (c1 < N) atomicAdd(&Cm[orow + c1], acc[mt][nt][1] * w);
                }
                if (r1 < Meff) {
                    long orow = (long)ridx[r1] * N;
                    float w = rw[r1];
                    if (c0 < N) atomicAdd(&Cm[orow + c0], acc[mt][nt][2] * w);
                    if (c1 < N) atomicAdd(&Cm[orow + c1], acc[mt][nt][3] * w);
                }
            }
        }
    }
}

// ---------------- launcher ----------------
extern "C" void kernel_launch(void* const* d_in, const int* in_sizes, int n_in,
                              void* d_out, int out_size) {
    const int*   tokens = (const int*)  d_in[0];
    const float* emb    = (const float*)d_in[1];
    const float* wq     = (const float*)d_in[2];
    const float* wk     = (const float*)d_in[3];
    const float* wv     = (const float*)d_in[4];
    const float* wo     = (const float*)d_in[5];
    const float* ln1g   = (const float*)d_in[6];
    const float* ln1b   = (const float*)d_in[7];
    const float* gatew  = (const float*)d_in[8];
    const float* w1     = (const float*)d_in[9];
    const float* w2     = (const float*)d_in[10];
    const float* w3     = (const float*)d_in[11];
    const float* ln2g   = (const float*)d_in[12];
    const float* ln2b   = (const float*)d_in[13];
    const float* fing   = (const float*)d_in[14];
    const float* finb   = (const float*)d_in[15];
    const float* headw  = (const float*)d_in[16];
    float* out = (float*)d_out;

    float *x, *q, *k, *v, *att, *x1, *x2, *x3, *x4, *x5, *moe, *t1, *t2, *wgt;
    int *cnt, *lst;
    cudaGetSymbolAddress((void**)&x,   g_x);
    cudaGetSymbolAddress((void**)&q,   g_q);
    cudaGetSymbolAddress((void**)&k,   g_k);
    cudaGetSymbolAddress((void**)&v,   g_v);
    cudaGetSymbolAddress((void**)&att, g_att);
    cudaGetSymbolAddress((void**)&x1,  g_x1);
    cudaGetSymbolAddress((void**)&x2,  g_x2);
    cudaGetSymbolAddress((void**)&x3,  g_x3);
    cudaGetSymbolAddress((void**)&x4,  g_x4);
    cudaGetSymbolAddress((void**)&x5,  g_x5);
    cudaGetSymbolAddress((void**)&moe, g_moe);
    cudaGetSymbolAddress((void**)&t1,  g_t1);
    cudaGetSymbolAddress((void**)&t2,  g_t2);
    cudaGetSymbolAddress((void**)&wgt, g_wgt);
    cudaGetSymbolAddress((void**)&cnt, g_cnt);
    cudaGetSymbolAddress((void**)&lst, g_list);

    cudaFuncSetAttribute(attn_kernel, cudaFuncAttributeMaxDynamicSharedMemorySize, ATTN_SMEM);

    // 0. init + rope tables
    zero_kernel<<<(S*D + 255)/256, 256>>>(moe);
    rope_table_kernel<<<(S*32 + 255)/256, 256>>>();
    // 1. embedding
    embed_kernel<<<S, 256>>>(tokens, emb, x);
    // 2. QKV projections (fp32, batched over z)
    qkv_gemm<<<dim3(D/BN, S/BM, 3), 256>>>(x, wq, wk, wv, q, k, v);
    // 3. RoPE
    rope_kernel<<<(S*NH*(HD/2))/256, 256>>>(q, k);
    // 4. attention
    attn_kernel<<<dim3(NH, NB), 256, ATTN_SMEM>>>(q, k, v, att);
    // 5. output projection + residual (fp32)
    wo_gemm<<<dim3(D/BN, S/BM, 1), 256>>>(att, wo, x1, x);
    // 6. layernorm 1
    ln_kernel<<<S, 256>>>(x1, ln1g, ln1b, x2);
    // 7. gating + routing + per-token variance
    gate_kernel<<<S, 128>>>(x2, gatew);
    aux_kernel<<<1, 256>>>(out, out_size);
    // 8. MoE expert GEMMs — tf32 tensor cores
    tgemm_k<0,true,true><<<dim3(FF/TBN, S/TBM, NE), 256, TSMEM>>>(x2, w1, t1, S, FF, D, cnt, lst, nullptr,
                                                                  0, (long)FF*D, (long)S*FF);
    tgemm_k<0,true,true><<<dim3(FF/TBN, S/TBM, NE), 256, TSMEM>>>(x2, w3, t2, S, FF, D, cnt, lst, nullptr,
                                                                  0, (long)FF*D, (long)S*FF);
    silu_kernel<<<NE*S, 256>>>();
    tgemm_k<2,false,true><<<dim3(D/TBN, S/TBM, NE), 256, TSMEM>>>(t1, w2, moe, S, D, FF, cnt, lst, wgt,
                                                                  (long)S*FF, (long)D*FF, 0);
    // 9. residual + layernorm 2 + final layernorm
    add_kernel<<<(S*D + 255)/256, 256>>>(moe, x2, x3);
    ln_kernel<<<S, 256>>>(x3, ln2g, ln2b, x4);
    ln_kernel<<<S, 256>>>(x4, fing, finb, x5);
    // 10. LM head — tf32 tensor cores
    tgemm_k<0,false,false><<<dim3((NV + TBN - 1)/TBN, S/TBM, 1), 256, TSMEM>>>(x5, headw, out, S, NV, D,
                                                                               nullptr, nullptr, nullptr, 0, 0, 0);
}

// round 7
// speedup vs baseline: 2.5114x; 1.0039x over previous
#include <cuda_runtime.h>
#include <math.h>
#include <stdint.h>

#define S    1024
#define D    2048
#define NH   32
#define HD   64
#define FF   8192
#define NE   4
#define NV   50257
#define BLKQ 64
#define NB   16   // S / BLKQ

// ---------------- scratch (static device globals; no runtime alloc) ----------------
__device__ float g_x  [S*D];
__device__ float g_q  [S*D];
__device__ float g_k  [S*D];
__device__ float g_v  [S*D];
__device__ float g_att[S*D];
__device__ float g_x1 [S*D];
__device__ float g_x2 [S*D];
__device__ float g_x3 [S*D];
__device__ float g_x4 [S*D];
__device__ float g_x5 [S*D];
__device__ float g_moe[S*D];
__device__ float g_t1 [(long)NE*S*FF];
__device__ float g_t2 [(long)NE*S*FF];
__device__ int   g_cnt[NE];
__device__ int   g_list[NE*S];
__device__ float g_wgt[NE*S];
__device__ float g_var[S];
__device__ float g_cos[S*32];
__device__ float g_sin[S*32];

// ---------------- packed f32x2 helpers ----------------
__device__ __forceinline__ uint64_t pack2(float x) {
    uint64_t r;
    uint32_t u = __float_as_uint(x);
    asm("mov.b64 %0, {%1, %1};" : "=l"(r) : "r"(u));
    return r;
}
__device__ __forceinline__ void fma2(uint64_t& d, uint64_t a, uint64_t b) {
    asm("fma.rn.f32x2 %0, %1, %2, %0;" : "+l"(d) : "l"(a), "l"(b));
}
__device__ __forceinline__ void unpack2(uint64_t v, float& lo, float& hi) {
    uint32_t a, b;
    asm("mov.b64 {%0, %1}, %2;" : "=r"(a), "=r"(b) : "l"(v));
    lo = __uint_as_float(a); hi = __uint_as_float(b);
}

// ---------------- init ----------------
__global__ void zero_kernel(float* moe) {
    long i = (long)blockIdx.x * blockDim.x + threadIdx.x;
    if (i < (long)S*D) moe[i] = 0.f;
    if (i < NE) g_cnt[i] = 0;
}

// ---------------- embedding gather ----------------
__global__ void embed_kernel(const int* __restrict__ tok, const float* __restrict__ emb,
                             float* __restrict__ x) {
    int t = blockIdx.x;
    long r = (long)tok[t] * D;
    for (int d = threadIdx.x; d < D; d += blockDim.x)
        x[(long)t*D + d] = emb[r + d];
}

// ---------------- RoPE tables ----------------
__global__ void rope_table_kernel() {
    int idx = blockIdx.x * blockDim.x + threadIdx.x;
    if (idx >= S*32) return;
    int j = idx & 31;
    int s = idx >> 5;
    double inv = pow(10000.0, -(double)(2*j) / (double)HD);
    double ang = (double)s * inv;
    g_cos[idx] = (float)cos(ang);
    g_sin[idx] = (float)sin(ang);
}

__global__ void rope_kernel(float* __restrict__ q, float* __restrict__ k) {
    int idx = blockIdx.x * blockDim.x + threadIdx.x;
    if (idx >= S*NH*(HD/2)) return;
    int j = idx & 31;
    int h = (idx >> 5) & 31;
    int s = idx >> 10;
    float c  = g_cos[s*32 + j];
    float sn = g_sin[s*32 + j];
    long base = (long)s*D + h*HD + 2*j;
    float q0 = q[base], q1 = q[base+1];
    q[base]   = q0*c - q1*sn;
    q[base+1] = q0*sn + q1*c;
    float k0 = k[base], k1 = k[base+1];
    k[base]   = k0*c - k1*sn;
    k[base+1] = k0*sn + k1*c;
}

// ---------------- attention (per-block-max softmax; f32x2 packed, bit-exact) ---------
// Ks2[d][l] = (K[l][d], K[l+32][d]);  Vs2[kk][l] = (V[kk][l], V[kk][l+32])
#define ATTN_SMEM ((64*64 + 64*64 + 64*64 + 8*64) * 4)
__global__ void attn_kernel(const float* __restrict__ q, const float* __restrict__ k,
                            const float* __restrict__ v, float* __restrict__ o) {
    int h  = blockIdx.x;
    int ib = blockIdx.y;
    extern __shared__ float sm[];
    float* Qs  = sm;            // [64][64]
    float* Ks2 = sm + 4096;     // pair layout, 4096 floats
    float* Vs2 = sm + 8192;     // pair layout, 4096 floats
    float* Ps  = sm + 12288;    // [8][64]
    int tid = threadIdx.x;
    int w = tid >> 5, l = tid & 31;

    for (int idx = tid; idx < 64*64; idx += 256) {
        int r = idx >> 6, c = idx & 63;
        Qs[r*64 + c] = q[((long)(ib*BLKQ + r))*D + h*HD + c];
    }
    uint64_t num2[8];
    float den[8];
    #pragma unroll
    for (int r = 0; r < 8; r++) { num2[r] = 0ull; den[r] = 0.f; }

    for (int jb = 0; jb <= ib; jb++) {
        __syncthreads();
        for (int idx = tid; idx < 64*64; idx += 256) {
            int r = idx >> 6, c = idx & 63;
            float kv = k[((long)(jb*BLKQ + r))*D + h*HD + c];
            float vv = v[((long)(jb*BLKQ + r))*D + h*HD + c];
            Ks2[c*64 + (r & 31)*2 + (r >> 5)] = kv;
            Vs2[r*64 + (c & 31)*2 + (c >> 5)] = vv;
        }
        __syncthreads();
        for (int r = 0; r < 8; r++) {
            int qr = w*8 + r;
            uint64_t s2 = 0ull;
            #pragma unroll 8
            for (int d = 0; d < HD; d++) {
                uint64_t q2 = pack2(Qs[qr*64 + d]);
                uint64_t kp = *(const uint64_t*)&Ks2[d*64 + l*2];
                fma2(s2, q2, kp);
            }
            float s0, s1;
            unpack2(s2, s0, s1);
            s0 *= 0.125f; s1 *= 0.125f;
            if (jb == ib) {
                if (l      > qr) s0 = -INFINITY;
                if (l + 32 > qr) s1 = -INFINITY;
            }
            float m = fmaxf(s0, s1);
            #pragma unroll
            for (int off = 16; off; off >>= 1)
                m = fmaxf(m, __shfl_xor_sync(0xffffffffu, m, off));
            float p0 = expf(s0 - m), p1 = expf(s1 - m);
            float ds = p0 + p1;
            #pragma unroll
            for (int off = 16; off; off >>= 1)
                ds += __shfl_xor_sync(0xffffffffu, ds, off);
            den[r] += ds;
            Ps[w*64 + l] = p0; Ps[w*64 + l + 32] = p1;
            __syncwarp();
            #pragma unroll 8
            for (int kk = 0; kk < 64; kk++) {
                uint64_t pk2 = pack2(Ps[w*64 + kk]);
                uint64_t vp  = *(const uint64_t*)&Vs2[kk*64 + l*2];
                fma2(num2[r], pk2, vp);
            }
            __syncwarp();
        }
    }
    for (int r = 0; r < 8; r++) {
        int qr = w*8 + r;
        float dinv = 1.0f / (den[r] + 1e-6f);
        float n0, n1;
        unpack2(num2[r], n0, n1);
        long base = ((long)(ib*BLKQ + qr))*D + h*HD;
        o[base + l]      = n0 * dinv;
        o[base + l + 32] = n1 * dinv;
    }
}

// ---------------- layernorm ----------------
__global__ void ln_kernel(const float* __restrict__ x, const float* __restrict__ g,
                          const float* __restrict__ b, float* __restrict__ y) {
    int t = blockIdx.x;
    __shared__ float red[256];
    const float* row = x + (long)t*D;
    float s = 0.f;
    for (int d = threadIdx.x; d < D; d += 256) s += row[d];
    red[threadIdx.x] = s; __syncthreads();
    for (int o = 128; o; o >>= 1) { if (threadIdx.x < o) red[threadIdx.x] += red[threadIdx.x+o]; __syncthreads(); }
    float mu = red[0] / (float)D;
    __syncthreads();
    float vs = 0.f;
    for (int d = threadIdx.x; d < D; d += 256) { float dd = row[d]-mu; vs = fmaf(dd, dd, vs); }
    red[threadIdx.x] = vs; __syncthreads();
    for (int o = 128; o; o >>= 1) { if (threadIdx.x < o) red[threadIdx.x] += red[threadIdx.x+o]; __syncthreads(); }
    float inv = 1.0f / sqrtf(red[0]/(float)D + 1e-5f);
    for (int d = threadIdx.x; d < D; d += 256)
        y[(long)t*D + d] = (row[d]-mu)*inv*g[d] + b[d];
}

// ---------------- gate ----------------
__global__ void gate_kernel(const float* __restrict__ x, const float* __restrict__ gw) {
    int t = blockIdx.x;
    int tid = threadIdx.x;  // 128
    __shared__ float red[4][128];
    const float* row = x + (long)t*D;
    float p[4] = {0.f,0.f,0.f,0.f};
    for (int d = tid; d < D; d += 128) {
        float xv = row[d];
        #pragma unroll
        for (int e = 0; e < 4; e++) p[e] = fmaf(xv, gw[e*D + d], p[e]);
    }
    #pragma unroll
    for (int e = 0; e < 4; e++) red[e][tid] = p[e];
    __syncthreads();
    for (int o = 64; o; o >>= 1) {
        if (tid < o) {
            red[0][tid] += red[0][tid+o];
            red[1][tid] += red[1][tid+o];
            red[2][tid] += red[2][tid+o];
            red[3][tid] += red[3][tid+o];
        }
        __syncthreads();
    }
    if (tid == 0) {
        float l[4];
        #pragma unroll
        for (int e = 0; e < 4; e++) l[e] = red[e][0];
        float mu = (l[0]+l[1]+l[2]+l[3]) * 0.25f;
        float var = 0.f;
        #pragma unroll
        for (int e = 0; e < 4; e++) { float d0 = l[e]-mu; var = fmaf(d0, d0, var); }
        g_var[t] = var / 3.0f;
        int i1 = 0;
        for (int e = 1; e < 4; e++) if (l[e] > l[i1]) i1 = e;
        int i2 = (i1 == 0) ? 1 : 0;
        for (int e = 0; e < 4; e++) if (e != i1 && l[e] > l[i2]) i2 = e;
        float m = fmaxf(fmaxf(l[0],l[1]), fmaxf(l[2],l[3]));
        float e1 = expf(l[i1]-m), e2 = expf(l[i2]-m);
        float w1 = e1/(e1+e2), w2 = e2/(e1+e2);
        int pos1 = atomicAdd(&g_cnt[i1], 1);
        g_list[i1*S + pos1] = t; g_wgt[i1*S + pos1] = w1;
        int pos2 = atomicAdd(&g_cnt[i2], 1);
        g_list[i2*S + pos2] = t; g_wgt[i2*S + pos2] = w2;
    }
}

// ---------------- aux ----------------
__global__ void aux_kernel(float* __restrict__ out, int out_size) {
    __shared__ float red[256];
    float s = 0.f;
    for (int i = threadIdx.x; i < S; i += 256) s += g_var[i];
    red[threadIdx.x] = s; __syncthreads();
    for (int o = 128; o; o >>= 1) { if (threadIdx.x < o) red[threadIdx.x] += red[threadIdx.x+o]; __syncthreads(); }
    if (threadIdx.x == 0) {
        long pos = (long)S * NV;
        if ((long)out_size > pos) out[pos] = red[0] / (float)S;
    }
}

// ---------------- silu-gate on valid routed rows only ----------------
__global__ void silu_kernel() {
    int row = blockIdx.x;
    int e = row >> 10;
    int slot = row & (S-1);
    if (slot >= g_cnt[e]) return;
    long base = (long)row * FF;
    for (int i = threadIdx.x; i < FF; i += 256) {
        float a = g_t1[base + i], b = g_t2[base + i];
        g_t1[base + i] = b * (a / (1.0f + expf(-a)));
    }
}

// ---------------- elementwise add ----------------
__global__ void add_kernel(const float* __restrict__ a, const float* __restrict__ b,
                           float* __restrict__ c) {
    long i = (long)blockIdx.x * 256 + threadIdx.x;
    if (i < (long)S*D) c[i] = a[i] + b[i];
}

// ================= fp32 SGEMM via packed f32x2 (exact routing path: QKV / WO) ========
constexpr int BM = 128, BN = 128, BKs = 8;

template<int EPI>
__device__ __forceinline__ void sgemm_body(
    const float* __restrict__ A, const float* __restrict__ Bm, float* __restrict__ Cm,
    int M, int N, int K, int m0, int n0, const float* __restrict__ resid)
{
    __shared__ float As[BKs][BM];
    __shared__ float Bs[BKs][BN];
    int tid = threadIdx.x;
    int tx = tid & 15, ty = tid >> 4;

    uint64_t acc2[8][4];
    #pragma unroll
    for (int i = 0; i < 8; i++)
        #pragma unroll
        for (int j = 0; j < 4; j++) acc2[i][j] = 0ull;

    int am = tid >> 1, aseg = (tid & 1) * 4;
    int arow = m0 + am;
    bool avld = arow < M;
    const float* Ap = avld ? (A + (long)arow * K + aseg) : nullptr;
    int bn = tid >> 1, bseg = (tid & 1) * 4;
    int brow = n0 + bn;
    bool bvld = brow < N;
    const float* Bp = bvld ? (Bm + (long)brow * K + bseg) : nullptr;

    for (int k0 = 0; k0 < K; k0 += BKs) {
        float4 a4 = avld ? *(const float4*)(Ap + k0) : make_float4(0.f,0.f,0.f,0.f);
        float4 b4 = bvld ? *(const float4*)(Bp + k0) : make_float4(0.f,0.f,0.f,0.f);
        __syncthreads();
        As[aseg+0][am] = a4.x; As[aseg+1][am] = a4.y; As[aseg+2][am] = a4.z; As[aseg+3][am] = a4.w;
        Bs[bseg+0][bn] = b4.x; Bs[bseg+1][bn] = b4.y; Bs[bseg+2][bn] = b4.z; Bs[bseg+3][bn] = b4.w;
        __syncthreads();
        #pragma unroll
        for (int kk = 0; kk < BKs; kk++) {
            float a[8];
            #pragma unroll
            for (int i = 0; i < 8; i++) a[i] = As[kk][ty*8 + i];
            const uint64_t* b2p = (const uint64_t*)&Bs[kk][tx*8];
            uint64_t b2[4];
            #pragma unroll
            for (int j = 0; j < 4; j++) b2[j] = b2p[j];
            #pragma unroll
            for (int i = 0; i < 8; i++) {
                uint64_t a2 = pack2(a[i]);
                #pragma unroll
                for (int j = 0; j < 4; j++) fma2(acc2[i][j], a2, b2[j]);
            }
        }
    }
    #pragma unroll
    for (int i = 0; i < 8; i++) {
        int m = m0 + ty*8 + i;
        if (m >= M) continue;
        #pragma unroll
        for (int j = 0; j < 4; j++) {
            float c0, c1;
            unpack2(acc2[i][j], c0, c1);
            int n = n0 + tx*8 + 2*j;
            if (n < N) {
                if constexpr (EPI == 0) Cm[(long)m*N + n] = c0;
                else                    Cm[(long)m*N + n] = c0 + resid[(long)m*N + n];
            }
            if (n + 1 < N) {
                if constexpr (EPI == 0) Cm[(long)m*N + n + 1] = c1;
                else                    Cm[(long)m*N + n + 1] = c1 + resid[(long)m*N + n + 1];
            }
        }
    }
}

__global__ void __launch_bounds__(256)
wo_gemm(const float* __restrict__ A, const float* __restrict__ Bm, float* __restrict__ Cm,
        const float* __restrict__ resid) {
    sgemm_body<1>(A, Bm, Cm, S, D, D, blockIdx.y * BM, blockIdx.x * BN, resid);
}

__global__ void __launch_bounds__(256)
qkv_gemm(const float* __restrict__ x,
         const float* __restrict__ wq, const float* __restrict__ wk, const float* __restrict__ wv,
         float* __restrict__ q, float* __restrict__ k, float* __restrict__ v) {
    const float* Bm = (blockIdx.z == 0) ? wq : (blockIdx.z == 1) ? wk : wv;
    float*       Cm = (blockIdx.z == 0) ? q  : (blockIdx.z == 1) ? k  : v;
    sgemm_body<0>(x, Bm, Cm, S, D, D, blockIdx.y * BM, blockIdx.x * BN, nullptr);
}

// ================= tf32 tensor-core GEMM: C[M,N] = A[M,K] @ B[N,K]^T =================
// 128x128x16 tiles, 256 thr = 8 warps (2 M x 4 N), warp tile 64x32 via mma.m16n8k8.
// Smem [row][k] pad 20: conflict-free fragment loads; 40KB/CTA => 2 CTAs/SM.
constexpr int TBM = 128, TBN = 128, TBK = 16;
constexpr int APAD = 20;
constexpr size_t TSMEM = (size_t)2 * TBM * APAD * sizeof(float) * 2;   // 40960 B

__device__ __forceinline__ float f2tf32(float x) {
    uint32_t u;
    asm("cvt.rna.tf32.f32 %0, %1;" : "=r"(u) : "f"(x));
    return __uint_as_float(u);
}

template<int EPI, bool GA, bool GCNT>
__global__ void __launch_bounds__(256, 2)
tgemm_k(const float* __restrict__ A, const float* __restrict__ Bm, float* __restrict__ Cm,
        int M, int N, int K,
        const int* __restrict__ cnt, const int* __restrict__ rowidx,
        const float* __restrict__ roww,
        long sAz, long sBz, long sCz)
{
    extern __shared__ float sh[];
    int z = blockIdx.z;
    A  += (long)z * sAz;
    Bm += (long)z * sBz;
    Cm += (long)z * sCz;
    const int*   ridx = rowidx ? rowidx + z*S : nullptr;
    const float* rw   = roww   ? roww   + z*S : nullptr;
    int Meff = GCNT ? cnt[z] : M;
    int m0 = blockIdx.y * TBM, n0 = blockIdx.x * TBN;
    if (m0 >= Meff) return;

    float (*As)[TBM][APAD] = (float (*)[TBM][APAD])sh;
    float (*Bs)[TBN][APAD] = (float (*)[TBN][APAD])(sh + 2*TBM*APAD);

    int tid = threadIdx.x, lane = tid & 31, wid = tid >> 5;
    int wm = (wid & 1) * 64;
    int wn = (wid >> 1) * 32;
    int lr = lane >> 2;          // 0..7
    int lc = lane & 3;           // 0..3

    float acc[4][4][4];
    #pragma unroll
    for (int mt = 0; mt < 4; mt++)
        #pragma unroll
        for (int nt = 0; nt < 4; nt++)
            #pragma unroll
            for (int r = 0; r < 4; r++) acc[mt][nt][r] = 0.f;

    int kq = (tid & 3) * 4;
    int r0l = tid >> 2;          // 0..63
    const float* Ap[2];
    const float* Bp[2];
    #pragma unroll
    for (int i = 0; i < 2; i++) {
        int ar = r0l + 64*i;
        int arow = m0 + ar;
        bool av = arow < Meff;
        long grow = av ? (GA ? (long)ridx[arow] : (long)arow) : 0;
        Ap[i] = av ? (A + grow*(long)K + kq) : nullptr;
        int brow = n0 + ar;
        Bp[i] = (brow < N) ? (Bm + (long)brow*K + kq) : nullptr;
    }

    float4 sa[2], sb[2];
    auto gload = [&](int kt) {
        #pragma unroll
        for (int i = 0; i < 2; i++) {
            sa[i] = Ap[i] ? *(const float4*)(Ap[i] + (long)kt*TBK) : make_float4(0.f,0.f,0.f,0.f);
            sb[i] = Bp[i] ? *(const float4*)(Bp[i] + (long)kt*TBK) : make_float4(0.f,0.f,0.f,0.f);
        }
    };
    auto sstore = [&](int buf) {
        #pragma unroll
        for (int i = 0; i < 2; i++) {
            int ar = r0l + 64*i;
            float4 ta = make_float4(f2tf32(sa[i].x), f2tf32(sa[i].y), f2tf32(sa[i].z), f2tf32(sa[i].w));
            float4 tb = make_float4(f2tf32(sb[i].x), f2tf32(sb[i].y), f2tf32(sb[i].z), f2tf32(sb[i].w));
            *(float4*)&As[buf][ar][kq] = ta;
            *(float4*)&Bs[buf][ar][kq] = tb;
        }
    };

    int ktiles = K / TBK;
    gload(0);
    sstore(0);
    __syncthreads();

    for (int t = 0; t < ktiles; t++) {
        int buf = t & 1;
        bool more = (t + 1) < ktiles;
        if (more) gload(t + 1);

        #pragma unroll
        for (int ks = 0; ks < 2; ks++) {
            int kb = ks * 8;
            uint32_t af[4][4], bf[4][2];
            #pragma unroll
            for (int mt = 0; mt < 4; mt++) {
                int r = wm + mt*16 + lr;
                af[mt][0] = __float_as_uint(As[buf][r    ][kb + lc    ]);
                af[mt][1] = __float_as_uint(As[buf][r + 8][kb + lc    ]);
                af[mt][2] = __float_as_uint(As[buf][r    ][kb + lc + 4]);
                af[mt][3] = __float_as_uint(As[buf][r + 8][kb + lc + 4]);
            }
            #pragma unroll
            for (int nt = 0; nt < 4; nt++) {
                int c = wn + nt*8 + lr;
                bf[nt][0] = __float_as_uint(Bs[buf][c][kb + lc    ]);
                bf[nt][1] = __float_as_uint(Bs[buf][c][kb + lc + 4]);
            }
            #pragma unroll
            for (int mt = 0; mt < 4; mt++)
                #pragma unroll
                for (int nt = 0; nt < 4; nt++) {
                    asm volatile(
                        "mma.sync.aligned.m16n8k8.row.col.f32.tf32.tf32.f32 "
                        "{%0,%1,%2,%3}, {%4,%5,%6,%7}, {%8,%9}, {%0,%1,%2,%3};"
                        : "+f"(acc[mt][nt][0]), "+f"(acc[mt][nt][1]),
                          "+f"(acc[mt][nt][2]), "+f"(acc[mt][nt][3])
                        : "r"(af[mt][0]), "r"(af[mt][1]), "r"(af[mt][2]), "r"(af[mt][3]),
                          "r"(bf[nt][0]), "r"(bf[nt][1]));
                }
        }

        if (more) {
            sstore(buf ^ 1);
            __syncthreads();
        }
    }

    // ---------------- epilogue ----------------
    #pragma unroll
    for (int mt = 0; mt < 4; mt++) {
        int r0 = m0 + wm + mt*16 + lr;
        int r1 = r0 + 8;
        #pragma unroll
        for (int nt = 0; nt < 4; nt++) {
            int c0 = n0 + wn + nt*8 + (lc << 1);
            int c1 = c0 + 1;
            if constexpr (EPI == 0) {
                if (r0 < Meff) {
                    if (c0 < N) Cm[(long)r0*N + c0] = acc[mt][nt][0];
                    if (c1 < N) Cm[(long)r0*N + c1] = acc[mt][nt][1];
                }
                if (r1 < Meff) {
                    if (c0 < N) Cm[(long)r1*N + c0] = acc[mt][nt][2];
                    if (c1 < N) Cm[(long)r1*N + c1] = acc[mt][nt][3];
                }
            } else {
                if (r0 < Meff) {
                    long orow = (long)ridx[r0] * N;
                    float w = rw[r0];
                    if (c0 < N) atomicAdd(&Cm[orow + c0], acc[mt][nt][0] * w);
                    if (c1 < N) atomicAdd(&Cm[orow + c1], acc[mt][nt][1] * w);
                }
                if (r1 < Meff) {
                    long orow = (long)ridx[r1] * N;
                    float w = rw[r1];
                    if (c0 < N) atomicAdd(&Cm[orow + c0], acc[mt][nt][2] * w);
                    if (c1 < N) atomicAdd(&Cm[orow + c1], acc[mt][nt][3] * w);
                }
            }
        }
    }
}

// ---------------- launcher ----------------
extern "C" void kernel_launch(void* const* d_in, const int* in_sizes, int n_in,
                              void* d_out, int out_size) {
    const int*   tokens = (const int*)  d_in[0];
    const float* emb    = (const float*)d_in[1];
    const float* wq     = (const float*)d_in[2];
    const float* wk     = (const float*)d_in[3];
    const float* wv     = (const float*)d_in[4];
    const float* wo     = (const float*)d_in[5];
    const float* ln1g   = (const float*)d_in[6];
    const float* ln1b   = (const float*)d_in[7];
    const float* gatew  = (const float*)d_in[8];
    const float* w1     = (const float*)d_in[9];
    const float* w2     = (const float*)d_in[10];
    const float* w3     = (const float*)d_in[11];
    const float* ln2g   = (const float*)d_in[12];
    const float* ln2b   = (const float*)d_in[13];
    const float* fing   = (const float*)d_in[14];
    const float* finb   = (const float*)d_in[15];
    const float* headw  = (const float*)d_in[16];
    float* out = (float*)d_out;

    float *x, *q, *k, *v, *att, *x1, *x2, *x3, *x4, *x5, *moe, *t1, *t2, *wgt;
    int *cnt, *lst;
    cudaGetSymbolAddress((void**)&x,   g_x);
    cudaGetSymbolAddress((void**)&q,   g_q);
    cudaGetSymbolAddress((void**)&k,   g_k);
    cudaGetSymbolAddress((void**)&v,   g_v);
    cudaGetSymbolAddress((void**)&att, g_att);
    cudaGetSymbolAddress((void**)&x1,  g_x1);
    cudaGetSymbolAddress((void**)&x2,  g_x2);
    cudaGetSymbolAddress((void**)&x3,  g_x3);
    cudaGetSymbolAddress((void**)&x4,  g_x4);
    cudaGetSymbolAddress((void**)&x5,  g_x5);
    cudaGetSymbolAddress((void**)&moe, g_moe);
    cudaGetSymbolAddress((void**)&t1,  g_t1);
    cudaGetSymbolAddress((void**)&t2,  g_t2);
    cudaGetSymbolAddress((void**)&wgt, g_wgt);
    cudaGetSymbolAddress((void**)&cnt, g_cnt);
    cudaGetSymbolAddress((void**)&lst, g_list);

    cudaFuncSetAttribute(attn_kernel, cudaFuncAttributeMaxDynamicSharedMemorySize, ATTN_SMEM);

    // 0. init + rope tables
    zero_kernel<<<(S*D + 255)/256, 256>>>(moe);
    rope_table_kernel<<<(S*32 + 255)/256, 256>>>();
    // 1. embedding
    embed_kernel<<<S, 256>>>(tokens, emb, x);
    // 2. QKV projections (fp32 f32x2, batched over z — routing bit-exact)
    qkv_gemm<<<dim3(D/BN, S/BM, 3), 256>>>(x, wq, wk, wv, q, k, v);
    // 3. RoPE
    rope_kernel<<<(S*NH*(HD/2))/256, 256>>>(q, k);
    // 4. attention
    attn_kernel<<<dim3(NH, NB), 256, ATTN_SMEM>>>(q, k, v, att);
    // 5. output projection + residual (fp32 f32x2)
    wo_gemm<<<dim3(D/BN, S/BM, 1), 256>>>(att, wo, x1, x);
    // 6. layernorm 1
    ln_kernel<<<S, 256>>>(x1, ln1g, ln1b, x2);
    // 7. gating + routing + per-token variance
    gate_kernel<<<S, 128>>>(x2, gatew);
    aux_kernel<<<1, 256>>>(out, out_size);
    // 8. MoE expert GEMMs — tf32 tensor cores
    tgemm_k<0,true,true><<<dim3(FF/TBN, S/TBM, NE), 256, TSMEM>>>(x2, w1, t1, S, FF, D, cnt, lst, nullptr,
                                                                  0, (long)FF*D, (long)S*FF);
    tgemm_k<0,true,true><<<dim3(FF/TBN, S/TBM, NE), 256, TSMEM>>>(x2, w3, t2, S, FF, D, cnt, lst, nullptr,
                                                                  0, (long)FF*D, (long)S*FF);
    silu_kernel<<<NE*S, 256>>>();
    tgemm_k<2,false,true><<<dim3(D/TBN, S/TBM, NE), 256, TSMEM>>>(t1, w2, moe, S, D, FF, cnt, lst, wgt,
                                                                  (long)S*FF, (long)D*FF, 0);
    // 9. residual + layernorm 2 + final layernorm
    add_kernel<<<(S*D + 255)/256, 256>>>(moe, x2, x3);
    ln_kernel<<<S, 256>>>(x3, ln2g, ln2b, x4);
    ln_kernel<<<S, 256>>>(x4, fing, finb, x5);
    // 10. LM head — tf32 tensor cores
    tgemm_k<0,false,false><<<dim3((NV + TBN - 1)/TBN, S/TBM, 1), 256, TSMEM>>>(x5, headw, out, S, NV, D,
                                                                               nullptr, nullptr, nullptr, 0, 0, 0);
}

// round 8
// speedup vs baseline: 2.5601x; 1.0194x over previous
#include <cuda_runtime.h>
#include <math.h>
#include <stdint.h>

#define S    1024
#define D    2048
#define NH   32
#define HD   64
#define FF   8192
#define NE   4
#define NV   50257
#define BLKQ 64
#define NB   16   // S / BLKQ

// ---------------- scratch (static device globals; no runtime alloc) ----------------
__device__ float g_x  [S*D];
__device__ float g_q  [S*D];
__device__ float g_k  [S*D];
__device__ float g_v  [S*D];
__device__ float g_att[S*D];
__device__ float g_x1 [S*D];
__device__ float g_x2 [S*D];
__device__ float g_x3 [S*D];
__device__ float g_x4 [S*D];
__device__ float g_x5 [S*D];
__device__ float g_moe[S*D];
__device__ float g_t1 [(long)NE*S*FF];
__device__ float g_t2 [(long)NE*S*FF];
__device__ int   g_cnt[NE];
__device__ int   g_list[NE*S];
__device__ float g_wgt[NE*S];
__device__ float g_var[S];
__device__ float g_cos[S*32];
__device__ float g_sin[S*32];

// ---------------- packed f32x2 helpers ----------------
__device__ __forceinline__ uint64_t pack2(float x) {
    uint64_t r;
    uint32_t u = __float_as_uint(x);
    asm("mov.b64 %0, {%1, %1};" : "=l"(r) : "r"(u));
    return r;
}
__device__ __forceinline__ uint64_t mk2(float lo, float hi) {
    uint64_t r;
    asm("mov.b64 %0, {%1, %2};" : "=l"(r) : "r"(__float_as_uint(lo)), "r"(__float_as_uint(hi)));
    return r;
}
__device__ __forceinline__ void fma2(uint64_t& d, uint64_t a, uint64_t b) {
    asm("fma.rn.f32x2 %0, %1, %2, %0;" : "+l"(d) : "l"(a), "l"(b));
}
__device__ __forceinline__ void unpack2(uint64_t v, float& lo, float& hi) {
    uint32_t a, b;
    asm("mov.b64 {%0, %1}, %2;" : "=r"(a), "=r"(b) : "l"(v));
    lo = __uint_as_float(a); hi = __uint_as_float(b);
}

// ---------------- init ----------------
__global__ void zero_kernel(float* moe) {
    long i = (long)blockIdx.x * blockDim.x + threadIdx.x;
    if (i < (long)S*D) moe[i] = 0.f;
    if (i < NE) g_cnt[i] = 0;
}

// ---------------- embedding gather ----------------
__global__ void embed_kernel(const int* __restrict__ tok, const float* __restrict__ emb,
                             float* __restrict__ x) {
    int t = blockIdx.x;
    long r = (long)tok[t] * D;
    for (int d = threadIdx.x; d < D; d += blockDim.x)
        x[(long)t*D + d] = emb[r + d];
}

// ---------------- RoPE tables ----------------
__global__ void rope_table_kernel() {
    int idx = blockIdx.x * blockDim.x + threadIdx.x;
    if (idx >= S*32) return;
    int j = idx & 31;
    int s = idx >> 5;
    double inv = pow(10000.0, -(double)(2*j) / (double)HD);
    double ang = (double)s * inv;
    g_cos[idx] = (float)cos(ang);
    g_sin[idx] = (float)sin(ang);
}

__global__ void rope_kernel(float* __restrict__ q, float* __restrict__ k) {
    int idx = blockIdx.x * blockDim.x + threadIdx.x;
    if (idx >= S*NH*(HD/2)) return;
    int j = idx & 31;
    int h = (idx >> 5) & 31;
    int s = idx >> 10;
    float c  = g_cos[s*32 + j];
    float sn = g_sin[s*32 + j];
    long base = (long)s*D + h*HD + 2*j;
    float q0 = q[base], q1 = q[base+1];
    q[base]   = q0*c - q1*sn;
    q[base+1] = q0*sn + q1*c;
    float k0 = k[base], k1 = k[base+1];
    k[base]   = k0*c - k1*sn;
    k[base+1] = k0*sn + k1*c;
}

// ---------------- attention (per-block-max softmax; f32x2 packed, bit-exact) ---------
#define ATTN_SMEM ((64*64 + 64*64 + 64*64 + 8*64) * 4)
__global__ void attn_kernel(const float* __restrict__ q, const float* __restrict__ k,
                            const float* __restrict__ v, float* __restrict__ o) {
    int h  = blockIdx.x;
    int ib = blockIdx.y;
    extern __shared__ float sm[];
    float* Qs  = sm;            // [64][64]
    float* Ks2 = sm + 4096;     // pair layout
    float* Vs2 = sm + 8192;     // pair layout
    float* Ps  = sm + 12288;    // [8][64]
    int tid = threadIdx.x;
    int w = tid >> 5, l = tid & 31;

    for (int idx = tid; idx < 64*64; idx += 256) {
        int r = idx >> 6, c = idx & 63;
        Qs[r*64 + c] = q[((long)(ib*BLKQ + r))*D + h*HD + c];
    }
    uint64_t num2[8];
    float den[8];
    #pragma unroll
    for (int r = 0; r < 8; r++) { num2[r] = 0ull; den[r] = 0.f; }

    for (int jb = 0; jb <= ib; jb++) {
        __syncthreads();
        for (int idx = tid; idx < 64*64; idx += 256) {
            int r = idx >> 6, c = idx & 63;
            float kv = k[((long)(jb*BLKQ + r))*D + h*HD + c];
            float vv = v[((long)(jb*BLKQ + r))*D + h*HD + c];
            Ks2[c*64 + (r & 31)*2 + (r >> 5)] = kv;
            Vs2[r*64 + (c & 31)*2 + (c >> 5)] = vv;
        }
        __syncthreads();
        for (int r = 0; r < 8; r++) {
            int qr = w*8 + r;
            uint64_t s2 = 0ull;
            #pragma unroll 8
            for (int d = 0; d < HD; d++) {
                uint64_t q2 = pack2(Qs[qr*64 + d]);
                uint64_t kp = *(const uint64_t*)&Ks2[d*64 + l*2];
                fma2(s2, q2, kp);
            }
            float s0, s1;
            unpack2(s2, s0, s1);
            s0 *= 0.125f; s1 *= 0.125f;
            if (jb == ib) {
                if (l      > qr) s0 = -INFINITY;
                if (l + 32 > qr) s1 = -INFINITY;
            }
            float m = fmaxf(s0, s1);
            #pragma unroll
            for (int off = 16; off; off >>= 1)
                m = fmaxf(m, __shfl_xor_sync(0xffffffffu, m, off));
            float p0 = expf(s0 - m), p1 = expf(s1 - m);
            float ds = p0 + p1;
            #pragma unroll
            for (int off = 16; off; off >>= 1)
                ds += __shfl_xor_sync(0xffffffffu, ds, off);
            den[r] += ds;
            Ps[w*64 + l] = p0; Ps[w*64 + l + 32] = p1;
            __syncwarp();
            #pragma unroll 8
            for (int kk = 0; kk < 64; kk++) {
                uint64_t pk2 = pack2(Ps[w*64 + kk]);
                uint64_t vp  = *(const uint64_t*)&Vs2[kk*64 + l*2];
                fma2(num2[r], pk2, vp);
            }
            __syncwarp();
        }
    }
    for (int r = 0; r < 8; r++) {
        int qr = w*8 + r;
        float dinv = 1.0f / (den[r] + 1e-6f);
        float n0, n1;
        unpack2(num2[r], n0, n1);
        long base = ((long)(ib*BLKQ + qr))*D + h*HD;
        o[base + l]      = n0 * dinv;
        o[base + l + 32] = n1 * dinv;
    }
}

// ---------------- layernorm ----------------
__global__ void ln_kernel(const float* __restrict__ x, const float* __restrict__ g,
                          const float* __restrict__ b, float* __restrict__ y) {
    int t = blockIdx.x;
    __shared__ float red[256];
    const float* row = x + (long)t*D;
    float s = 0.f;
    for (int d = threadIdx.x; d < D; d += 256) s += row[d];
    red[threadIdx.x] = s; __syncthreads();
    for (int o = 128; o; o >>= 1) { if (threadIdx.x < o) red[threadIdx.x] += red[threadIdx.x+o]; __syncthreads(); }
    float mu = red[0] / (float)D;
    __syncthreads();
    float vs = 0.f;
    for (int d = threadIdx.x; d < D; d += 256) { float dd = row[d]-mu; vs = fmaf(dd, dd, vs); }
    red[threadIdx.x] = vs; __syncthreads();
    for (int o = 128; o; o >>= 1) { if (threadIdx.x < o) red[threadIdx.x] += red[threadIdx.x+o]; __syncthreads(); }
    float inv = 1.0f / sqrtf(red[0]/(float)D + 1e-5f);
    for (int d = threadIdx.x; d < D; d += 256)
        y[(long)t*D + d] = (row[d]-mu)*inv*g[d] + b[d];
}

// ---------------- gate ----------------
__global__ void gate_kernel(const float* __restrict__ x, const float* __restrict__ gw) {
    int t = blockIdx.x;
    int tid = threadIdx.x;  // 128
    __shared__ float red[4][128];
    const float* row = x + (long)t*D;
    float p[4] = {0.f,0.f,0.f,0.f};
    for (int d = tid; d < D; d += 128) {
        float xv = row[d];
        #pragma unroll
        for (int e = 0; e < 4; e++) p[e] = fmaf(xv, gw[e*D + d], p[e]);
    }
    #pragma unroll
    for (int e = 0; e < 4; e++) red[e][tid] = p[e];
    __syncthreads();
    for (int o = 64; o; o >>= 1) {
        if (tid < o) {
            red[0][tid] += red[0][tid+o];
            red[1][tid] += red[1][tid+o];
            red[2][tid] += red[2][tid+o];
            red[3][tid] += red[3][tid+o];
        }
        __syncthreads();
    }
    if (tid == 0) {
        float l[4];
        #pragma unroll
        for (int e = 0; e < 4; e++) l[e] = red[e][0];
        float mu = (l[0]+l[1]+l[2]+l[3]) * 0.25f;
        float var = 0.f;
        #pragma unroll
        for (int e = 0; e < 4; e++) { float d0 = l[e]-mu; var = fmaf(d0, d0, var); }
        g_var[t] = var / 3.0f;
        int i1 = 0;
        for (int e = 1; e < 4; e++) if (l[e] > l[i1]) i1 = e;
        int i2 = (i1 == 0) ? 1 : 0;
        for (int e = 0; e < 4; e++) if (e != i1 && l[e] > l[i2]) i2 = e;
        float m = fmaxf(fmaxf(l[0],l[1]), fmaxf(l[2],l[3]));
        float e1 = expf(l[i1]-m), e2 = expf(l[i2]-m);
        float w1 = e1/(e1+e2), w2 = e2/(e1+e2);
        int pos1 = atomicAdd(&g_cnt[i1], 1);
        g_list[i1*S + pos1] = t; g_wgt[i1*S + pos1] = w1;
        int pos2 = atomicAdd(&g_cnt[i2], 1);
        g_list[i2*S + pos2] = t; g_wgt[i2*S + pos2] = w2;
    }
}

// ---------------- aux ----------------
__global__ void aux_kernel(float* __restrict__ out, int out_size) {
    __shared__ float red[256];
    float s = 0.f;
    for (int i = threadIdx.x; i < S; i += 256) s += g_var[i];
    red[threadIdx.x] = s; __syncthreads();
    for (int o = 128; o; o >>= 1) { if (threadIdx.x < o) red[threadIdx.x] += red[threadIdx.x+o]; __syncthreads(); }
    if (threadIdx.x == 0) {
        long pos = (long)S * NV;
        if ((long)out_size > pos) out[pos] = red[0] / (float)S;
    }
}

// ---------------- silu-gate on valid routed rows only ----------------
__global__ void silu_kernel() {
    int row = blockIdx.x;
    int e = row >> 10;
    int slot = row & (S-1);
    if (slot >= g_cnt[e]) return;
    long base = (long)row * FF;
    for (int i = threadIdx.x; i < FF; i += 256) {
        float a = g_t1[base + i], b = g_t2[base + i];
        g_t1[base + i] = b * (a / (1.0f + expf(-a)));
    }
}

// ---------------- elementwise add ----------------
__global__ void add_kernel(const float* __restrict__ a, const float* __restrict__ b,
                           float* __restrict__ c) {
    long i = (long)blockIdx.x * 256 + threadIdx.x;
    if (i < (long)S*D) c[i] = a[i] + b[i];
}

// ================= fp32 SGEMM via packed f32x2, BK=16, LDS.128 fragments =============
constexpr int BM = 128, BN = 128, BKs = 16;

template<int EPI>
__device__ __forceinline__ void sgemm_body(
    const float* __restrict__ A, const float* __restrict__ Bm, float* __restrict__ Cm,
    int M, int N, int K, int m0, int n0, const float* __restrict__ resid)
{
    __shared__ float As[BKs][BM];
    __shared__ float Bs[BKs][BN];
    int tid = threadIdx.x;
    int tx = tid & 15, ty = tid >> 4;

    uint64_t acc2[8][4];
    #pragma unroll
    for (int i = 0; i < 8; i++)
        #pragma unroll
        for (int j = 0; j < 4; j++) acc2[i][j] = 0ull;

    int lrow = tid >> 1;            // 0..127
    int lq   = (tid & 1) * 8;       // k offset 0 or 8
    int arow = m0 + lrow;
    bool avld = arow < M;
    const float* Ap = avld ? (A + (long)arow * K + lq) : nullptr;
    int brow = n0 + lrow;
    bool bvld = brow < N;
    const float* Bp = bvld ? (Bm + (long)brow * K + lq) : nullptr;

    const float4 z4 = make_float4(0.f,0.f,0.f,0.f);
    for (int k0 = 0; k0 < K; k0 += BKs) {
        float4 a0 = avld ? *(const float4*)(Ap + k0)     : z4;
        float4 a1 = avld ? *(const float4*)(Ap + k0 + 4) : z4;
        float4 b0 = bvld ? *(const float4*)(Bp + k0)     : z4;
        float4 b1 = bvld ? *(const float4*)(Bp + k0 + 4) : z4;
        __syncthreads();
        As[lq+0][lrow]=a0.x; As[lq+1][lrow]=a0.y; As[lq+2][lrow]=a0.z; As[lq+3][lrow]=a0.w;
        As[lq+4][lrow]=a1.x; As[lq+5][lrow]=a1.y; As[lq+6][lrow]=a1.z; As[lq+7][lrow]=a1.w;
        Bs[lq+0][lrow]=b0.x; Bs[lq+1][lrow]=b0.y; Bs[lq+2][lrow]=b0.z; Bs[lq+3][lrow]=b0.w;
        Bs[lq+4][lrow]=b1.x; Bs[lq+5][lrow]=b1.y; Bs[lq+6][lrow]=b1.z; Bs[lq+7][lrow]=b1.w;
        __syncthreads();
        #pragma unroll
        for (int kk = 0; kk < BKs; kk++) {
            float4 af0 = *(const float4*)&As[kk][ty*8];
            float4 af1 = *(const float4*)&As[kk][ty*8 + 4];
            float4 bf0 = *(const float4*)&Bs[kk][tx*8];
            float4 bf1 = *(const float4*)&Bs[kk][tx*8 + 4];
            uint64_t b2[4];
            b2[0] = mk2(bf0.x, bf0.y); b2[1] = mk2(bf0.z, bf0.w);
            b2[2] = mk2(bf1.x, bf1.y); b2[3] = mk2(bf1.z, bf1.w);
            float a[8] = {af0.x, af0.y, af0.z, af0.w, af1.x, af1.y, af1.z, af1.w};
            #pragma unroll
            for (int i = 0; i < 8; i++) {
                uint64_t a2 = pack2(a[i]);
                #pragma unroll
                for (int j = 0; j < 4; j++) fma2(acc2[i][j], a2, b2[j]);
            }
        }
    }
    #pragma unroll
    for (int i = 0; i < 8; i++) {
        int m = m0 + ty*8 + i;
        if (m >= M) continue;
        #pragma unroll
        for (int j = 0; j < 4; j++) {
            float c0, c1;
            unpack2(acc2[i][j], c0, c1);
            int n = n0 + tx*8 + 2*j;
            if (n < N) {
                if constexpr (EPI == 0) Cm[(long)m*N + n] = c0;
                else                    Cm[(long)m*N + n] = c0 + resid[(long)m*N + n];
            }
            if (n + 1 < N) {
                if constexpr (EPI == 0) Cm[(long)m*N + n + 1] = c1;
                else                    Cm[(long)m*N + n + 1] = c1 + resid[(long)m*N + n + 1];
            }
        }
    }
}

__global__ void __launch_bounds__(256)
wo_gemm(const float* __restrict__ A, const float* __restrict__ Bm, float* __restrict__ Cm,
        const float* __restrict__ resid) {
    sgemm_body<1>(A, Bm, Cm, S, D, D, blockIdx.y * BM, blockIdx.x * BN, resid);
}

__global__ void __launch_bounds__(256)
qkv_gemm(const float* __restrict__ x,
         const float* __restrict__ wq, const float* __restrict__ wk, const float* __restrict__ wv,
         float* __restrict__ q, float* __restrict__ k, float* __restrict__ v) {
    const float* Bm = (blockIdx.z == 0) ? wq : (blockIdx.z == 1) ? wk : wv;
    float*       Cm = (blockIdx.z == 0) ? q  : (blockIdx.z == 1) ? k  : v;
    sgemm_body<0>(x, Bm, Cm, S, D, D, blockIdx.y * BM, blockIdx.x * BN, nullptr);
}

// ================= tf32 tensor-core GEMM body: C[M,N] = A[M,K] @ B[N,K]^T =============
// 128x128x16 tiles, 256 thr = 8 warps (2 M x 4 N), warp tile 64x32 via mma.m16n8k8.
constexpr int TBM = 128, TBN = 128, TBK = 16;
constexpr int APAD = 20;
constexpr size_t TSMEM = (size_t)2 * TBM * APAD * sizeof(float) * 2;   // 40960 B

__device__ __forceinline__ float f2tf32(float x) {
    uint32_t u;
    asm("cvt.rna.tf32.f32 %0, %1;" : "=r"(u) : "f"(x));
    return __uint_as_float(u);
}

template<int EPI, bool GA>
__device__ __forceinline__ void tgemm_body(
    const float* __restrict__ A, const float* __restrict__ Bm, float* __restrict__ Cm,
    int Meff, int N, int K,
    const int* __restrict__ ridx, const float* __restrict__ rw,
    int m0, int n0)
{
    extern __shared__ float sh[];
    float (*As)[TBM][APAD] = (float (*)[TBM][APAD])sh;
    float (*Bs)[TBN][APAD] = (float (*)[TBN][APAD])(sh + 2*TBM*APAD);

    int tid = threadIdx.x, lane = tid & 31, wid = tid >> 5;
    int wm = (wid & 1) * 64;
    int wn = (wid >> 1) * 32;
    int lr = lane >> 2;          // 0..7
    int lc = lane & 3;           // 0..3

    float acc[4][4][4];
    #pragma unroll
    for (int mt = 0; mt < 4; mt++)
        #pragma unroll
        for (int nt = 0; nt < 4; nt++)
            #pragma unroll
            for (int r = 0; r < 4; r++) acc[mt][nt][r] = 0.f;

    int kq = (tid & 3) * 4;
    int r0l = tid >> 2;          // 0..63
    const float* Ap[2];
    const float* Bp[2];
    #pragma unroll
    for (int i = 0; i < 2; i++) {
        int ar = r0l + 64*i;
        int arow = m0 + ar;
        bool av = arow < Meff;
        long grow = av ? (GA ? (long)ridx[arow] : (long)arow) : 0;
        Ap[i] = av ? (A + grow*(long)K + kq) : nullptr;
        int brow = n0 + ar;
        Bp[i] = (brow < N) ? (Bm + (long)brow*K + kq) : nullptr;
    }

    float4 sa[2], sb[2];
    auto gload = [&](int kt) {
        #pragma unroll
        for (int i = 0; i < 2; i++) {
            sa[i] = Ap[i] ? *(const float4*)(Ap[i] + (long)kt*TBK) : make_float4(0.f,0.f,0.f,0.f);
            sb[i] = Bp[i] ? *(const float4*)(Bp[i] + (long)kt*TBK) : make_float4(0.f,0.f,0.f,0.f);
        }
    };
    auto sstore = [&](int buf) {
        #pragma unroll
        for (int i = 0; i < 2; i++) {
            int ar = r0l + 64*i;
            float4 ta = make_float4(f2tf32(sa[i].x), f2tf32(sa[i].y), f2tf32(sa[i].z), f2tf32(sa[i].w));
            float4 tb = make_float4(f2tf32(sb[i].x), f2tf32(sb[i].y), f2tf32(sb[i].z), f2tf32(sb[i].w));
            *(float4*)&As[buf][ar][kq] = ta;
            *(float4*)&Bs[buf][ar][kq] = tb;
        }
    };

    int ktiles = K / TBK;
    gload(0);
    sstore(0);
    __syncthreads();

    for (int t = 0; t < ktiles; t++) {
        int buf = t & 1;
        bool more = (t + 1) < ktiles;
        if (more) gload(t + 1);

        #pragma unroll
        for (int ks = 0; ks < 2; ks++) {
            int kb = ks * 8;
            uint32_t af[4][4], bf[4][2];
            #pragma unroll
            for (int mt = 0; mt < 4; mt++) {
                int r = wm + mt*16 + lr;
                af[mt][0] = __float_as_uint(As[buf][r    ][kb + lc    ]);
                af[mt][1] = __float_as_uint(As[buf][r + 8][kb + lc    ]);
                af[mt][2] = __float_as_uint(As[buf][r    ][kb + lc + 4]);
                af[mt][3] = __float_as_uint(As[buf][r + 8][kb + lc + 4]);
            }
            #pragma unroll
            for (int nt = 0; nt < 4; nt++) {
                int c = wn + nt*8 + lr;
                bf[nt][0] = __float_as_uint(Bs[buf][c][kb + lc    ]);
                bf[nt][1] = __float_as_uint(Bs[buf][c][kb + lc + 4]);
            }
            #pragma unroll
            for (int mt = 0; mt < 4; mt++)
                #pragma unroll
                for (int nt = 0; nt < 4; nt++) {
                    asm volatile(
                        "mma.sync.aligned.m16n8k8.row.col.f32.tf32.tf32.f32 "
                        "{%0,%1,%2,%3}, {%4,%5,%6,%7}, {%8,%9}, {%0,%1,%2,%3};"
                        : "+f"(acc[mt][nt][0]), "+f"(acc[mt][nt][1]),
                          "+f"(acc[mt][nt][2]), "+f"(acc[mt][nt][3])
                        : "r"(af[mt][0]), "r"(af[mt][1]), "r"(af[mt][2]), "r"(af[mt][3]),
                          "r"(bf[nt][0]), "r"(bf[nt][1]));
                }
        }

        if (more) {
            sstore(buf ^ 1);
            __syncthreads();
        }
    }

    // ---------------- epilogue ----------------
    #pragma unroll
    for (int mt = 0; mt < 4; mt++) {
        int r0 = m0 + wm + mt*16 + lr;
        int r1 = r0 + 8;
        #pragma unroll
        for (int nt = 0; nt < 4; nt++) {
            int c0 = n0 + wn + nt*8 + (lc << 1);
            int c1 = c0 + 1;
            if constexpr (EPI == 0) {
                if (r0 < Meff) {
                    if (c0 < N) Cm[(long)r0*N + c0] = acc[mt][nt][0];
                    if (c1 < N) Cm[(long)r0*N + c1] = acc[mt][nt][1];
                }
                if (r1 < Meff) {
                    if (c0 < N) Cm[(long)r1*N + c0] = acc[mt][nt][2];
                    if (c1 < N) Cm[(long)r1*N + c1] = acc[mt][nt][3];
                }
            } else {
                if (r0 < Meff) {
                    long orow = (long)ridx[r0] * N;
                    float w = rw[r0];
                    if (c0 < N) atomicAdd(&Cm[orow + c0], acc[mt][nt][0] * w);
                    if (c1 < N) atomicAdd(&Cm[orow + c1], acc[mt][nt][1] * w);
                }
                if (r1 < Meff) {
                    long orow = (long)ridx[r1] * N;
                    float w = rw[r1];
                    if (c0 < N) atomicAdd(&Cm[orow + c0], acc[mt][nt][2] * w);
                    if (c1 < N) atomicAdd(&Cm[orow + c1], acc[mt][nt][3] * w);
                }
            }
        }
    }
}

// merged w1 + w3 MoE GEMM: z in [0, 2*NE) -> (expert, which-weight)
__global__ void __launch_bounds__(256, 2)
moe13_gemm(const float* __restrict__ x2,
           const float* __restrict__ w1, const float* __restrict__ w3,
           float* __restrict__ t1, float* __restrict__ t2) {
    int z = blockIdx.z;
    int e = z & (NE-1);
    int sel = z >> 2;
    int Meff = g_cnt[e];
    int m0 = blockIdx.y * TBM;
    if (m0 >= Meff) return;
    const float* Bm = (sel ? w3 : w1) + (long)e * FF * D;
    float*       Cm = (sel ? t2 : t1) + (long)e * S * FF;
    tgemm_body<0, true>(x2, Bm, Cm, Meff, FF, D, g_list + e*S, nullptr,
                        m0, blockIdx.x * TBN);
}

// w2 GEMM with weighted scatter epilogue: z = expert
__global__ void __launch_bounds__(256, 2)
moe2_gemm(const float* __restrict__ t1, const float* __restrict__ w2,
          float* __restrict__ moe) {
    int e = blockIdx.z;
    int Meff = g_cnt[e];
    int m0 = blockIdx.y * TBM;
    if (m0 >= Meff) return;
    tgemm_body<2, false>(t1 + (long)e*S*FF, w2 + (long)e*D*FF, moe,
                         Meff, D, FF, g_list + e*S, g_wgt + e*S,
                         m0, blockIdx.x * TBN);
}

// LM head
__global__ void __launch_bounds__(256, 2)
head_gemm(const float* __restrict__ x5, const float* __restrict__ hw,
          float* __restrict__ out) {
    tgemm_body<0, false>(x5, hw, out, S, NV, D, nullptr, nullptr,
                         blockIdx.y * TBM, blockIdx.x * TBN);
}

// ---------------- launcher ----------------
extern "C" void kernel_launch(void* const* d_in, const int* in_sizes, int n_in,
                              void* d_out, int out_size) {
    const int*   tokens = (const int*)  d_in[0];
    const float* emb    = (const float*)d_in[1];
    const float* wq     = (const float*)d_in[2];
    const float* wk     = (const float*)d_in[3];
    const float* wv     = (const float*)d_in[4];
    const float* wo     = (const float*)d_in[5];
    const float* ln1g   = (const float*)d_in[6];
    const float* ln1b   = (const float*)d_in[7];
    const float* gatew  = (const float*)d_in[8];
    const float* w1     = (const float*)d_in[9];
    const float* w2     = (const float*)d_in[10];
    const float* w3     = (const float*)d_in[11];
    const float* ln2g   = (const float*)d_in[12];
    const float* ln2b   = (const float*)d_in[13];
    const float* fing   = (const float*)d_in[14];
    const float* finb   = (const float*)d_in[15];
    const float* headw  = (const float*)d_in[16];
    float* out = (float*)d_out;

    float *x, *q, *k, *v, *att, *x1, *x2, *x3, *x4, *x5, *moe, *t1, *t2;
    cudaGetSymbolAddress((void**)&x,   g_x);
    cudaGetSymbolAddress((void**)&q,   g_q);
    cudaGetSymbolAddress((void**)&k,   g_k);
    cudaGetSymbolAddress((void**)&v,   g_v);
    cudaGetSymbolAddress((void**)&att, g_att);
    cudaGetSymbolAddress((void**)&x1,  g_x1);
    cudaGetSymbolAddress((void**)&x2,  g_x2);
    cudaGetSymbolAddress((void**)&x3,  g_x3);
    cudaGetSymbolAddress((void**)&x4,  g_x4);
    cudaGetSymbolAddress((void**)&x5,  g_x5);
    cudaGetSymbolAddress((void**)&moe, g_moe);
    cudaGetSymbolAddress((void**)&t1,  g_t1);
    cudaGetSymbolAddress((void**)&t2,  g_t2);

    cudaFuncSetAttribute(attn_kernel, cudaFuncAttributeMaxDynamicSharedMemorySize, ATTN_SMEM);

    // 0. init + rope tables
    zero_kernel<<<(S*D + 255)/256, 256>>>(moe);
    rope_table_kernel<<<(S*32 + 255)/256, 256>>>();
    // 1. embedding
    embed_kernel<<<S, 256>>>(tokens, emb, x);
    // 2. QKV projections (fp32 f32x2 — routing bit-exact)
    qkv_gemm<<<dim3(D/BN, S/BM, 3), 256>>>(x, wq, wk, wv, q, k, v);
    // 3. RoPE
    rope_kernel<<<(S*NH*(HD/2))/256, 256>>>(q, k);
    // 4. attention
    attn_kernel<<<dim3(NH, NB), 256, ATTN_SMEM>>>(q, k, v, att);
    // 5. output projection + residual (fp32 f32x2)
    wo_gemm<<<dim3(D/BN, S/BM, 1), 256>>>(att, wo, x1, x);
    // 6. layernorm 1
    ln_kernel<<<S, 256>>>(x1, ln1g, ln1b, x2);
    // 7. gating + routing + per-token variance
    gate_kernel<<<S, 128>>>(x2, gatew);
    aux_kernel<<<1, 256>>>(out, out_size);
    // 8. MoE expert GEMMs — tf32 tensor cores (w1+w3 merged)
    moe13_gemm<<<dim3(FF/TBN, S/TBM, 2*NE), 256, TSMEM>>>(x2, w1, w3, t1, t2);
    silu_kernel<<<NE*S, 256>>>();
    moe2_gemm<<<dim3(D/TBN, S/TBM, NE), 256, TSMEM>>>(t1, w2, moe);
    // 9. residual + layernorm 2 + final layernorm
    add_kernel<<<(S*D + 255)/256, 256>>>(moe, x2, x3);
    ln_kernel<<<S, 256>>>(x3, ln2g, ln2b, x4);
    ln_kernel<<<S, 256>>>(x4, fing, finb, x5);
    // 10. LM head — tf32 tensor cores
    head_gemm<<<dim3((NV + TBN - 1)/TBN, S/TBM, 1), 256, TSMEM>>>(x5, headw, out);
}

// round 9
// speedup vs baseline: 3.0604x; 1.1954x over previous
#include <cuda_runtime.h>
#include <cuda_fp16.h>
#include <math.h>
#include <stdint.h>

#define S    1024
#define D    2048
#define NH   32
#define HD   64
#define FF   8192
#define NE   4
#define NV   50257
#define BLKQ 64
#define NB   16   // S / BLKQ

// ---------------- scratch (static device globals; no runtime alloc) ----------------
__device__ float g_x  [S*D];
__device__ float g_q  [S*D];
__device__ float g_k  [S*D];
__device__ float g_v  [S*D];
__device__ float g_att[S*D];
__device__ float g_x1 [S*D];
__device__ float g_x2 [S*D];
__device__ float g_x3 [S*D];
__device__ float g_x4 [S*D];
__device__ float g_x5 [S*D];
__device__ float g_moe[S*D];
__device__ float g_t1 [(long)NE*S*FF];
__device__ float g_t2 [(long)NE*S*FF];
__device__ int   g_cnt[NE];
__device__ int   g_list[NE*S];
__device__ float g_wgt[NE*S];
__device__ float g_var[S];
__device__ float g_cos[S*32];
__device__ float g_sin[S*32];

// ---------------- packed f32x2 helpers ----------------
__device__ __forceinline__ uint64_t pack2(float x) {
    uint64_t r;
    uint32_t u = __float_as_uint(x);
    asm("mov.b64 %0, {%1, %1};" : "=l"(r) : "r"(u));
    return r;
}
__device__ __forceinline__ uint64_t mk2(float lo, float hi) {
    uint64_t r;
    asm("mov.b64 %0, {%1, %2};" : "=l"(r) : "r"(__float_as_uint(lo)), "r"(__float_as_uint(hi)));
    return r;
}
__device__ __forceinline__ void fma2(uint64_t& d, uint64_t a, uint64_t b) {
    asm("fma.rn.f32x2 %0, %1, %2, %0;" : "+l"(d) : "l"(a), "l"(b));
}
__device__ __forceinline__ void unpack2(uint64_t v, float& lo, float& hi) {
    uint32_t a, b;
    asm("mov.b64 {%0, %1}, %2;" : "=r"(a), "=r"(b) : "l"(v));
    lo = __uint_as_float(a); hi = __uint_as_float(b);
}

// ---------------- init ----------------
__global__ void zero_kernel(float* moe) {
    long i = (long)blockIdx.x * blockDim.x + threadIdx.x;
    if (i < (long)S*D) moe[i] = 0.f;
    if (i < NE) g_cnt[i] = 0;
}

// ---------------- embedding gather ----------------
__global__ void embed_kernel(const int* __restrict__ tok, const float* __restrict__ emb,
                             float* __restrict__ x) {
    int t = blockIdx.x;
    long r = (long)tok[t] * D;
    for (int d = threadIdx.x; d < D; d += blockDim.x)
        x[(long)t*D + d] = emb[r + d];
}

// ---------------- RoPE tables ----------------
__global__ void rope_table_kernel() {
    int idx = blockIdx.x * blockDim.x + threadIdx.x;
    if (idx >= S*32) return;
    int j = idx & 31;
    int s = idx >> 5;
    double inv = pow(10000.0, -(double)(2*j) / (double)HD);
    double ang = (double)s * inv;
    g_cos[idx] = (float)cos(ang);
    g_sin[idx] = (float)sin(ang);
}

__global__ void rope_kernel(float* __restrict__ q, float* __restrict__ k) {
    int idx = blockIdx.x * blockDim.x + threadIdx.x;
    if (idx >= S*NH*(HD/2)) return;
    int j = idx & 31;
    int h = (idx >> 5) & 31;
    int s = idx >> 10;
    float c  = g_cos[s*32 + j];
    float sn = g_sin[s*32 + j];
    long base = (long)s*D + h*HD + 2*j;
    float q0 = q[base], q1 = q[base+1];
    q[base]   = q0*c - q1*sn;
    q[base+1] = q0*sn + q1*c;
    float k0 = k[base], k1 = k[base+1];
    k[base]   = k0*c - k1*sn;
    k[base+1] = k0*sn + k1*c;
}

// ---------------- attention (per-block-max softmax; f32x2 packed, bit-exact) ---------
#define ATTN_SMEM ((64*64 + 64*64 + 64*64 + 8*64) * 4)
__global__ void attn_kernel(const float* __restrict__ q, const float* __restrict__ k,
                            const float* __restrict__ v, float* __restrict__ o) {
    int h  = blockIdx.x;
    int ib = blockIdx.y;
    extern __shared__ float sm[];
    float* Qs  = sm;            // [64][64]
    float* Ks2 = sm + 4096;     // pair layout
    float* Vs2 = sm + 8192;     // pair layout
    float* Ps  = sm + 12288;    // [8][64]
    int tid = threadIdx.x;
    int w = tid >> 5, l = tid & 31;

    for (int idx = tid; idx < 64*64; idx += 256) {
        int r = idx >> 6, c = idx & 63;
        Qs[r*64 + c] = q[((long)(ib*BLKQ + r))*D + h*HD + c];
    }
    uint64_t num2[8];
    float den[8];
    #pragma unroll
    for (int r = 0; r < 8; r++) { num2[r] = 0ull; den[r] = 0.f; }

    for (int jb = 0; jb <= ib; jb++) {
        __syncthreads();
        for (int idx = tid; idx < 64*64; idx += 256) {
            int r = idx >> 6, c = idx & 63;
            float kv = k[((long)(jb*BLKQ + r))*D + h*HD + c];
            float vv = v[((long)(jb*BLKQ + r))*D + h*HD + c];
            Ks2[c*64 + (r & 31)*2 + (r >> 5)] = kv;
            Vs2[r*64 + (c & 31)*2 + (c >> 5)] = vv;
        }
        __syncthreads();
        for (int r = 0; r < 8; r++) {
            int qr = w*8 + r;
            uint64_t s2 = 0ull;
            #pragma unroll 8
            for (int d = 0; d < HD; d++) {
                uint64_t q2 = pack2(Qs[qr*64 + d]);
                uint64_t kp = *(const uint64_t*)&Ks2[d*64 + l*2];
                fma2(s2, q2, kp);
            }
            float s0, s1;
            unpack2(s2, s0, s1);
            s0 *= 0.125f; s1 *= 0.125f;
            if (jb == ib) {
                if (l      > qr) s0 = -INFINITY;
                if (l + 32 > qr) s1 = -INFINITY;
            }
            float m = fmaxf(s0, s1);
            #pragma unroll
            for (int off = 16; off; off >>= 1)
                m = fmaxf(m, __shfl_xor_sync(0xffffffffu, m, off));
            float p0 = expf(s0 - m), p1 = expf(s1 - m);
            float ds = p0 + p1;
            #pragma unroll
            for (int off = 16; off; off >>= 1)
                ds += __shfl_xor_sync(0xffffffffu, ds, off);
            den[r] += ds;
            Ps[w*64 + l] = p0; Ps[w*64 + l + 32] = p1;
            __syncwarp();
            #pragma unroll 8
            for (int kk = 0; kk < 64; kk++) {
                uint64_t pk2 = pack2(Ps[w*64 + kk]);
                uint64_t vp  = *(const uint64_t*)&Vs2[kk*64 + l*2];
                fma2(num2[r], pk2, vp);
            }
            __syncwarp();
        }
    }
    for (int r = 0; r < 8; r++) {
        int qr = w*8 + r;
        float dinv = 1.0f / (den[r] + 1e-6f);
        float n0, n1;
        unpack2(num2[r], n0, n1);
        long base = ((long)(ib*BLKQ + qr))*D + h*HD;
        o[base + l]      = n0 * dinv;
        o[base + l + 32] = n1 * dinv;
    }
}

// ---------------- layernorm ----------------
__global__ void ln_kernel(const float* __restrict__ x, const float* __restrict__ g,
                          const float* __restrict__ b, float* __restrict__ y) {
    int t = blockIdx.x;
    __shared__ float red[256];
    const float* row = x + (long)t*D;
    float s = 0.f;
    for (int d = threadIdx.x; d < D; d += 256) s += row[d];
    red[threadIdx.x] = s; __syncthreads();
    for (int o = 128; o; o >>= 1) { if (threadIdx.x < o) red[threadIdx.x] += red[threadIdx.x+o]; __syncthreads(); }
    float mu = red[0] / (float)D;
    __syncthreads();
    float vs = 0.f;
    for (int d = threadIdx.x; d < D; d += 256) { float dd = row[d]-mu; vs = fmaf(dd, dd, vs); }
    red[threadIdx.x] = vs; __syncthreads();
    for (int o = 128; o; o >>= 1) { if (threadIdx.x < o) red[threadIdx.x] += red[threadIdx.x+o]; __syncthreads(); }
    float inv = 1.0f / sqrtf(red[0]/(float)D + 1e-5f);
    for (int d = threadIdx.x; d < D; d += 256)
        y[(long)t*D + d] = (row[d]-mu)*inv*g[d] + b[d];
}

// ---------------- gate ----------------
__global__ void gate_kernel(const float* __restrict__ x, const float* __restrict__ gw) {
    int t = blockIdx.x;
    int tid = threadIdx.x;  // 128
    __shared__ float red[4][128];
    const float* row = x + (long)t*D;
    float p[4] = {0.f,0.f,0.f,0.f};
    for (int d = tid; d < D; d += 128) {
        float xv = row[d];
        #pragma unroll
        for (int e = 0; e < 4; e++) p[e] = fmaf(xv, gw[e*D + d], p[e]);
    }
    #pragma unroll
    for (int e = 0; e < 4; e++) red[e][tid] = p[e];
    __syncthreads();
    for (int o = 64; o; o >>= 1) {
        if (tid < o) {
            red[0][tid] += red[0][tid+o];
            red[1][tid] += red[1][tid+o];
            red[2][tid] += red[2][tid+o];
            red[3][tid] += red[3][tid+o];
        }
        __syncthreads();
    }
    if (tid == 0) {
        float l[4];
        #pragma unroll
        for (int e = 0; e < 4; e++) l[e] = red[e][0];
        float mu = (l[0]+l[1]+l[2]+l[3]) * 0.25f;
        float var = 0.f;
        #pragma unroll
        for (int e = 0; e < 4; e++) { float d0 = l[e]-mu; var = fmaf(d0, d0, var); }
        g_var[t] = var / 3.0f;
        int i1 = 0;
        for (int e = 1; e < 4; e++) if (l[e] > l[i1]) i1 = e;
        int i2 = (i1 == 0) ? 1 : 0;
        for (int e = 0; e < 4; e++) if (e != i1 && l[e] > l[i2]) i2 = e;
        float m = fmaxf(fmaxf(l[0],l[1]), fmaxf(l[2],l[3]));
        float e1 = expf(l[i1]-m), e2 = expf(l[i2]-m);
        float w1 = e1/(e1+e2), w2 = e2/(e1+e2);
        int pos1 = atomicAdd(&g_cnt[i1], 1);
        g_list[i1*S + pos1] = t; g_wgt[i1*S + pos1] = w1;
        int pos2 = atomicAdd(&g_cnt[i2], 1);
        g_list[i2*S + pos2] = t; g_wgt[i2*S + pos2] = w2;
    }
}

// ---------------- aux ----------------
__global__ void aux_kernel(float* __restrict__ out, int out_size) {
    __shared__ float red[256];
    float s = 0.f;
    for (int i = threadIdx.x; i < S; i += 256) s += g_var[i];
    red[threadIdx.x] = s; __syncthreads();
    for (int o = 128; o; o >>= 1) { if (threadIdx.x < o) red[threadIdx.x] += red[threadIdx.x+o]; __syncthreads(); }
    if (threadIdx.x == 0) {
        long pos = (long)S * NV;
        if ((long)out_size > pos) out[pos] = red[0] / (float)S;
    }
}

// ---------------- silu-gate on valid routed rows only ----------------
__global__ void silu_kernel() {
    int row = blockIdx.x;
    int e = row >> 10;
    int slot = row & (S-1);
    if (slot >= g_cnt[e]) return;
    long base = (long)row * FF;
    for (int i = threadIdx.x; i < FF; i += 256) {
        float a = g_t1[base + i], b = g_t2[base + i];
        g_t1[base + i] = b * (a / (1.0f + expf(-a)));
    }
}

// ---------------- elementwise add ----------------
__global__ void add_kernel(const float* __restrict__ a, const float* __restrict__ b,
                           float* __restrict__ c) {
    long i = (long)blockIdx.x * 256 + threadIdx.x;
    if (i < (long)S*D) c[i] = a[i] + b[i];
}

// ================= fp32 SGEMM via packed f32x2, BK=16, LDS.128 fragments =============
constexpr int BM = 128, BN = 128, BKs = 16;

template<int EPI>
__device__ __forceinline__ void sgemm_body(
    const float* __restrict__ A, const float* __restrict__ Bm, float* __restrict__ Cm,
    int M, int N, int K, int m0, int n0, const float* __restrict__ resid)
{
    __shared__ float As[BKs][BM];
    __shared__ float Bs[BKs][BN];
    int tid = threadIdx.x;
    int tx = tid & 15, ty = tid >> 4;

    uint64_t acc2[8][4];
    #pragma unroll
    for (int i = 0; i < 8; i++)
        #pragma unroll
        for (int j = 0; j < 4; j++) acc2[i][j] = 0ull;

    int lrow = tid >> 1;
    int lq   = (tid & 1) * 8;
    int arow = m0 + lrow;
    bool avld = arow < M;
    const float* Ap = avld ? (A + (long)arow * K + lq) : nullptr;
    int brow = n0 + lrow;
    bool bvld = brow < N;
    const float* Bp = bvld ? (Bm + (long)brow * K + lq) : nullptr;

    const float4 z4 = make_float4(0.f,0.f,0.f,0.f);
    for (int k0 = 0; k0 < K; k0 += BKs) {
        float4 a0 = avld ? *(const float4*)(Ap + k0)     : z4;
        float4 a1 = avld ? *(const float4*)(Ap + k0 + 4) : z4;
        float4 b0 = bvld ? *(const float4*)(Bp + k0)     : z4;
        float4 b1 = bvld ? *(const float4*)(Bp + k0 + 4) : z4;
        __syncthreads();
        As[lq+0][lrow]=a0.x; As[lq+1][lrow]=a0.y; As[lq+2][lrow]=a0.z; As[lq+3][lrow]=a0.w;
        As[lq+4][lrow]=a1.x; As[lq+5][lrow]=a1.y; As[lq+6][lrow]=a1.z; As[lq+7][lrow]=a1.w;
        Bs[lq+0][lrow]=b0.x; Bs[lq+1][lrow]=b0.y; Bs[lq+2][lrow]=b0.z; Bs[lq+3][lrow]=b0.w;
        Bs[lq+4][lrow]=b1.x; Bs[lq+5][lrow]=b1.y; Bs[lq+6][lrow]=b1.z; Bs[lq+7][lrow]=b1.w;
        __syncthreads();
        #pragma unroll
        for (int kk = 0; kk < BKs; kk++) {
            float4 af0 = *(const float4*)&As[kk][ty*8];
            float4 af1 = *(const float4*)&As[kk][ty*8 + 4];
            float4 bf0 = *(const float4*)&Bs[kk][tx*8];
            float4 bf1 = *(const float4*)&Bs[kk][tx*8 + 4];
            uint64_t b2[4];
            b2[0] = mk2(bf0.x, bf0.y); b2[1] = mk2(bf0.z, bf0.w);
            b2[2] = mk2(bf1.x, bf1.y); b2[3] = mk2(bf1.z, bf1.w);
            float a[8] = {af0.x, af0.y, af0.z, af0.w, af1.x, af1.y, af1.z, af1.w};
            #pragma unroll
            for (int i = 0; i < 8; i++) {
                uint64_t a2 = pack2(a[i]);
                #pragma unroll
                for (int j = 0; j < 4; j++) fma2(acc2[i][j], a2, b2[j]);
            }
        }
    }
    #pragma unroll
    for (int i = 0; i < 8; i++) {
        int m = m0 + ty*8 + i;
        if (m >= M) continue;
        #pragma unroll
        for (int j = 0; j < 4; j++) {
            float c0, c1;
            unpack2(acc2[i][j], c0, c1);
            int n = n0 + tx*8 + 2*j;
            if (n < N) {
                if constexpr (EPI == 0) Cm[(long)m*N + n] = c0;
                else                    Cm[(long)m*N + n] = c0 + resid[(long)m*N + n];
            }
            if (n + 1 < N) {
                if constexpr (EPI == 0) Cm[(long)m*N + n + 1] = c1;
                else                    Cm[(long)m*N + n + 1] = c1 + resid[(long)m*N + n + 1];
            }
        }
    }
}

__global__ void __launch_bounds__(256)
wo_gemm(const float* __restrict__ A, const float* __restrict__ Bm, float* __restrict__ Cm,
        const float* __restrict__ resid) {
    sgemm_body<1>(A, Bm, Cm, S, D, D, blockIdx.y * BM, blockIdx.x * BN, resid);
}

__global__ void __launch_bounds__(256)
qkv_gemm(const float* __restrict__ x,
         const float* __restrict__ wq, const float* __restrict__ wk, const float* __restrict__ wv,
         float* __restrict__ q, float* __restrict__ k, float* __restrict__ v) {
    const float* Bm = (blockIdx.z == 0) ? wq : (blockIdx.z == 1) ? wk : wv;
    float*       Cm = (blockIdx.z == 0) ? q  : (blockIdx.z == 1) ? k  : v;
    sgemm_body<0>(x, Bm, Cm, S, D, D, blockIdx.y * BM, blockIdx.x * BN, nullptr);
}

// ================= fp16 tensor-core GEMM body: C[M,N] = A[M,K] @ B[N,K]^T =============
// fp32 inputs rounded to fp16 (same 10-bit mantissa as tf32), fp32 accumulate.
// 128x128x32 tiles, 256 thr = 8 warps (2 M x 4 N), warp tile 64x32 via mma.m16n8k16.
// Smem halves [row][40] (pad 8): bank (20*lr+lc) mod 32 is a permutation => conflict-free.
constexpr int TBM = 128, TBN = 128, THK = 32;      // k floats per tile
constexpr int KPADH = 40;                          // halves per row
constexpr size_t TSMEM = (size_t)2 * 2 * TBM * KPADH * sizeof(__half);  // 40960 B

template<int EPI, bool GA>
__device__ __forceinline__ void tgemm_body(
    const float* __restrict__ A, const float* __restrict__ Bm, float* __restrict__ Cm,
    int Meff, int N, int K,
    const int* __restrict__ ridx, const float* __restrict__ rw,
    int m0, int n0)
{
    extern __shared__ __half hsh[];
    __half* Ah = hsh;                       // [2][TBM][KPADH]
    __half* Bh = hsh + 2*TBM*KPADH;

    int tid = threadIdx.x, lane = tid & 31, wid = tid >> 5;
    int wm = (wid & 1) * 64;
    int wn = (wid >> 1) * 32;
    int lr = lane >> 2;          // 0..7
    int lc = lane & 3;           // 0..3

    float acc[4][4][4];
    #pragma unroll
    for (int mt = 0; mt < 4; mt++)
        #pragma unroll
        for (int nt = 0; nt < 4; nt++)
            #pragma unroll
            for (int r = 0; r < 4; r++) acc[mt][nt][r] = 0.f;

    // loader: 4 rows per matrix per thread, float4 at k-offset kq
    int kq = (tid & 7) * 4;          // 0..28
    int r0l = tid >> 3;              // 0..31
    const float* Ap[4];
    const float* Bp[4];
    #pragma unroll
    for (int i = 0; i < 4; i++) {
        int ar = r0l + 32*i;
        int arow = m0 + ar;
        bool av = arow < Meff;
        long grow = av ? (GA ? (long)ridx[arow] : (long)arow) : 0;
        Ap[i] = av ? (A + grow*(long)K + kq) : nullptr;
        int brow = n0 + ar;
        Bp[i] = (brow < N) ? (Bm + (long)brow*K + kq) : nullptr;
    }

    float4 sa[4], sb[4];
    const float4 z4 = make_float4(0.f,0.f,0.f,0.f);
    auto gload = [&](int kt) {
        #pragma unroll
        for (int i = 0; i < 4; i++) {
            sa[i] = Ap[i] ? *(const float4*)(Ap[i] + (long)kt*THK) : z4;
            sb[i] = Bp[i] ? *(const float4*)(Bp[i] + (long)kt*THK) : z4;
        }
    };
    auto sstore = [&](int buf) {
        #pragma unroll
        for (int i = 0; i < 4; i++) {
            int ar = r0l + 32*i;
            __half2 a01 = __floats2half2_rn(sa[i].x, sa[i].y);
            __half2 a23 = __floats2half2_rn(sa[i].z, sa[i].w);
            __half2 b01 = __floats2half2_rn(sb[i].x, sb[i].y);
            __half2 b23 = __floats2half2_rn(sb[i].z, sb[i].w);
            __half2* pa = (__half2*)&Ah[((long)buf*TBM + ar)*KPADH + kq];
            pa[0] = a01; pa[1] = a23;
            __half2* pb = (__half2*)&Bh[((long)buf*TBM + ar)*KPADH + kq];
            pb[0] = b01; pb[1] = b23;
        }
    };

    int ktiles = K / THK;
    gload(0);
    sstore(0);
    __syncthreads();

    for (int t = 0; t < ktiles; t++) {
        int buf = t & 1;
        bool more = (t + 1) < ktiles;
        if (more) gload(t + 1);

        const __half* Ab = Ah + (long)buf*TBM*KPADH;
        const __half* Bb = Bh + (long)buf*TBM*KPADH;

        #pragma unroll
        for (int ks = 0; ks < 2; ks++) {          // two k16 steps per tile
            int kb = ks * 16;
            uint32_t af[4][4], bf[4][2];
            #pragma unroll
            for (int mt = 0; mt < 4; mt++) {
                int r = wm + mt*16 + lr;
                af[mt][0] = *(const uint32_t*)&Ab[(long)r      *KPADH + kb + 2*lc    ];
                af[mt][1] = *(const uint32_t*)&Ab[(long)(r + 8)*KPADH + kb + 2*lc    ];
                af[mt][2] = *(const uint32_t*)&Ab[(long)r      *KPADH + kb + 2*lc + 8];
                af[mt][3] = *(const uint32_t*)&Ab[(long)(r + 8)*KPADH + kb + 2*lc + 8];
            }
            #pragma unroll
            for (int nt = 0; nt < 4; nt++) {
                int c = wn + nt*8 + lr;
                bf[nt][0] = *(const uint32_t*)&Bb[(long)c*KPADH + kb + 2*lc    ];
                bf[nt][1] = *(const uint32_t*)&Bb[(long)c*KPADH + kb + 2*lc + 8];
            }
            #pragma unroll
            for (int mt = 0; mt < 4; mt++)
                #pragma unroll
                for (int nt = 0; nt < 4; nt++) {
                    asm volatile(
                        "mma.sync.aligned.m16n8k16.row.col.f32.f16.f16.f32 "
                        "{%0,%1,%2,%3}, {%4,%5,%6,%7}, {%8,%9}, {%0,%1,%2,%3};"
                        : "+f"(acc[mt][nt][0]), "+f"(acc[mt][nt][1]),
                          "+f"(acc[mt][nt][2]), "+f"(acc[mt][nt][3])
                        : "r"(af[mt][0]), "r"(af[mt][1]), "r"(af[mt][2]), "r"(af[mt][3]),
                          "r"(bf[nt][0]), "r"(bf[nt][1]));
                }
        }

        if (more) {
            sstore(buf ^ 1);
            __syncthreads();
        }
    }

    // ---------------- epilogue ----------------
    #pragma unroll
    for (int mt = 0; mt < 4; mt++) {
        int r0 = m0 + wm + mt*16 + lr;
        int r1 = r0 + 8;
        #pragma unroll
        for (int nt = 0; nt < 4; nt++) {
            int c0 = n0 + wn + nt*8 + (lc << 1);
            int c1 = c0 + 1;
            if constexpr (EPI == 0) {
                if (r0 < Meff) {
                    if (c0 < N) Cm[(long)r0*N + c0] = acc[mt][nt][0];
                    if (c1 < N) Cm[(long)r0*N + c1] = acc[mt][nt][1];
                }
                if (r1 < Meff) {
                    if (c0 < N) Cm[(long)r1*N + c0] = acc[mt][nt][2];
                    if (c1 < N) Cm[(long)r1*N + c1] = acc[mt][nt][3];
                }
            } else {
                if (r0 < Meff) {
                    long orow = (long)ridx[r0] * N;
                    float w = rw[r0];
                    if (c0 < N) atomicAdd(&Cm[orow + c0], acc[mt][nt][0] * w);
                    if (c1 < N) atomicAdd(&Cm[orow + c1], acc[mt][nt][1] * w);
                }
                if (r1 < Meff) {
                    long orow = (long)ridx[r1] * N;
                    float w = rw[r1];
                    if (c0 < N) atomicAdd(&Cm[orow + c0], acc[mt][nt][2] * w);
                    if (c1 < N) atomicAdd(&Cm[orow + c1], acc[mt][nt][3] * w);
                }
            }
        }
    }
}

// merged w1 + w3 MoE GEMM: z in [0, 2*NE) -> (expert, which-weight)
__global__ void __launch_bounds__(256, 2)
moe13_gemm(const float* __restrict__ x2,
           const float* __restrict__ w1, const float* __restrict__ w3,
           float* __restrict__ t1, float* __restrict__ t2) {
    int z = blockIdx.z;
    int e = z & (NE-1);
    int sel = z >> 2;
    int Meff = g_cnt[e];
    int m0 = blockIdx.y * TBM;
    if (m0 >= Meff) return;
    const float* Bm = (sel ? w3 : w1) + (long)e * FF * D;
    float*       Cm = (sel ? t2 : t1) + (long)e * S * FF;
    tgemm_body<0, true>(x2, Bm, Cm, Meff, FF, D, g_list + e*S, nullptr,
                        m0, blockIdx.x * TBN);
}

// w2 GEMM with weighted scatter epilogue: z = expert
__global__ void __launch_bounds__(256, 2)
moe2_gemm(const float* __restrict__ t1, const float* __restrict__ w2,
          float* __restrict__ moe) {
    int e = blockIdx.z;
    int Meff = g_cnt[e];
    int m0 = blockIdx.y * TBM;
    if (m0 >= Meff) return;
    tgemm_body<2, false>(t1 + (long)e*S*FF, w2 + (long)e*D*FF, moe,
                         Meff, D, FF, g_list + e*S, g_wgt + e*S,
                         m0, blockIdx.x * TBN);
}

// LM head
__global__ void __launch_bounds__(256, 2)
head_gemm(const float* __restrict__ x5, const float* __restrict__ hw,
          float* __restrict__ out) {
    tgemm_body<0, false>(x5, hw, out, S, NV, D, nullptr, nullptr,
                         blockIdx.y * TBM, blockIdx.x * TBN);
}

// ---------------- launcher ----------------
extern "C" void kernel_launch(void* const* d_in, const int* in_sizes, int n_in,
                              void* d_out, int out_size) {
    const int*   tokens = (const int*)  d_in[0];
    const float* emb    = (const float*)d_in[1];
    const float* wq     = (const float*)d_in[2];
    const float* wk     = (const float*)d_in[3];
    const float* wv     = (const float*)d_in[4];
    const float* wo     = (const float*)d_in[5];
    const float* ln1g   = (const float*)d_in[6];
    const float* ln1b   = (const float*)d_in[7];
    const float* gatew  = (const float*)d_in[8];
    const float* w1     = (const float*)d_in[9];
    const float* w2     = (const float*)d_in[10];
    const float* w3     = (const float*)d_in[11];
    const float* ln2g   = (const float*)d_in[12];
    const float* ln2b   = (const float*)d_in[13];
    const float* fing   = (const float*)d_in[14];
    const float* finb   = (const float*)d_in[15];
    const float* headw  = (const float*)d_in[16];
    float* out = (float*)d_out;

    float *x, *q, *k, *v, *att, *x1, *x2, *x3, *x4, *x5, *moe, *t1, *t2;
    cudaGetSymbolAddress((void**)&x,   g_x);
    cudaGetSymbolAddress((void**)&q,   g_q);
    cudaGetSymbolAddress((void**)&k,   g_k);
    cudaGetSymbolAddress((void**)&v,   g_v);
    cudaGetSymbolAddress((void**)&att, g_att);
    cudaGetSymbolAddress((void**)&x1,  g_x1);
    cudaGetSymbolAddress((void**)&x2,  g_x2);
    cudaGetSymbolAddress((void**)&x3,  g_x3);
    cudaGetSymbolAddress((void**)&x4,  g_x4);
    cudaGetSymbolAddress((void**)&x5,  g_x5);
    cudaGetSymbolAddress((void**)&moe, g_moe);
    cudaGetSymbolAddress((void**)&t1,  g_t1);
    cudaGetSymbolAddress((void**)&t2,  g_t2);

    cudaFuncSetAttribute(attn_kernel, cudaFuncAttributeMaxDynamicSharedMemorySize, ATTN_SMEM);

    // 0. init + rope tables
    zero_kernel<<<(S*D + 255)/256, 256>>>(moe);
    rope_table_kernel<<<(S*32 + 255)/256, 256>>>();
    // 1. embedding
    embed_kernel<<<S, 256>>>(tokens, emb, x);
    // 2. QKV projections (fp32 f32x2 — routing bit-exact)
    qkv_gemm<<<dim3(D/BN, S/BM, 3), 256>>>(x, wq, wk, wv, q, k, v);
    // 3. RoPE
    rope_kernel<<<(S*NH*(HD/2))/256, 256>>>(q, k);
    // 4. attention
    attn_kernel<<<dim3(NH, NB), 256, ATTN_SMEM>>>(q, k, v, att);
    // 5. output projection + residual (fp32 f32x2)
    wo_gemm<<<dim3(D/BN, S/BM, 1), 256>>>(att, wo, x1, x);
    // 6. layernorm 1
    ln_kernel<<<S, 256>>>(x1, ln1g, ln1b, x2);
    // 7. gating + routing + per-token variance
    gate_kernel<<<S, 128>>>(x2, gatew);
    aux_kernel<<<1, 256>>>(out, out_size);
    // 8. MoE expert GEMMs — fp16 tensor cores (w1+w3 merged)
    moe13_gemm<<<dim3(FF/TBN, S/TBM, 2*NE), 256, TSMEM>>>(x2, w1, w3, t1, t2);
    silu_kernel<<<NE*S, 256>>>();
    moe2_gemm<<<dim3(D/TBN, S/TBM, NE), 256, TSMEM>>>(t1, w2, moe);
    // 9. residual + layernorm 2 + final layernorm
    add_kernel<<<(S*D + 255)/256, 256>>>(moe, x2, x3);
    ln_kernel<<<S, 256>>>(x3, ln2g, ln2b, x4);
    ln_kernel<<<S, 256>>>(x4, fing, finb, x5);
    // 10. LM head — fp16 tensor cores
    head_gemm<<<dim3((NV + TBN - 1)/TBN, S/TBM, 1), 256, TSMEM>>>(x5, headw, out);
}

// round 10
// speedup vs baseline: 3.4864x; 1.1392x over previous
#include <cuda_runtime.h>
#include <cuda_fp16.h>
#include <math.h>
#include <stdint.h>

#define S    1024
#define D    2048
#define NH   32
#define HD   64
#define FF   8192
#define NE   4
#define NV   50257
#define BLKQ 64
#define NB   16   // S / BLKQ

// ---------------- scratch (static device globals; no runtime alloc) ----------------
__device__ float g_x  [S*D];
__device__ float g_q  [S*D];
__device__ float g_k  [S*D];
__device__ float g_v  [S*D];
__device__ float g_att[S*D];
__device__ float g_x1 [S*D];
__device__ float g_x2 [S*D];
__device__ float g_x5 [S*D];
__device__ float g_moe[S*D];
__device__ float g_t1 [(long)NE*S*FF];
__device__ float g_t2 [(long)NE*S*FF];
__device__ int   g_cnt[NE];
__device__ int   g_list[NE*S];
__device__ float g_wgt[NE*S];
__device__ float g_var[S];
__device__ float g_cos[S*32];
__device__ float g_sin[S*32];

// ---------------- packed f32x2 helpers ----------------
__device__ __forceinline__ uint64_t pack2(float x) {
    uint64_t r;
    uint32_t u = __float_as_uint(x);
    asm("mov.b64 %0, {%1, %1};" : "=l"(r) : "r"(u));
    return r;
}
__device__ __forceinline__ uint64_t mk2(float lo, float hi) {
    uint64_t r;
    asm("mov.b64 %0, {%1, %2};" : "=l"(r) : "r"(__float_as_uint(lo)), "r"(__float_as_uint(hi)));
    return r;
}
__device__ __forceinline__ void fma2(uint64_t& d, uint64_t a, uint64_t b) {
    asm("fma.rn.f32x2 %0, %1, %2, %0;" : "+l"(d) : "l"(a), "l"(b));
}
__device__ __forceinline__ void unpack2(uint64_t v, float& lo, float& hi) {
    uint32_t a, b;
    asm("mov.b64 {%0, %1}, %2;" : "=r"(a), "=r"(b) : "l"(v));
    lo = __uint_as_float(a); hi = __uint_as_float(b);
}
__device__ __forceinline__ uint32_t smem_u32(const void* p) {
    uint32_t a;
    asm("{ .reg .u64 t; cvta.to.shared.u64 t, %1; cvt.u32.u64 %0, t; }" : "=r"(a) : "l"(p));
    return a;
}

// ---------------- init ----------------
__global__ void zero_kernel(float* moe) {
    long i = (long)blockIdx.x * blockDim.x + threadIdx.x;
    if (i < (long)S*D) moe[i] = 0.f;
    if (i < NE) g_cnt[i] = 0;
}

// ---------------- embedding gather ----------------
__global__ void embed_kernel(const int* __restrict__ tok, const float* __restrict__ emb,
                             float* __restrict__ x) {
    int t = blockIdx.x;
    long r = (long)tok[t] * D;
    for (int d = threadIdx.x; d < D; d += blockDim.x)
        x[(long)t*D + d] = emb[r + d];
}

// ---------------- RoPE tables ----------------
__global__ void rope_table_kernel() {
    int idx = blockIdx.x * blockDim.x + threadIdx.x;
    if (idx >= S*32) return;
    int j = idx & 31;
    int s = idx >> 5;
    double inv = pow(10000.0, -(double)(2*j) / (double)HD);
    double ang = (double)s * inv;
    g_cos[idx] = (float)cos(ang);
    g_sin[idx] = (float)sin(ang);
}

__global__ void rope_kernel(float* __restrict__ q, float* __restrict__ k) {
    int idx = blockIdx.x * blockDim.x + threadIdx.x;
    if (idx >= S*NH*(HD/2)) return;
    int j = idx & 31;
    int h = (idx >> 5) & 31;
    int s = idx >> 10;
    float c  = g_cos[s*32 + j];
    float sn = g_sin[s*32 + j];
    long base = (long)s*D + h*HD + 2*j;
    float q0 = q[base], q1 = q[base+1];
    q[base]   = q0*c - q1*sn;
    q[base+1] = q0*sn + q1*c;
    float k0 = k[base], k1 = k[base+1];
    k[base]   = k0*c - k1*sn;
    k[base+1] = k0*sn + k1*c;
}

// ---------------- attention (per-block-max softmax; f32x2 packed, bit-exact) ---------
#define ATTN_SMEM ((64*64 + 64*64 + 64*64 + 8*64) * 4)
__global__ void attn_kernel(const float* __restrict__ q, const float* __restrict__ k,
                            const float* __restrict__ v, float* __restrict__ o) {
    int h  = blockIdx.x;
    int ib = blockIdx.y;
    extern __shared__ float sm[];
    float* Qs  = sm;            // [64][64]
    float* Ks2 = sm + 4096;     // pair layout
    float* Vs2 = sm + 8192;     // pair layout
    float* Ps  = sm + 12288;    // [8][64]
    int tid = threadIdx.x;
    int w = tid >> 5, l = tid & 31;

    for (int idx = tid; idx < 64*64; idx += 256) {
        int r = idx >> 6, c = idx & 63;
        Qs[r*64 + c] = q[((long)(ib*BLKQ + r))*D + h*HD + c];
    }
    uint64_t num2[8];
    float den[8];
    #pragma unroll
    for (int r = 0; r < 8; r++) { num2[r] = 0ull; den[r] = 0.f; }

    for (int jb = 0; jb <= ib; jb++) {
        __syncthreads();
        for (int idx = tid; idx < 64*64; idx += 256) {
            int r = idx >> 6, c = idx & 63;
            float kv = k[((long)(jb*BLKQ + r))*D + h*HD + c];
            float vv = v[((long)(jb*BLKQ + r))*D + h*HD + c];
            Ks2[c*64 + (r & 31)*2 + (r >> 5)] = kv;
            Vs2[r*64 + (c & 31)*2 + (c >> 5)] = vv;
        }
        __syncthreads();
        for (int r = 0; r < 8; r++) {
            int qr = w*8 + r;
            uint64_t s2 = 0ull;
            #pragma unroll 8
            for (int d = 0; d < HD; d++) {
                uint64_t q2 = pack2(Qs[qr*64 + d]);
                uint64_t kp = *(const uint64_t*)&Ks2[d*64 + l*2];
                fma2(s2, q2, kp);
            }
            float s0, s1;
            unpack2(s2, s0, s1);
            s0 *= 0.125f; s1 *= 0.125f;
            if (jb == ib) {
                if (l      > qr) s0 = -INFINITY;
                if (l + 32 > qr) s1 = -INFINITY;
            }
            float m = fmaxf(s0, s1);
            #pragma unroll
            for (int off = 16; off; off >>= 1)
                m = fmaxf(m, __shfl_xor_sync(0xffffffffu, m, off));
            float p0 = expf(s0 - m), p1 = expf(s1 - m);
            float ds = p0 + p1;
            #pragma unroll
            for (int off = 16; off; off >>= 1)
                ds += __shfl_xor_sync(0xffffffffu, ds, off);
            den[r] += ds;
            Ps[w*64 + l] = p0; Ps[w*64 + l + 32] = p1;
            __syncwarp();
            #pragma unroll 8
            for (int kk = 0; kk < 64; kk++) {
                uint64_t pk2 = pack2(Ps[w*64 + kk]);
                uint64_t vp  = *(const uint64_t*)&Vs2[kk*64 + l*2];
                fma2(num2[r], pk2, vp);
            }
            __syncwarp();
        }
    }
    for (int r = 0; r < 8; r++) {
        int qr = w*8 + r;
        float dinv = 1.0f / (den[r] + 1e-6f);
        float n0, n1;
        unpack2(num2[r], n0, n1);
        long base = ((long)(ib*BLKQ + qr))*D + h*HD;
        o[base + l]      = n0 * dinv;
        o[base + l + 32] = n1 * dinv;
    }
}

// ---------------- layernorm (single) ----------------
__global__ void ln_kernel(const float* __restrict__ x, const float* __restrict__ g,
                          const float* __restrict__ b, float* __restrict__ y) {
    int t = blockIdx.x;
    __shared__ float red[256];
    const float* row = x + (long)t*D;
    float s = 0.f;
    for (int d = threadIdx.x; d < D; d += 256) s += row[d];
    red[threadIdx.x] = s; __syncthreads();
    for (int o = 128; o; o >>= 1) { if (threadIdx.x < o) red[threadIdx.x] += red[threadIdx.x+o]; __syncthreads(); }
    float mu = red[0] / (float)D;
    __syncthreads();
    float vs = 0.f;
    for (int d = threadIdx.x; d < D; d += 256) { float dd = row[d]-mu; vs = fmaf(dd, dd, vs); }
    red[threadIdx.x] = vs; __syncthreads();
    for (int o = 128; o; o >>= 1) { if (threadIdx.x < o) red[threadIdx.x] += red[threadIdx.x+o]; __syncthreads(); }
    float inv = 1.0f / sqrtf(red[0]/(float)D + 1e-5f);
    for (int d = threadIdx.x; d < D; d += 256)
        y[(long)t*D + d] = (row[d]-mu)*inv*g[d] + b[d];
}

// ---------------- fused tail: x5 = LN(LN(moe + x2, g2,b2), fg,fb) ----------------
__global__ void tail_kernel(const float* __restrict__ moe, const float* __restrict__ x2,
                            const float* __restrict__ g2, const float* __restrict__ b2,
                            const float* __restrict__ fg, const float* __restrict__ fb,
                            float* __restrict__ y) {
    int t = blockIdx.x;
    __shared__ float row[D];
    __shared__ float red[256];
    int tid = threadIdx.x;
    // add
    for (int d = tid; d < D; d += 256)
        row[d] = moe[(long)t*D + d] + x2[(long)t*D + d];
    __syncthreads();
    // LN 1 (g2,b2)
    float s = 0.f;
    for (int d = tid; d < D; d += 256) s += row[d];
    red[tid] = s; __syncthreads();
    for (int o = 128; o; o >>= 1) { if (tid < o) red[tid] += red[tid+o]; __syncthreads(); }
    float mu = red[0] / (float)D;
    __syncthreads();
    float vs = 0.f;
    for (int d = tid; d < D; d += 256) { float dd = row[d]-mu; vs = fmaf(dd, dd, vs); }
    red[tid] = vs; __syncthreads();
    for (int o = 128; o; o >>= 1) { if (tid < o) red[tid] += red[tid+o]; __syncthreads(); }
    float inv = 1.0f / sqrtf(red[0]/(float)D + 1e-5f);
    __syncthreads();
    for (int d = tid; d < D; d += 256)
        row[d] = (row[d]-mu)*inv*g2[d] + b2[d];
    __syncthreads();
    // LN 2 (fg,fb)
    s = 0.f;
    for (int d = tid; d < D; d += 256) s += row[d];
    red[tid] = s; __syncthreads();
    for (int o = 128; o; o >>= 1) { if (tid < o) red[tid] += red[tid+o]; __syncthreads(); }
    mu = red[0] / (float)D;
    __syncthreads();
    vs = 0.f;
    for (int d = tid; d < D; d += 256) { float dd = row[d]-mu; vs = fmaf(dd, dd, vs); }
    red[tid] = vs; __syncthreads();
    for (int o = 128; o; o >>= 1) { if (tid < o) red[tid] += red[tid+o]; __syncthreads(); }
    inv = 1.0f / sqrtf(red[0]/(float)D + 1e-5f);
    for (int d = tid; d < D; d += 256)
        y[(long)t*D + d] = (row[d]-mu)*inv*fg[d] + fb[d];
}

// ---------------- gate ----------------
__global__ void gate_kernel(const float* __restrict__ x, const float* __restrict__ gw) {
    int t = blockIdx.x;
    int tid = threadIdx.x;  // 128
    __shared__ float red[4][128];
    const float* row = x + (long)t*D;
    float p[4] = {0.f,0.f,0.f,0.f};
    for (int d = tid; d < D; d += 128) {
        float xv = row[d];
        #pragma unroll
        for (int e = 0; e < 4; e++) p[e] = fmaf(xv, gw[e*D + d], p[e]);
    }
    #pragma unroll
    for (int e = 0; e < 4; e++) red[e][tid] = p[e];
    __syncthreads();
    for (int o = 64; o; o >>= 1) {
        if (tid < o) {
            red[0][tid] += red[0][tid+o];
            red[1][tid] += red[1][tid+o];
            red[2][tid] += red[2][tid+o];
            red[3][tid] += red[3][tid+o];
        }
        __syncthreads();
    }
    if (tid == 0) {
        float l[4];
        #pragma unroll
        for (int e = 0; e < 4; e++) l[e] = red[e][0];
        float mu = (l[0]+l[1]+l[2]+l[3]) * 0.25f;
        float var = 0.f;
        #pragma unroll
        for (int e = 0; e < 4; e++) { float d0 = l[e]-mu; var = fmaf(d0, d0, var); }
        g_var[t] = var / 3.0f;
        int i1 = 0;
        for (int e = 1; e < 4; e++) if (l[e] > l[i1]) i1 = e;
        int i2 = (i1 == 0) ? 1 : 0;
        for (int e = 0; e < 4; e++) if (e != i1 && l[e] > l[i2]) i2 = e;
        float m = fmaxf(fmaxf(l[0],l[1]), fmaxf(l[2],l[3]));
        float e1 = expf(l[i1]-m), e2 = expf(l[i2]-m);
        float w1 = e1/(e1+e2), w2 = e2/(e1+e2);
        int pos1 = atomicAdd(&g_cnt[i1], 1);
        g_list[i1*S + pos1] = t; g_wgt[i1*S + pos1] = w1;
        int pos2 = atomicAdd(&g_cnt[i2], 1);
        g_list[i2*S + pos2] = t; g_wgt[i2*S + pos2] = w2;
    }
}

// ---------------- aux ----------------
__global__ void aux_kernel(float* __restrict__ out, int out_size) {
    __shared__ float red[256];
    float s = 0.f;
    for (int i = threadIdx.x; i < S; i += 256) s += g_var[i];
    red[threadIdx.x] = s; __syncthreads();
    for (int o = 128; o; o >>= 1) { if (threadIdx.x < o) red[threadIdx.x] += red[threadIdx.x+o]; __syncthreads(); }
    if (threadIdx.x == 0) {
        long pos = (long)S * NV;
        if ((long)out_size > pos) out[pos] = red[0] / (float)S;
    }
}

// ---------------- silu-gate on valid routed rows only (float4) ----------------
__global__ void silu_kernel() {
    int row = blockIdx.x;
    int e = row >> 10;
    int slot = row & (S-1);
    if (slot >= g_cnt[e]) return;
    long base = (long)row * FF;
    float4* t1p = (float4*)(g_t1 + base);
    const float4* t2p = (const float4*)(g_t2 + base);
    for (int i = threadIdx.x; i < FF/4; i += 256) {
        float4 a = t1p[i], b = t2p[i];
        a.x = b.x * (a.x / (1.0f + expf(-a.x)));
        a.y = b.y * (a.y / (1.0f + expf(-a.y)));
        a.z = b.z * (a.z / (1.0f + expf(-a.z)));
        a.w = b.w * (a.w / (1.0f + expf(-a.w)));
        t1p[i] = a;
    }
}

// ================= fp32 SGEMM via packed f32x2, BK=16, LDS.128 fragments =============
constexpr int BM = 128, BN = 128, BKs = 16;

template<int EPI>
__device__ __forceinline__ void sgemm_body(
    const float* __restrict__ A, const float* __restrict__ Bm, float* __restrict__ Cm,
    int M, int N, int K, int m0, int n0, const float* __restrict__ resid)
{
    __shared__ float As[BKs][BM];
    __shared__ float Bs[BKs][BN];
    int tid = threadIdx.x;
    int tx = tid & 15, ty = tid >> 4;

    uint64_t acc2[8][4];
    #pragma unroll
    for (int i = 0; i < 8; i++)
        #pragma unroll
        for (int j = 0; j < 4; j++) acc2[i][j] = 0ull;

    int lrow = tid >> 1;
    int lq   = (tid & 1) * 8;
    int arow = m0 + lrow;
    bool avld = arow < M;
    const float* Ap = avld ? (A + (long)arow * K + lq) : nullptr;
    int brow = n0 + lrow;
    bool bvld = brow < N;
    const float* Bp = bvld ? (Bm + (long)brow * K + lq) : nullptr;

    const float4 z4 = make_float4(0.f,0.f,0.f,0.f);
    for (int k0 = 0; k0 < K; k0 += BKs) {
        float4 a0 = avld ? *(const float4*)(Ap + k0)     : z4;
        float4 a1 = avld ? *(const float4*)(Ap + k0 + 4) : z4;
        float4 b0 = bvld ? *(const float4*)(Bp + k0)     : z4;
        float4 b1 = bvld ? *(const float4*)(Bp + k0 + 4) : z4;
        __syncthreads();
        As[lq+0][lrow]=a0.x; As[lq+1][lrow]=a0.y; As[lq+2][lrow]=a0.z; As[lq+3][lrow]=a0.w;
        As[lq+4][lrow]=a1.x; As[lq+5][lrow]=a1.y; As[lq+6][lrow]=a1.z; As[lq+7][lrow]=a1.w;
        Bs[lq+0][lrow]=b0.x; Bs[lq+1][lrow]=b0.y; Bs[lq+2][lrow]=b0.z; Bs[lq+3][lrow]=b0.w;
        Bs[lq+4][lrow]=b1.x; Bs[lq+5][lrow]=b1.y; Bs[lq+6][lrow]=b1.z; Bs[lq+7][lrow]=b1.w;
        __syncthreads();
        #pragma unroll
        for (int kk = 0; kk < BKs; kk++) {
            float4 af0 = *(const float4*)&As[kk][ty*8];
            float4 af1 = *(const float4*)&As[kk][ty*8 + 4];
            float4 bf0 = *(const float4*)&Bs[kk][tx*8];
            float4 bf1 = *(const float4*)&Bs[kk][tx*8 + 4];
            uint64_t b2[4];
            b2[0] = mk2(bf0.x, bf0.y); b2[1] = mk2(bf0.z, bf0.w);
            b2[2] = mk2(bf1.x, bf1.y); b2[3] = mk2(bf1.z, bf1.w);
            float a[8] = {af0.x, af0.y, af0.z, af0.w, af1.x, af1.y, af1.z, af1.w};
            #pragma unroll
            for (int i = 0; i < 8; i++) {
                uint64_t a2 = pack2(a[i]);
                #pragma unroll
                for (int j = 0; j < 4; j++) fma2(acc2[i][j], a2, b2[j]);
            }
        }
    }
    #pragma unroll
    for (int i = 0; i < 8; i++) {
        int m = m0 + ty*8 + i;
        if (m >= M) continue;
        #pragma unroll
        for (int j = 0; j < 4; j++) {
            float c0, c1;
            unpack2(acc2[i][j], c0, c1);
            int n = n0 + tx*8 + 2*j;
            if (n < N) {
                if constexpr (EPI == 0) Cm[(long)m*N + n] = c0;
                else                    Cm[(long)m*N + n] = c0 + resid[(long)m*N + n];
            }
            if (n + 1 < N) {
                if constexpr (EPI == 0) Cm[(long)m*N + n + 1] = c1;
                else                    Cm[(long)m*N + n + 1] = c1 + resid[(long)m*N + n + 1];
            }
        }
    }
}

__global__ void __launch_bounds__(256)
wo_gemm(const float* __restrict__ A, const float* __restrict__ Bm, float* __restrict__ Cm,
        const float* __restrict__ resid) {
    sgemm_body<1>(A, Bm, Cm, S, D, D, blockIdx.y * BM, blockIdx.x * BN, resid);
}

__global__ void __launch_bounds__(256)
qkv_gemm(const float* __restrict__ x,
         const float* __restrict__ wq, const float* __restrict__ wk, const float* __restrict__ wv,
         float* __restrict__ q, float* __restrict__ k, float* __restrict__ v) {
    const float* Bm = (blockIdx.z == 0) ? wq : (blockIdx.z == 1) ? wk : wv;
    float*       Cm = (blockIdx.z == 0) ? q  : (blockIdx.z == 1) ? k  : v;
    sgemm_body<0>(x, Bm, Cm, S, D, D, blockIdx.y * BM, blockIdx.x * BN, nullptr);
}

// ================= fp16 tensor-core GEMM body with ldmatrix fragments ================
// 128x128x32 tiles, 256 thr = 8 warps (2 M x 4 N), warp tile 64x32 via mma.m16n8k16.
constexpr int TBM = 128, TBN = 128, THK = 32;
constexpr int KPADH = 40;
constexpr size_t TSMEM = (size_t)2 * 2 * TBM * KPADH * sizeof(__half);  // 40960 B

__device__ __forceinline__ void ldsm4(uint32_t& r0, uint32_t& r1, uint32_t& r2, uint32_t& r3,
                                      uint32_t addr) {
    asm volatile("ldmatrix.sync.aligned.m8n8.x4.shared.b16 {%0,%1,%2,%3}, [%4];"
                 : "=r"(r0), "=r"(r1), "=r"(r2), "=r"(r3) : "r"(addr));
}

template<int EPI, bool GA>
__device__ __forceinline__ void tgemm_body(
    const float* __restrict__ A, const float* __restrict__ Bm, float* __restrict__ Cm,
    int Meff, int N, int K,
    const int* __restrict__ ridx, const float* __restrict__ rw,
    int m0, int n0)
{
    extern __shared__ __half hsh[];
    __half* Ah = hsh;                       // [2][TBM][KPADH]
    __half* Bh = hsh + 2*TBM*KPADH;
    uint32_t Abase = smem_u32(Ah);
    uint32_t Bbase = smem_u32(Bh);

    int tid = threadIdx.x, lane = tid & 31, wid = tid >> 5;
    int wm = (wid & 1) * 64;
    int wn = (wid >> 1) * 32;
    int lr = lane >> 2;          // 0..7
    int lc = lane & 3;           // 0..3

    // ldmatrix per-lane source offsets
    int rr  = lane & 7, sub = lane >> 3;
    int a_row = rr + ((sub & 1) << 3);       // 0..15
    int a_kh  = (sub >> 1) << 3;             // 0 or 8
    int b_row = rr + ((sub >> 1) << 3);
    int b_kh  = (sub & 1) << 3;

    float acc[4][4][4];
    #pragma unroll
    for (int mt = 0; mt < 4; mt++)
        #pragma unroll
        for (int nt = 0; nt < 4; nt++)
            #pragma unroll
            for (int r = 0; r < 4; r++) acc[mt][nt][r] = 0.f;

    // loader: 4 rows per matrix per thread, float4 at k-offset kq
    int kq = (tid & 7) * 4;
    int r0l = tid >> 3;
    const float* Ap[4];
    const float* Bp[4];
    #pragma unroll
    for (int i = 0; i < 4; i++) {
        int ar = r0l + 32*i;
        int arow = m0 + ar;
        bool av = arow < Meff;
        long grow = av ? (GA ? (long)ridx[arow] : (long)arow) : 0;
        Ap[i] = av ? (A + grow*(long)K + kq) : nullptr;
        int brow = n0 + ar;
        Bp[i] = (brow < N) ? (Bm + (long)brow*K + kq) : nullptr;
    }

    float4 sa[4], sb[4];
    const float4 z4 = make_float4(0.f,0.f,0.f,0.f);
    auto gload = [&](int kt) {
        #pragma unroll
        for (int i = 0; i < 4; i++) {
            sa[i] = Ap[i] ? *(const float4*)(Ap[i] + (long)kt*THK) : z4;
            sb[i] = Bp[i] ? *(const float4*)(Bp[i] + (long)kt*THK) : z4;
        }
    };
    auto sstore = [&](int buf) {
        #pragma unroll
        for (int i = 0; i < 4; i++) {
            int ar = r0l + 32*i;
            __half2 a01 = __floats2half2_rn(sa[i].x, sa[i].y);
            __half2 a23 = __floats2half2_rn(sa[i].z, sa[i].w);
            __half2 b01 = __floats2half2_rn(sb[i].x, sb[i].y);
            __half2 b23 = __floats2half2_rn(sb[i].z, sb[i].w);
            __half2* pa = (__half2*)&Ah[((long)buf*TBM + ar)*KPADH + kq];
            pa[0] = a01; pa[1] = a23;
            __half2* pb = (__half2*)&Bh[((long)buf*TBM + ar)*KPADH + kq];
            pb[0] = b01; pb[1] = b23;
        }
    };

    int ktiles = K / THK;
    gload(0);
    sstore(0);
    __syncthreads();

    for (int t = 0; t < ktiles; t++) {
        int buf = t & 1;
        bool more = (t + 1) < ktiles;
        if (more) gload(t + 1);

        uint32_t Abuf = Abase + (uint32_t)buf * TBM * KPADH * 2;
        uint32_t Bbuf = Bbase + (uint32_t)buf * TBM * KPADH * 2;

        #pragma unroll
        for (int ks = 0; ks < 2; ks++) {          // two k16 steps per tile
            int kb = ks * 16;
            uint32_t af[4][4], bf[4][2];
            #pragma unroll
            for (int mt = 0; mt < 4; mt++) {
                uint32_t addr = Abuf + (uint32_t)((wm + mt*16 + a_row) * KPADH + kb + a_kh) * 2;
                ldsm4(af[mt][0], af[mt][1], af[mt][2], af[mt][3], addr);
            }
            #pragma unroll
            for (int p = 0; p < 2; p++) {
                uint32_t addr = Bbuf + (uint32_t)((wn + p*16 + b_row) * KPADH + kb + b_kh) * 2;
                ldsm4(bf[2*p][0], bf[2*p][1], bf[2*p+1][0], bf[2*p+1][1], addr);
            }
            #pragma unroll
            for (int mt = 0; mt < 4; mt++)
                #pragma unroll
                for (int nt = 0; nt < 4; nt++) {
                    asm volatile(
                        "mma.sync.aligned.m16n8k16.row.col.f32.f16.f16.f32 "
                        "{%0,%1,%2,%3}, {%4,%5,%6,%7}, {%8,%9}, {%0,%1,%2,%3};"
                        : "+f"(acc[mt][nt][0]), "+f"(acc[mt][nt][1]),
                          "+f"(acc[mt][nt][2]), "+f"(acc[mt][nt][3])
                        : "r"(af[mt][0]), "r"(af[mt][1]), "r"(af[mt][2]), "r"(af[mt][3]),
                          "r"(bf[nt][0]), "r"(bf[nt][1]));
                }
        }

        if (more) {
            sstore(buf ^ 1);
            __syncthreads();
        }
    }

    // ---------------- epilogue ----------------
    #pragma unroll
    for (int mt = 0; mt < 4; mt++) {
        int r0 = m0 + wm + mt*16 + lr;
        int r1 = r0 + 8;
        #pragma unroll
        for (int nt = 0; nt < 4; nt++) {
            int c0 = n0 + wn + nt*8 + (lc << 1);
            int c1 = c0 + 1;
            if constexpr (EPI == 0) {
                if (r0 < Meff) {
                    if (c0 < N) Cm[(long)r0*N + c0] = acc[mt][nt][0];
                    if (c1 < N) Cm[(long)r0*N + c1] = acc[mt][nt][1];
                }
                if (r1 < Meff) {
                    if (c0 < N) Cm[(long)r1*N + c0] = acc[mt][nt][2];
                    if (c1 < N) Cm[(long)r1*N + c1] = acc[mt][nt][3];
                }
            } else {
                if (r0 < Meff) {
                    long orow = (long)ridx[r0] * N;
                    float w = rw[r0];
                    if (c0 < N) atomicAdd(&Cm[orow + c0], acc[mt][nt][0] * w);
                    if (c1 < N) atomicAdd(&Cm[orow + c1], acc[mt][nt][1] * w);
                }
                if (r1 < Meff) {
                    long orow = (long)ridx[r1] * N;
                    float w = rw[r1];
                    if (c0 < N) atomicAdd(&Cm[orow + c0], acc[mt][nt][2] * w);
                    if (c1 < N) atomicAdd(&Cm[orow + c1], acc[mt][nt][3] * w);
                }
            }
        }
    }
}

// merged w1 + w3 MoE GEMM: z in [0, 2*NE) -> (expert, which-weight)
__global__ void __launch_bounds__(256, 2)
moe13_gemm(const float* __restrict__ x2,
           const float* __restrict__ w1, const float* __restrict__ w3,
           float* __restrict__ t1, float* __restrict__ t2) {
    int z = blockIdx.z;
    int e = z & (NE-1);
    int sel = z >> 2;
    int Meff = g_cnt[e];
    int m0 = blockIdx.y * TBM;
    if (m0 >= Meff) return;
    const float* Bm = (sel ? w3 : w1) + (long)e * FF * D;
    float*       Cm = (sel ? t2 : t1) + (long)e * S * FF;
    tgemm_body<0, true>(x2, Bm, Cm, Meff, FF, D, g_list + e*S, nullptr,
                        m0, blockIdx.x * TBN);
}

// w2 GEMM with weighted scatter epilogue: z = expert
__global__ void __launch_bounds__(256, 2)
moe2_gemm(const float* __restrict__ t1, const float* __restrict__ w2,
          float* __restrict__ moe) {
    int e = blockIdx.z;
    int Meff = g_cnt[e];
    int m0 = blockIdx.y * TBM;
    if (m0 >= Meff) return;
    tgemm_body<2, false>(t1 + (long)e*S*FF, w2 + (long)e*D*FF, moe,
                         Meff, D, FF, g_list + e*S, g_wgt + e*S,
                         m0, blockIdx.x * TBN);
}

// LM head
__global__ void __launch_bounds__(256, 2)
head_gemm(const float* __restrict__ x5, const float* __restrict__ hw,
          float* __restrict__ out) {
    tgemm_body<0, false>(x5, hw, out, S, NV, D, nullptr, nullptr,
                         blockIdx.y * TBM, blockIdx.x * TBN);
}

// ---------------- launcher ----------------
extern "C" void kernel_launch(void* const* d_in, const int* in_sizes, int n_in,
                              void* d_out, int out_size) {
    const int*   tokens = (const int*)  d_in[0];
    const float* emb    = (const float*)d_in[1];
    const float* wq     = (const float*)d_in[2];
    const float* wk     = (const float*)d_in[3];
    const float* wv     = (const float*)d_in[4];
    const float* wo     = (const float*)d_in[5];
    const float* ln1g   = (const float*)d_in[6];
    const float* ln1b   = (const float*)d_in[7];
    const float* gatew  = (const float*)d_in[8];
    const float* w1     = (const float*)d_in[9];
    const float* w2     = (const float*)d_in[10];
    const float* w3     = (const float*)d_in[11];
    const float* ln2g   = (const float*)d_in[12];
    const float* ln2b   = (const float*)d_in[13];
    const float* fing   = (const float*)d_in[14];
    const float* finb   = (const float*)d_in[15];
    const float* headw  = (const float*)d_in[16];
    float* out = (float*)d_out;

    float *x, *q, *k, *v, *att, *x1, *x2, *x5, *moe, *t1, *t2;
    cudaGetSymbolAddress((void**)&x,   g_x);
    cudaGetSymbolAddress((void**)&q,   g_q);
    cudaGetSymbolAddress((void**)&k,   g_k);
    cudaGetSymbolAddress((void**)&v,   g_v);
    cudaGetSymbolAddress((void**)&att, g_att);
    cudaGetSymbolAddress((void**)&x1,  g_x1);
    cudaGetSymbolAddress((void**)&x2,  g_x2);
    cudaGetSymbolAddress((void**)&x5,  g_x5);
    cudaGetSymbolAddress((void**)&moe, g_moe);
    cudaGetSymbolAddress((void**)&t1,  g_t1);
    cudaGetSymbolAddress((void**)&t2,  g_t2);

    cudaFuncSetAttribute(attn_kernel, cudaFuncAttributeMaxDynamicSharedMemorySize, ATTN_SMEM);

    // 0. init + rope tables
    zero_kernel<<<(S*D + 255)/256, 256>>>(moe);
    rope_table_kernel<<<(S*32 + 255)/256, 256>>>();
    // 1. embedding
    embed_kernel<<<S, 256>>>(tokens, emb, x);
    // 2. QKV projections (fp32 f32x2 — routing bit-exact)
    qkv_gemm<<<dim3(D/BN, S/BM, 3), 256>>>(x, wq, wk, wv, q, k, v);
    // 3. RoPE
    rope_kernel<<<(S*NH*(HD/2))/256, 256>>>(q, k);
    // 4. attention
    attn_kernel<<<dim3(NH, NB), 256, ATTN_SMEM>>>(q, k, v, att);
    // 5. output projection + residual (fp32 f32x2)
    wo_gemm<<<dim3(D/BN, S/BM, 1), 256>>>(att, wo, x1, x);
    // 6. layernorm 1
    ln_kernel<<<S, 256>>>(x1, ln1g, ln1b, x2);
    // 7. gating + routing + per-token variance
    gate_kernel<<<S, 128>>>(x2, gatew);
    aux_kernel<<<1, 256>>>(out, out_size);
    // 8. MoE expert GEMMs — fp16 tensor cores + ldmatrix (w1+w3 merged)
    moe13_gemm<<<dim3(FF/TBN, S/TBM, 2*NE), 256, TSMEM>>>(x2, w1, w3, t1, t2);
    silu_kernel<<<NE*S, 256>>>();
    moe2_gemm<<<dim3(D/TBN, S/TBM, NE), 256, TSMEM>>>(t1, w2, moe);
    // 9. fused residual + double layernorm
    tail_kernel<<<S, 256>>>(moe, x2, ln2g, ln2b, fing, finb, x5);
    // 10. LM head — fp16 tensor cores + ldmatrix
    head_gemm<<<dim3((NV + TBN - 1)/TBN, S/TBM, 1), 256, TSMEM>>>(x5, headw, out);
}

// round 11
// speedup vs baseline: 3.8305x; 1.0987x over previous
#include <cuda_runtime.h>
#include <cuda_fp16.h>
#include <math.h>
#include <stdint.h>

#define S    1024
#define D    2048
#define NH   32
#define HD   64
#define FF   8192
#define NE   4
#define NV   50257
#define BLKQ 64
#define NB   16   // S / BLKQ

// ---------------- scratch (static device globals; no runtime alloc) ----------------
__device__ float  g_x  [S*D];
__device__ float  g_q  [S*D];
__device__ float  g_k  [S*D];
__device__ float  g_v  [S*D];
__device__ float  g_att[S*D];
__device__ float  g_x1 [S*D];
__device__ float  g_x2 [S*D];
__device__ float  g_moe[S*D];
__device__ float  g_t1 [(long)NE*S*FF];
__device__ float  g_t2 [(long)NE*S*FF];
__device__ __half g_x2h[S*D];
__device__ __half g_t1h[(long)NE*S*FF];
__device__ __half g_x5h[S*D];
__device__ int    g_cnt[NE];
__device__ int    g_list[NE*S];
__device__ float  g_wgt[NE*S];
__device__ float  g_var[S];
__device__ float  g_cos[S*32];
__device__ float  g_sin[S*32];

// ---------------- packed f32x2 helpers ----------------
__device__ __forceinline__ uint64_t pack2(float x) {
    uint64_t r;
    uint32_t u = __float_as_uint(x);
    asm("mov.b64 %0, {%1, %1};" : "=l"(r) : "r"(u));
    return r;
}
__device__ __forceinline__ uint64_t mk2(float lo, float hi) {
    uint64_t r;
    asm("mov.b64 %0, {%1, %2};" : "=l"(r) : "r"(__float_as_uint(lo)), "r"(__float_as_uint(hi)));
    return r;
}
__device__ __forceinline__ void fma2(uint64_t& d, uint64_t a, uint64_t b) {
    asm("fma.rn.f32x2 %0, %1, %2, %0;" : "+l"(d) : "l"(a), "l"(b));
}
__device__ __forceinline__ void unpack2(uint64_t v, float& lo, float& hi) {
    uint32_t a, b;
    asm("mov.b64 {%0, %1}, %2;" : "=r"(a), "=r"(b) : "l"(v));
    lo = __uint_as_float(a); hi = __uint_as_float(b);
}
__device__ __forceinline__ uint32_t smem_u32(const void* p) {
    uint32_t a;
    asm("{ .reg .u64 t; cvta.to.shared.u64 t, %1; cvt.u32.u64 %0, t; }" : "=r"(a) : "l"(p));
    return a;
}

// ---------------- init ----------------
__global__ void zero_kernel(float* moe) {
    long i = (long)blockIdx.x * blockDim.x + threadIdx.x;
    if (i < (long)S*D) moe[i] = 0.f;
    if (i < NE) g_cnt[i] = 0;
}

// ---------------- embedding gather ----------------
__global__ void embed_kernel(const int* __restrict__ tok, const float* __restrict__ emb,
                             float* __restrict__ x) {
    int t = blockIdx.x;
    long r = (long)tok[t] * D;
    for (int d = threadIdx.x; d < D; d += blockDim.x)
        x[(long)t*D + d] = emb[r + d];
}

// ---------------- RoPE tables ----------------
__global__ void rope_table_kernel() {
    int idx = blockIdx.x * blockDim.x + threadIdx.x;
    if (idx >= S*32) return;
    int j = idx & 31;
    int s = idx >> 5;
    double inv = pow(10000.0, -(double)(2*j) / (double)HD);
    double ang = (double)s * inv;
    g_cos[idx] = (float)cos(ang);
    g_sin[idx] = (float)sin(ang);
}

__global__ void rope_kernel(float* __restrict__ q, float* __restrict__ k) {
    int idx = blockIdx.x * blockDim.x + threadIdx.x;
    if (idx >= S*NH*(HD/2)) return;
    int j = idx & 31;
    int h = (idx >> 5) & 31;
    int s = idx >> 10;
    float c  = g_cos[s*32 + j];
    float sn = g_sin[s*32 + j];
    long base = (long)s*D + h*HD + 2*j;
    float q0 = q[base], q1 = q[base+1];
    q[base]   = q0*c - q1*sn;
    q[base+1] = q0*sn + q1*c;
    float k0 = k[base], k1 = k[base+1];
    k[base]   = k0*c - k1*sn;
    k[base+1] = k0*sn + k1*c;
}

// ---------------- attention (per-block-max softmax; f32x2 packed, bit-exact) ---------
#define ATTN_SMEM ((64*64 + 64*64 + 64*64 + 8*64) * 4)
__global__ void attn_kernel(const float* __restrict__ q, const float* __restrict__ k,
                            const float* __restrict__ v, float* __restrict__ o) {
    int h  = blockIdx.x;
    int ib = blockIdx.y;
    extern __shared__ float sm[];
    float* Qs  = sm;            // [64][64]
    float* Ks2 = sm + 4096;     // pair layout
    float* Vs2 = sm + 8192;     // pair layout
    float* Ps  = sm + 12288;    // [8][64]
    int tid = threadIdx.x;
    int w = tid >> 5, l = tid & 31;

    for (int idx = tid; idx < 64*64; idx += 256) {
        int r = idx >> 6, c = idx & 63;
        Qs[r*64 + c] = q[((long)(ib*BLKQ + r))*D + h*HD + c];
    }
    uint64_t num2[8];
    float den[8];
    #pragma unroll
    for (int r = 0; r < 8; r++) { num2[r] = 0ull; den[r] = 0.f; }

    for (int jb = 0; jb <= ib; jb++) {
        __syncthreads();
        for (int idx = tid; idx < 64*64; idx += 256) {
            int r = idx >> 6, c = idx & 63;
            float kv = k[((long)(jb*BLKQ + r))*D + h*HD + c];
            float vv = v[((long)(jb*BLKQ + r))*D + h*HD + c];
            Ks2[c*64 + (r & 31)*2 + (r >> 5)] = kv;
            Vs2[r*64 + (c & 31)*2 + (c >> 5)] = vv;
        }
        __syncthreads();
        for (int r = 0; r < 8; r++) {
            int qr = w*8 + r;
            uint64_t s2 = 0ull;
            #pragma unroll 8
            for (int d = 0; d < HD; d++) {
                uint64_t q2 = pack2(Qs[qr*64 + d]);
                uint64_t kp = *(const uint64_t*)&Ks2[d*64 + l*2];
                fma2(s2, q2, kp);
            }
            float s0, s1;
            unpack2(s2, s0, s1);
            s0 *= 0.125f; s1 *= 0.125f;
            if (jb == ib) {
                if (l      > qr) s0 = -INFINITY;
                if (l + 32 > qr) s1 = -INFINITY;
            }
            float m = fmaxf(s0, s1);
            #pragma unroll
            for (int off = 16; off; off >>= 1)
                m = fmaxf(m, __shfl_xor_sync(0xffffffffu, m, off));
            float p0 = expf(s0 - m), p1 = expf(s1 - m);
            float ds = p0 + p1;
            #pragma unroll
            for (int off = 16; off; off >>= 1)
                ds += __shfl_xor_sync(0xffffffffu, ds, off);
            den[r] += ds;
            Ps[w*64 + l] = p0; Ps[w*64 + l + 32] = p1;
            __syncwarp();
            #pragma unroll 8
            for (int kk = 0; kk < 64; kk++) {
                uint64_t pk2 = pack2(Ps[w*64 + kk]);
                uint64_t vp  = *(const uint64_t*)&Vs2[kk*64 + l*2];
                fma2(num2[r], pk2, vp);
            }
            __syncwarp();
        }
    }
    for (int r = 0; r < 8; r++) {
        int qr = w*8 + r;
        float dinv = 1.0f / (den[r] + 1e-6f);
        float n0, n1;
        unpack2(num2[r], n0, n1);
        long base = ((long)(ib*BLKQ + qr))*D + h*HD;
        o[base + l]      = n0 * dinv;
        o[base + l + 32] = n1 * dinv;
    }
}

// ---------------- layernorm (optionally also emits fp16 copy) ----------------
__global__ void ln_kernel(const float* __restrict__ x, const float* __restrict__ g,
                          const float* __restrict__ b, float* __restrict__ y,
                          __half* __restrict__ yh) {
    int t = blockIdx.x;
    __shared__ float red[256];
    const float* row = x + (long)t*D;
    float s = 0.f;
    for (int d = threadIdx.x; d < D; d += 256) s += row[d];
    red[threadIdx.x] = s; __syncthreads();
    for (int o = 128; o; o >>= 1) { if (threadIdx.x < o) red[threadIdx.x] += red[threadIdx.x+o]; __syncthreads(); }
    float mu = red[0] / (float)D;
    __syncthreads();
    float vs = 0.f;
    for (int d = threadIdx.x; d < D; d += 256) { float dd = row[d]-mu; vs = fmaf(dd, dd, vs); }
    red[threadIdx.x] = vs; __syncthreads();
    for (int o = 128; o; o >>= 1) { if (threadIdx.x < o) red[threadIdx.x] += red[threadIdx.x+o]; __syncthreads(); }
    float inv = 1.0f / sqrtf(red[0]/(float)D + 1e-5f);
    for (int d = threadIdx.x; d < D; d += 256) {
        float vvv = (row[d]-mu)*inv*g[d] + b[d];
        y[(long)t*D + d] = vvv;
        if (yh) yh[(long)t*D + d] = __float2half_rn(vvv);
    }
}

// ---------------- fused tail: x5h = half(LN(LN(moe + x2))) ----------------
__global__ void tail_kernel(const float* __restrict__ moe, const float* __restrict__ x2,
                            const float* __restrict__ g2, const float* __restrict__ b2,
                            const float* __restrict__ fg, const float* __restrict__ fb,
                            __half* __restrict__ yh) {
    int t = blockIdx.x;
    __shared__ float row[D];
    __shared__ float red[256];
    int tid = threadIdx.x;
    for (int d = tid; d < D; d += 256)
        row[d] = moe[(long)t*D + d] + x2[(long)t*D + d];
    __syncthreads();
    float s = 0.f;
    for (int d = tid; d < D; d += 256) s += row[d];
    red[tid] = s; __syncthreads();
    for (int o = 128; o; o >>= 1) { if (tid < o) red[tid] += red[tid+o]; __syncthreads(); }
    float mu = red[0] / (float)D;
    __syncthreads();
    float vs = 0.f;
    for (int d = tid; d < D; d += 256) { float dd = row[d]-mu; vs = fmaf(dd, dd, vs); }
    red[tid] = vs; __syncthreads();
    for (int o = 128; o; o >>= 1) { if (tid < o) red[tid] += red[tid+o]; __syncthreads(); }
    float inv = 1.0f / sqrtf(red[0]/(float)D + 1e-5f);
    __syncthreads();
    for (int d = tid; d < D; d += 256)
        row[d] = (row[d]-mu)*inv*g2[d] + b2[d];
    __syncthreads();
    s = 0.f;
    for (int d = tid; d < D; d += 256) s += row[d];
    red[tid] = s; __syncthreads();
    for (int o = 128; o; o >>= 1) { if (tid < o) red[tid] += red[tid+o]; __syncthreads(); }
    mu = red[0] / (float)D;
    __syncthreads();
    vs = 0.f;
    for (int d = tid; d < D; d += 256) { float dd = row[d]-mu; vs = fmaf(dd, dd, vs); }
    red[tid] = vs; __syncthreads();
    for (int o = 128; o; o >>= 1) { if (tid < o) red[tid] += red[tid+o]; __syncthreads(); }
    inv = 1.0f / sqrtf(red[0]/(float)D + 1e-5f);
    for (int d = tid; d < D; d += 256)
        yh[(long)t*D + d] = __float2half_rn((row[d]-mu)*inv*fg[d] + fb[d]);
}

// ---------------- gate ----------------
__global__ void gate_kernel(const float* __restrict__ x, const float* __restrict__ gw) {
    int t = blockIdx.x;
    int tid = threadIdx.x;  // 128
    __shared__ float red[4][128];
    const float* row = x + (long)t*D;
    float p[4] = {0.f,0.f,0.f,0.f};
    for (int d = tid; d < D; d += 128) {
        float xv = row[d];
        #pragma unroll
        for (int e = 0; e < 4; e++) p[e] = fmaf(xv, gw[e*D + d], p[e]);
    }
    #pragma unroll
    for (int e = 0; e < 4; e++) red[e][tid] = p[e];
    __syncthreads();
    for (int o = 64; o; o >>= 1) {
        if (tid < o) {
            red[0][tid] += red[0][tid+o];
            red[1][tid] += red[1][tid+o];
            red[2][tid] += red[2][tid+o];
            red[3][tid] += red[3][tid+o];
        }
        __syncthreads();
    }
    if (tid == 0) {
        float l[4];
        #pragma unroll
        for (int e = 0; e < 4; e++) l[e] = red[e][0];
        float mu = (l[0]+l[1]+l[2]+l[3]) * 0.25f;
        float var = 0.f;
        #pragma unroll
        for (int e = 0; e < 4; e++) { float d0 = l[e]-mu; var = fmaf(d0, d0, var); }
        g_var[t] = var / 3.0f;
        int i1 = 0;
        for (int e = 1; e < 4; e++) if (l[e] > l[i1]) i1 = e;
        int i2 = (i1 == 0) ? 1 : 0;
        for (int e = 0; e < 4; e++) if (e != i1 && l[e] > l[i2]) i2 = e;
        float m = fmaxf(fmaxf(l[0],l[1]), fmaxf(l[2],l[3]));
        float e1 = expf(l[i1]-m), e2 = expf(l[i2]-m);
        float w1 = e1/(e1+e2), w2 = e2/(e1+e2);
        int pos1 = atomicAdd(&g_cnt[i1], 1);
        g_list[i1*S + pos1] = t; g_wgt[i1*S + pos1] = w1;
        int pos2 = atomicAdd(&g_cnt[i2], 1);
        g_list[i2*S + pos2] = t; g_wgt[i2*S + pos2] = w2;
    }
}

// ---------------- aux ----------------
__global__ void aux_kernel(float* __restrict__ out, int out_size) {
    __shared__ float red[256];
    float s = 0.f;
    for (int i = threadIdx.x; i < S; i += 256) s += g_var[i];
    red[threadIdx.x] = s; __syncthreads();
    for (int o = 128; o; o >>= 1) { if (threadIdx.x < o) red[threadIdx.x] += red[threadIdx.x+o]; __syncthreads(); }
    if (threadIdx.x == 0) {
        long pos = (long)S * NV;
        if ((long)out_size > pos) out[pos] = red[0] / (float)S;
    }
}

// ---------------- silu-gate on valid routed rows: writes fp16 directly ----------------
__global__ void silu_kernel() {
    int row = blockIdx.x;
    int e = row >> 10;
    int slot = row & (S-1);
    if (slot >= g_cnt[e]) return;
    long base = (long)row * FF;
    const float4* t1p = (const float4*)(g_t1 + base);
    const float4* t2p = (const float4*)(g_t2 + base);
    uint2* oh = (uint2*)(g_t1h + base);
    for (int i = threadIdx.x; i < FF/4; i += 256) {
        float4 a = t1p[i], b = t2p[i];
        a.x = b.x * (a.x / (1.0f + expf(-a.x)));
        a.y = b.y * (a.y / (1.0f + expf(-a.y)));
        a.z = b.z * (a.z / (1.0f + expf(-a.z)));
        a.w = b.w * (a.w / (1.0f + expf(-a.w)));
        __half2 lo = __floats2half2_rn(a.x, a.y);
        __half2 hi = __floats2half2_rn(a.z, a.w);
        uint2 pk;
        pk.x = *(uint32_t*)&lo;
        pk.y = *(uint32_t*)&hi;
        oh[i] = pk;
    }
}

// ================= fp32 SGEMM via packed f32x2, BK=16, software-pipelined =============
constexpr int BM = 128, BN = 128, BKs = 16;

template<int EPI>
__device__ __forceinline__ void sgemm_body(
    const float* __restrict__ A, const float* __restrict__ Bm, float* __restrict__ Cm,
    int M, int N, int K, int m0, int n0, const float* __restrict__ resid)
{
    __shared__ float As[BKs][BM];
    __shared__ float Bs[BKs][BN];
    int tid = threadIdx.x;
    int tx = tid & 15, ty = tid >> 4;

    uint64_t acc2[8][4];
    #pragma unroll
    for (int i = 0; i < 8; i++)
        #pragma unroll
        for (int j = 0; j < 4; j++) acc2[i][j] = 0ull;

    int lrow = tid >> 1;
    int lq   = (tid & 1) * 8;
    int arow = m0 + lrow;
    bool avld = arow < M;
    const float* Ap = avld ? (A + (long)arow * K + lq) : nullptr;
    int brow = n0 + lrow;
    bool bvld = brow < N;
    const float* Bp = bvld ? (Bm + (long)brow * K + lq) : nullptr;

    const float4 z4 = make_float4(0.f,0.f,0.f,0.f);
    float4 a0, a1, b0, b1;
    auto gload = [&](int k0) {
        a0 = avld ? *(const float4*)(Ap + k0)     : z4;
        a1 = avld ? *(const float4*)(Ap + k0 + 4) : z4;
        b0 = bvld ? *(const float4*)(Bp + k0)     : z4;
        b1 = bvld ? *(const float4*)(Bp + k0 + 4) : z4;
    };
    auto sstore = [&]() {
        As[lq+0][lrow]=a0.x; As[lq+1][lrow]=a0.y; As[lq+2][lrow]=a0.z; As[lq+3][lrow]=a0.w;
        As[lq+4][lrow]=a1.x; As[lq+5][lrow]=a1.y; As[lq+6][lrow]=a1.z; As[lq+7][lrow]=a1.w;
        Bs[lq+0][lrow]=b0.x; Bs[lq+1][lrow]=b0.y; Bs[lq+2][lrow]=b0.z; Bs[lq+3][lrow]=b0.w;
        Bs[lq+4][lrow]=b1.x; Bs[lq+5][lrow]=b1.y; Bs[lq+6][lrow]=b1.z; Bs[lq+7][lrow]=b1.w;
    };

    int T = K / BKs;
    gload(0);
    sstore();
    __syncthreads();

    for (int t = 0; t < T; t++) {
        bool more = (t + 1) < T;
        if (more) gload((t + 1) * BKs);       // prefetch hidden behind compute
        #pragma unroll
        for (int kk = 0; kk < BKs; kk++) {
            float4 af0 = *(const float4*)&As[kk][ty*8];
            float4 af1 = *(const float4*)&As[kk][ty*8 + 4];
            float4 bf0 = *(const float4*)&Bs[kk][tx*8];
            float4 bf1 = *(const float4*)&Bs[kk][tx*8 + 4];
            uint64_t b2[4];
            b2[0] = mk2(bf0.x, bf0.y); b2[1] = mk2(bf0.z, bf0.w);
            b2[2] = mk2(bf1.x, bf1.y); b2[3] = mk2(bf1.z, bf1.w);
            float a[8] = {af0.x, af0.y, af0.z, af0.w, af1.x, af1.y, af1.z, af1.w};
            #pragma unroll
            for (int i = 0; i < 8; i++) {
                uint64_t a2 = pack2(a[i]);
                #pragma unroll
                for (int j = 0; j < 4; j++) fma2(acc2[i][j], a2, b2[j]);
            }
        }
        if (more) {
            __syncthreads();
            sstore();
            __syncthreads();
        }
    }
    #pragma unroll
    for (int i = 0; i < 8; i++) {
        int m = m0 + ty*8 + i;
        if (m >= M) continue;
        #pragma unroll
        for (int j = 0; j < 4; j++) {
            float c0, c1;
            unpack2(acc2[i][j], c0, c1);
            int n = n0 + tx*8 + 2*j;
            if (n < N) {
                if constexpr (EPI == 0) Cm[(long)m*N + n] = c0;
                else                    Cm[(long)m*N + n] = c0 + resid[(long)m*N + n];
            }
            if (n + 1 < N) {
                if constexpr (EPI == 0) Cm[(long)m*N + n + 1] = c1;
                else                    Cm[(long)m*N + n + 1] = c1 + resid[(long)m*N + n + 1];
            }
        }
    }
}

__global__ void __launch_bounds__(256)
wo_gemm(const float* __restrict__ A, const float* __restrict__ Bm, float* __restrict__ Cm,
        const float* __restrict__ resid) {
    sgemm_body<1>(A, Bm, Cm, S, D, D, blockIdx.y * BM, blockIdx.x * BN, resid);
}

__global__ void __launch_bounds__(256)
qkv_gemm(const float* __restrict__ x,
         const float* __restrict__ wq, const float* __restrict__ wk, const float* __restrict__ wv,
         float* __restrict__ q, float* __restrict__ k, float* __restrict__ v) {
    const float* Bm = (blockIdx.z == 0) ? wq : (blockIdx.z == 1) ? wk : wv;
    float*       Cm = (blockIdx.z == 0) ? q  : (blockIdx.z == 1) ? k  : v;
    sgemm_body<0>(x, Bm, Cm, S, D, D, blockIdx.y * BM, blockIdx.x * BN, nullptr);
}

// ================= fp16 tensor-core GEMM: A fp16 in gmem, B fp32->fp16 in-loop ========
// 128x128x32 tiles, 256 thr = 8 warps (2 M x 4 N), warp tile 64x32 via mma.m16n8k16.
constexpr int TBM = 128, TBN = 128, THK = 32;
constexpr int KPADH = 40;
constexpr size_t TSMEM = (size_t)2 * 2 * TBM * KPADH * sizeof(__half);  // 40960 B

__device__ __forceinline__ void ldsm4(uint32_t& r0, uint32_t& r1, uint32_t& r2, uint32_t& r3,
                                      uint32_t addr) {
    asm volatile("ldmatrix.sync.aligned.m8n8.x4.shared.b16 {%0,%1,%2,%3}, [%4];"
                 : "=r"(r0), "=r"(r1), "=r"(r2), "=r"(r3) : "r"(addr));
}

template<int EPI, bool GA>
__device__ __forceinline__ void tgemm_body(
    const __half* __restrict__ A, const float* __restrict__ Bm, float* __restrict__ Cm,
    int Meff, int N, int K,
    const int* __restrict__ ridx, const float* __restrict__ rw,
    int m0, int n0)
{
    extern __shared__ __half hsh[];
    __half* Ah = hsh;                       // [2][TBM][KPADH]
    __half* Bh = hsh + 2*TBM*KPADH;
    uint32_t Abase = smem_u32(Ah);
    uint32_t Bbase = smem_u32(Bh);

    int tid = threadIdx.x, lane = tid & 31, wid = tid >> 5;
    int wm = (wid & 1) * 64;
    int wn = (wid >> 1) * 32;
    int lr = lane >> 2;          // 0..7
    int lc = lane & 3;           // 0..3

    // ldmatrix per-lane source offsets
    int rr  = lane & 7, sub = lane >> 3;
    int a_row = rr + ((sub & 1) << 3);
    int a_kh  = (sub >> 1) << 3;
    int b_row = rr + ((sub >> 1) << 3);
    int b_kh  = (sub & 1) << 3;

    float acc[4][4][4];
    #pragma unroll
    for (int mt = 0; mt < 4; mt++)
        #pragma unroll
        for (int nt = 0; nt < 4; nt++)
            #pragma unroll
            for (int r = 0; r < 4; r++) acc[mt][nt][r] = 0.f;

    // A loader: fp16 rows, per thread one row, 2x16B chunk
    int arow_l = tid >> 1;                    // 0..127
    int ach    = (tid & 1) * 16;              // half offset 0 or 16
    const __half* ApH;
    {
        int arow = m0 + arow_l;
        bool av = arow < Meff;
        long grow = av ? (GA ? (long)ridx[arow] : (long)arow) : 0;
        ApH = av ? (A + grow*(long)K + ach) : nullptr;
    }
    // B loader: fp32 rows, 4 rows per thread, float4 at kq
    int kq = (tid & 7) * 4;
    int r0l = tid >> 3;
    const float* Bp[4];
    #pragma unroll
    for (int i = 0; i < 4; i++) {
        int brow = n0 + r0l + 32*i;
        Bp[i] = (brow < N) ? (Bm + (long)brow*K + kq) : nullptr;
    }

    uint4 av0, av1;
    float4 sb[4];
    const float4 z4 = make_float4(0.f,0.f,0.f,0.f);
    const uint4 zu4 = make_uint4(0,0,0,0);
    auto gload = [&](int kt) {
        av0 = ApH ? *(const uint4*)(ApH + (long)kt*THK)     : zu4;
        av1 = ApH ? *(const uint4*)(ApH + (long)kt*THK + 8) : zu4;
        #pragma unroll
        for (int i = 0; i < 4; i++)
            sb[i] = Bp[i] ? *(const float4*)(Bp[i] + (long)kt*THK) : z4;
    };
    auto sstore = [&](int buf) {
        uint4* pa = (uint4*)&Ah[((long)buf*TBM + arow_l)*KPADH + ach];
        pa[0] = av0; pa[1] = av1;
        #pragma unroll
        for (int i = 0; i < 4; i++) {
            int ar = r0l + 32*i;
            __half2 b01 = __floats2half2_rn(sb[i].x, sb[i].y);
            __half2 b23 = __floats2half2_rn(sb[i].z, sb[i].w);
            __half2* pb = (__half2*)&Bh[((long)buf*TBM + ar)*KPADH + kq];
            pb[0] = b01; pb[1] = b23;
        }
    };

    int ktiles = K / THK;
    gload(0);
    sstore(0);
    __syncthreads();

    for (int t = 0; t < ktiles; t++) {
        int buf = t & 1;
        bool more = (t + 1) < ktiles;
        if (more) gload(t + 1);

        uint32_t Abuf = Abase + (uint32_t)buf * TBM * KPADH * 2;
        uint32_t Bbuf = Bbase + (uint32_t)buf * TBM * KPADH * 2;

        #pragma unroll
        for (int ks = 0; ks < 2; ks++) {
            int kb = ks * 16;
            uint32_t af[4][4], bf[4][2];
            #pragma unroll
            for (int mt = 0; mt < 4; mt++) {
                uint32_t addr = Abuf + (uint32_t)((wm + mt*16 + a_row) * KPADH + kb + a_kh) * 2;
                ldsm4(af[mt][0], af[mt][1], af[mt][2], af[mt][3], addr);
            }
            #pragma unroll
            for (int p = 0; p < 2; p++) {
                uint32_t addr = Bbuf + (uint32_t)((wn + p*16 + b_row) * KPADH + kb + b_kh) * 2;
                ldsm4(bf[2*p][0], bf[2*p][1], bf[2*p+1][0], bf[2*p+1][1], addr);
            }
            #pragma unroll
            for (int mt = 0; mt < 4; mt++)
                #pragma unroll
                for (int nt = 0; nt < 4; nt++) {
                    asm volatile(
                        "mma.sync.aligned.m16n8k16.row.col.f32.f16.f16.f32 "
                        "{%0,%1,%2,%3}, {%4,%5,%6,%7}, {%8,%9}, {%0,%1,%2,%3};"
                        : "+f"(acc[mt][nt][0]), "+f"(acc[mt][nt][1]),
                          "+f"(acc[mt][nt][2]), "+f"(acc[mt][nt][3])
                        : "r"(af[mt][0]), "r"(af[mt][1]), "r"(af[mt][2]), "r"(af[mt][3]),
                          "r"(bf[nt][0]), "r"(bf[nt][1]));
                }
        }

        if (more) {
            sstore(buf ^ 1);
            __syncthreads();
        }
    }

    // ---------------- epilogue ----------------
    #pragma unroll
    for (int mt = 0; mt < 4; mt++) {
        int r0 = m0 + wm + mt*16 + lr;
        int r1 = r0 + 8;
        #pragma unroll
        for (int nt = 0; nt < 4; nt++) {
            int c0 = n0 + wn + nt*8 + (lc << 1);
            int c1 = c0 + 1;
            if constexpr (EPI == 0) {
                if (r0 < Meff) {
                    if (c0 < N) Cm[(long)r0*N + c0] = acc[mt][nt][0];
                    if (c1 < N) Cm[(long)r0*N + c1] = acc[mt][nt][1];
                }
                if (r1 < Meff) {
                    if (c0 < N) Cm[(long)r1*N + c0] = acc[mt][nt][2];
                    if (c1 < N) Cm[(long)r1*N + c1] = acc[mt][nt][3];
                }
            } else {
                if (r0 < Meff) {
                    long orow = (long)ridx[r0] * N;
                    float w = rw[r0];
                    if (c0 < N) atomicAdd(&Cm[orow + c0], acc[mt][nt][0] * w);
                    if (c1 < N) atomicAdd(&Cm[orow + c1], acc[mt][nt][1] * w);
                }
                if (r1 < Meff) {
                    long orow = (long)ridx[r1] * N;
                    float w = rw[r1];
                    if (c0 < N) atomicAdd(&Cm[orow + c0], acc[mt][nt][2] * w);
                    if (c1 < N) atomicAdd(&Cm[orow + c1], acc[mt][nt][3] * w);
                }
            }
        }
    }
}

// merged w1 + w3 MoE GEMM: z in [0, 2*NE) -> (expert, which-weight)
__global__ void __launch_bounds__(256, 2)
moe13_gemm(const float* __restrict__ w1, const float* __restrict__ w3,
           float* __restrict__ t1, float* __restrict__ t2) {
    int z = blockIdx.z;
    int e = z & (NE-1);
    int sel = z >> 2;
    int Meff = g_cnt[e];
    int m0 = blockIdx.y * TBM;
    if (m0 >= Meff) return;
    const float* Bm = (sel ? w3 : w1) + (long)e * FF * D;
    float*       Cm = (sel ? t2 : t1) + (long)e * S * FF;
    tgemm_body<0, true>(g_x2h, Bm, Cm, Meff, FF, D, g_list + e*S, nullptr,
                        m0, blockIdx.x * TBN);
}

// w2 GEMM with weighted scatter epilogue: z = expert
__global__ void __launch_bounds__(256, 2)
moe2_gemm(const float* __restrict__ w2, float* __restrict__ moe) {
    int e = blockIdx.z;
    int Meff = g_cnt[e];
    int m0 = blockIdx.y * TBM;
    if (m0 >= Meff) return;
    tgemm_body<2, false>(g_t1h + (long)e*S*FF, w2 + (long)e*D*FF, moe,
                         Meff, D, FF, g_list + e*S, g_wgt + e*S,
                         m0, blockIdx.x * TBN);
}

// LM head
__global__ void __launch_bounds__(256, 2)
head_gemm(const float* __restrict__ hw, float* __restrict__ out) {
    tgemm_body<0, false>(g_x5h, hw, out, S, NV, D, nullptr, nullptr,
                         blockIdx.y * TBM, blockIdx.x * TBN);
}

// ---------------- launcher ----------------
extern "C" void kernel_launch(void* const* d_in, const int* in_sizes, int n_in,
                              void* d_out, int out_size) {
    const int*   tokens = (const int*)  d_in[0];
    const float* emb    = (const float*)d_in[1];
    const float* wq     = (const float*)d_in[2];
    const float* wk     = (const float*)d_in[3];
    const float* wv     = (const float*)d_in[4];
    const float* wo     = (const float*)d_in[5];
    const float* ln1g   = (const float*)d_in[6];
    const float* ln1b   = (const float*)d_in[7];
    const float* gatew  = (const float*)d_in[8];
    const float* w1     = (const float*)d_in[9];
    const float* w2     = (const float*)d_in[10];
    const float* w3     = (const float*)d_in[11];
    const float* ln2g   = (const float*)d_in[12];
    const float* ln2b   = (const float*)d_in[13];
    const float* fing   = (const float*)d_in[14];
    const float* finb   = (const float*)d_in[15];
    const float* headw  = (const float*)d_in[16];
    float* out = (float*)d_out;

    float *x, *q, *k, *v, *att, *x1, *x2, *moe, *t1, *t2;
    __half *x2h, *x5h;
    cudaGetSymbolAddress((void**)&x,   g_x);
    cudaGetSymbolAddress((void**)&q,   g_q);
    cudaGetSymbolAddress((void**)&k,   g_k);
    cudaGetSymbolAddress((void**)&v,   g_v);
    cudaGetSymbolAddress((void**)&att, g_att);
    cudaGetSymbolAddress((void**)&x1,  g_x1);
    cudaGetSymbolAddress((void**)&x2,  g_x2);
    cudaGetSymbolAddress((void**)&moe, g_moe);
    cudaGetSymbolAddress((void**)&t1,  g_t1);
    cudaGetSymbolAddress((void**)&t2,  g_t2);
    cudaGetSymbolAddress((void**)&x2h, g_x2h);
    cudaGetSymbolAddress((void**)&x5h, g_x5h);

    cudaFuncSetAttribute(attn_kernel, cudaFuncAttributeMaxDynamicSharedMemorySize, ATTN_SMEM);

    // 0. init + rope tables
    zero_kernel<<<(S*D + 255)/256, 256>>>(moe);
    rope_table_kernel<<<(S*32 + 255)/256, 256>>>();
    // 1. embedding
    embed_kernel<<<S, 256>>>(tokens, emb, x);
    // 2. QKV projections (fp32 f32x2, pipelined — routing bit-exact)
    qkv_gemm<<<dim3(D/BN, S/BM, 3), 256>>>(x, wq, wk, wv, q, k, v);
    // 3. RoPE
    rope_kernel<<<(S*NH*(HD/2))/256, 256>>>(q, k);
    // 4. attention
    attn_kernel<<<dim3(NH, NB), 256, ATTN_SMEM>>>(q, k, v, att);
    // 5. output projection + residual (fp32 f32x2, pipelined)
    wo_gemm<<<dim3(D/BN, S/BM, 1), 256>>>(att, wo, x1, x);
    // 6. layernorm 1 (emits fp32 + fp16)
    ln_kernel<<<S, 256>>>(x1, ln1g, ln1b, x2, x2h);
    // 7. gating + routing + per-token variance
    gate_kernel<<<S, 128>>>(x2, gatew);
    aux_kernel<<<1, 256>>>(out, out_size);
    // 8. MoE expert GEMMs — fp16 tensor cores, fp16 A operands
    moe13_gemm<<<dim3(FF/TBN, S/TBM, 2*NE), 256, TSMEM>>>(w1, w3, t1, t2);
    silu_kernel<<<NE*S, 256>>>();
    moe2_gemm<<<dim3(D/TBN, S/TBM, NE), 256, TSMEM>>>(w2, moe);
    // 9. fused residual + double layernorm -> fp16 x5
    tail_kernel<<<S, 256>>>(moe, x2, ln2g, ln2b, fing, finb, x5h);
    // 10. LM head — fp16 tensor cores, fp16 A
    head_gemm<<<dim3((NV + TBN - 1)/TBN, S/TBM, 1), 256, TSMEM>>>(headw, out);
}